// round 1
// baseline (speedup 1.0000x reference)
#include <cuda_runtime.h>
#include <cstdint>

// Problem constants
#define B_   4
#define T_   2048
#define C_   2048
#define H_   16
#define HKV_ 4
#define REP_ 4
#define D_   128
#define M_   (B_*T_)   // 8192 rows

// Scratch (device globals — no allocation allowed)
__device__ float g_q[(size_t)M_ * H_ * D_];    // (B,T,H,D)   = 8192 x 2048
__device__ float g_k[(size_t)M_ * HKV_ * D_];  // (B,T,HKV,D) = 8192 x 512
__device__ float g_v[(size_t)M_ * HKV_ * D_];
__device__ float g_y[(size_t)M_ * C_];         // attention output, (B,T,C)

// ============================================================================
// Tiled FP32 SGEMM: C[M,N] = A[M,K] @ B[K,N]
// 128x128 block, BK=16, 256 threads, 8x8 per-thread microtile.
// ============================================================================
#define BM 128
#define BN 128
#define BK 16

__global__ __launch_bounds__(256) void sgemm_kernel(
    const float* __restrict__ A, const float* __restrict__ Bm,
    float* __restrict__ Cm, int M, int N, int K)
{
    __shared__ float As[BK][BM];  // A tile, transposed
    __shared__ float Bs[BK][BN];

    const int tid  = threadIdx.x;
    const int brow = blockIdx.y, bcol = blockIdx.x;
    const float* Ab = A  + (size_t)brow * BM * K;
    const float* Bb = Bm + (size_t)bcol * BN;

    const int aRow = tid >> 2;          // 0..63
    const int aCol = (tid & 3) << 2;    // 0,4,8,12
    const int bRow = tid >> 5;          // 0..7
    const int bCol = (tid & 31) << 2;   // 0..124
    const int tm   = (tid >> 4) << 3;   // 0..120
    const int tn   = (tid & 15) << 3;

    float acc[8][8];
    #pragma unroll
    for (int i = 0; i < 8; i++)
        #pragma unroll
        for (int j = 0; j < 8; j++) acc[i][j] = 0.f;

    for (int k0 = 0; k0 < K; k0 += BK) {
        #pragma unroll
        for (int h = 0; h < 2; h++) {
            int r = aRow + h * 64;
            float4 v = *(const float4*)(Ab + (size_t)r * K + k0 + aCol);
            As[aCol + 0][r] = v.x;
            As[aCol + 1][r] = v.y;
            As[aCol + 2][r] = v.z;
            As[aCol + 3][r] = v.w;
        }
        #pragma unroll
        for (int h = 0; h < 2; h++) {
            int r = bRow + h * 8;
            *(float4*)&Bs[r][bCol] = *(const float4*)(Bb + (size_t)(k0 + r) * N + bCol);
        }
        __syncthreads();

        #pragma unroll
        for (int kk = 0; kk < BK; kk++) {
            float a[8], b[8];
            #pragma unroll
            for (int i = 0; i < 8; i++) a[i] = As[kk][tm + i];
            #pragma unroll
            for (int j = 0; j < 8; j++) b[j] = Bs[kk][tn + j];
            #pragma unroll
            for (int i = 0; i < 8; i++)
                #pragma unroll
                for (int j = 0; j < 8; j++)
                    acc[i][j] += a[i] * b[j];
        }
        __syncthreads();
    }

    float* Cb = Cm + (size_t)brow * BM * N + (size_t)bcol * BN;
    #pragma unroll
    for (int i = 0; i < 8; i++) {
        #pragma unroll
        for (int j = 0; j < 8; j += 4) {
            float4 v = make_float4(acc[i][j], acc[i][j+1], acc[i][j+2], acc[i][j+3]);
            *(float4*)(Cb + (size_t)(tm + i) * N + tn + j) = v;
        }
    }
}

// ============================================================================
// Fused per-head RMSNorm + RoPE (in place).
// grid = B*T*nheads blocks (one head-row of D=128 each), 128 threads.
// X layout: (B,T,nh,D). freqs_cis: (T, D/2, 2) = cos/sin interleaved.
// ============================================================================
__global__ __launch_bounds__(128) void rmsnorm_rope_kernel(
    float* __restrict__ X, const float* __restrict__ fc, int nheads)
{
    const int idx = blockIdx.x;                 // (b*T + t)*nh + h
    const int t   = (idx / nheads) % T_;
    float* xp = X + (size_t)idx * D_;
    const int d = threadIdx.x;

    __shared__ float red[4];
    __shared__ float sh[D_];

    float v  = xp[d];
    float sq = v * v;
    #pragma unroll
    for (int o = 16; o > 0; o >>= 1)
        sq += __shfl_xor_sync(0xffffffffu, sq, o);
    if ((d & 31) == 0) red[d >> 5] = sq;
    __syncthreads();
    float ms = (red[0] + red[1] + red[2] + red[3]) * (1.f / (float)D_);
    float xn = v * rsqrtf(ms + 1e-6f);
    sh[d] = xn;
    __syncthreads();

    const int p = d >> 1;
    float c = fc[(size_t)t * D_ + p * 2 + 0];
    float s = fc[(size_t)t * D_ + p * 2 + 1];
    float t0 = sh[2 * p], t1 = sh[2 * p + 1];
    float out = (d & 1) ? (t0 * s + t1 * c) : (t0 * c - t1 * s);
    xp[d] = out;
}

// ============================================================================
// Causal GQA flash attention, fp32.
// grid = (T/64, B*H). 256 threads. Each thread owns one q-row (row = tid/4)
// and a d/column quadrant (quad = tid&3). 64x64 KV tiles, online softmax.
// Dynamic smem: qs 64x128 | kv 64x128 (K then reused for V) | ps 64x65.
// ============================================================================
#define FA_BM 64
#define FA_BN 64

__global__ __launch_bounds__(256) void flash_kernel(
    const float* __restrict__ Q, const float* __restrict__ Kg,
    const float* __restrict__ Vg, float* __restrict__ Og)
{
    extern __shared__ float smem[];
    float* qs = smem;            // 64*128
    float* kv = smem + 8192;     // 64*128 (K, then V)
    float* ps = smem + 16384;    // 64*65 (padded probs)

    const int bh  = blockIdx.y;
    const int b   = bh / H_;
    const int h   = bh % H_;
    const int kvh = h / REP_;
    const int m0  = blockIdx.x * FA_BM;
    const int tid = threadIdx.x;
    const int row = tid >> 2;
    const int quad = tid & 3;
    const float scale = 0.088388347648318447f;  // 1/sqrt(128)

    // Load + pre-scale Q tile
    const float* Qb = Q + ((size_t)(b * T_ + m0) * H_ + h) * D_;
    for (int i = tid; i < FA_BM * 32; i += 256) {
        int r = i >> 5, c = (i & 31) << 2;
        float4 v = *(const float4*)(Qb + (size_t)r * (H_ * D_) + c);
        v.x *= scale; v.y *= scale; v.z *= scale; v.w *= scale;
        *(float4*)(qs + r * 128 + c) = v;
    }

    float acc[32];
    #pragma unroll
    for (int i = 0; i < 32; i++) acc[i] = 0.f;
    float m_i = -1e30f, l_i = 0.f;

    const float* Kb = Kg + ((size_t)b * T_ * HKV_ + kvh) * D_;
    const float* Vb = Vg + ((size_t)b * T_ * HKV_ + kvh) * D_;
    const int nT = blockIdx.x + 1;  // causal: only tiles n0 <= m0

    for (int j = 0; j < nT; j++) {
        const int n0 = j * FA_BN;
        __syncthreads();  // prev PV done (and Q visible on first iter)
        for (int i = tid; i < FA_BN * 32; i += 256) {
            int r = i >> 5, c = (i & 31) << 2;
            *(float4*)(kv + r * 128 + c) =
                *(const float4*)(Kb + (size_t)(n0 + r) * (HKV_ * D_) + c);
        }
        __syncthreads();

        // Scores: q row in registers per kk-chunk; 16 columns per thread
        float s[16];
        #pragma unroll
        for (int n = 0; n < 16; n++) s[n] = 0.f;
        const float4* qrow = (const float4*)(qs + row * 128);
        #pragma unroll 4
        for (int kk = 0; kk < 32; kk++) {
            float4 qv = qrow[kk];
            #pragma unroll
            for (int n = 0; n < 16; n++) {
                float4 kvv = ((const float4*)(kv + (quad * 16 + n) * 128))[kk];
                s[n] += qv.x * kvv.x + qv.y * kvv.y + qv.z * kvv.z + qv.w * kvv.w;
            }
        }

        // Causal mask on diagonal tile (last tile: n0 == m0)
        if (j == nT - 1) {
            #pragma unroll
            for (int n = 0; n < 16; n++)
                if (n0 + quad * 16 + n > m0 + row) s[n] = -1e30f;
        }

        // Online softmax (stats replicated across the 4 threads of a row)
        float mloc = s[0];
        #pragma unroll
        for (int n = 1; n < 16; n++) mloc = fmaxf(mloc, s[n]);
        mloc = fmaxf(mloc, __shfl_xor_sync(0xffffffffu, mloc, 1));
        mloc = fmaxf(mloc, __shfl_xor_sync(0xffffffffu, mloc, 2));
        float m_new = fmaxf(m_i, mloc);
        float alpha = __expf(m_i - m_new);
        float lsum = 0.f;
        float* prow = ps + row * 65 + quad * 16;
        #pragma unroll
        for (int n = 0; n < 16; n++) {
            float p = __expf(s[n] - m_new);
            lsum += p;
            prow[n] = p;
        }
        lsum += __shfl_xor_sync(0xffffffffu, lsum, 1);
        lsum += __shfl_xor_sync(0xffffffffu, lsum, 2);
        l_i = l_i * alpha + lsum;
        m_i = m_new;
        #pragma unroll
        for (int i = 0; i < 32; i++) acc[i] *= alpha;

        __syncthreads();  // all score reads of K done; ps written
        for (int i = tid; i < FA_BN * 32; i += 256) {
            int r = i >> 5, c = (i & 31) << 2;
            *(float4*)(kv + r * 128 + c) =
                *(const float4*)(Vb + (size_t)(n0 + r) * (HKV_ * D_) + c);
        }
        __syncthreads();

        // PV: interleaved d-mapping (quad*4 + i*16) for conflict-free LDS.128
        const float* prow2 = ps + row * 65;
        for (int n = 0; n < FA_BN; n++) {
            float p = prow2[n];
            const float4* vr = (const float4*)(kv + n * 128 + quad * 4);
            #pragma unroll
            for (int i2 = 0; i2 < 8; i2++) {
                float4 v = vr[i2 * 4];
                acc[i2 * 4 + 0] += p * v.x;
                acc[i2 * 4 + 1] += p * v.y;
                acc[i2 * 4 + 2] += p * v.z;
                acc[i2 * 4 + 3] += p * v.w;
            }
        }
    }

    const float inv = 1.f / l_i;
    float* Ob = Og + ((size_t)(b * T_ + m0 + row) * H_ + h) * D_;
    #pragma unroll
    for (int i2 = 0; i2 < 8; i2++) {
        float4 v = make_float4(acc[i2 * 4 + 0] * inv, acc[i2 * 4 + 1] * inv,
                               acc[i2 * 4 + 2] * inv, acc[i2 * 4 + 3] * inv);
        *(float4*)(Ob + i2 * 16 + quad * 4) = v;
    }
}

// ============================================================================
// Launch
// ============================================================================
extern "C" void kernel_launch(void* const* d_in, const int* in_sizes, int n_in,
                              void* d_out, int out_size)
{
    (void)in_sizes; (void)n_in; (void)out_size;
    const float* x  = (const float*)d_in[0];
    const float* fc = (const float*)d_in[1];
    const float* Wq = (const float*)d_in[2];
    const float* Wk = (const float*)d_in[3];
    const float* Wv = (const float*)d_in[4];
    const float* Wc = (const float*)d_in[5];
    float* out = (float*)d_out;

    float *q, *k, *v, *y;
    cudaGetSymbolAddress((void**)&q, g_q);
    cudaGetSymbolAddress((void**)&k, g_k);
    cudaGetSymbolAddress((void**)&v, g_v);
    cudaGetSymbolAddress((void**)&y, g_y);

    // QKV projections
    dim3 gq(C_ / BN, M_ / BM);          // (16, 64)
    dim3 gkv((HKV_ * D_) / BN, M_ / BM);// (4, 64)
    sgemm_kernel<<<gq, 256>>>(x, Wq, q, M_, H_ * D_, C_);
    sgemm_kernel<<<gkv, 256>>>(x, Wk, k, M_, HKV_ * D_, C_);
    sgemm_kernel<<<gkv, 256>>>(x, Wv, v, M_, HKV_ * D_, C_);

    // RMSNorm + RoPE on q and k
    rmsnorm_rope_kernel<<<B_ * T_ * H_, 128>>>(q, fc, H_);
    rmsnorm_rope_kernel<<<B_ * T_ * HKV_, 128>>>(k, fc, HKV_);

    // Flash attention
    size_t fa_smem = (size_t)(2 * 64 * 128 + 64 * 65) * sizeof(float);  // 82176 B
    cudaFuncSetAttribute(flash_kernel, cudaFuncAttributeMaxDynamicSharedMemorySize,
                         (int)fa_smem);
    flash_kernel<<<dim3(T_ / FA_BM, B_ * H_), 256, fa_smem>>>(q, k, v, y);

    // Output projection
    sgemm_kernel<<<gq, 256>>>(y, Wc, out, M_, C_, C_);
}

// round 3
// speedup vs baseline: 1.2108x; 1.2108x over previous
#include <cuda_runtime.h>
#include <cstdint>

// Problem constants
#define B_   4
#define T_   2048
#define C_   2048
#define H_   16
#define HKV_ 4
#define REP_ 4
#define D_   128
#define M_   (B_*T_)   // 8192 rows

// Scratch (device globals — no allocation allowed)
__device__ float g_q[(size_t)M_ * H_ * D_];
__device__ float g_k[(size_t)M_ * HKV_ * D_];
__device__ float g_v[(size_t)M_ * HKV_ * D_];
__device__ float g_y[(size_t)M_ * C_];
__device__ float g_xa[(size_t)M_ * C_];          // x rounded to tf32
__device__ float g_wqr[(size_t)C_ * (H_ * D_)];  // tf32-rounded weights (same layout)
__device__ float g_wkr[(size_t)C_ * (HKV_ * D_)];
__device__ float g_wvr[(size_t)C_ * (HKV_ * D_)];
__device__ float g_wcr[(size_t)C_ * C_];

// ============================================================================
// Helpers
// ============================================================================
__device__ __forceinline__ float tf32r(float x) {
    float r; asm("cvt.rna.tf32.f32 %0, %1;" : "=f"(r) : "f"(x)); return r;
}
__device__ __forceinline__ uint32_t smem_u32(const void* p) {
    uint32_t a;
    asm("{ .reg .u64 t; cvta.to.shared.u64 t, %1; cvt.u32.u64 %0, t; }" : "=r"(a) : "l"(p));
    return a;
}
#define CP_ASYNC16(dst_u32, src_ptr) \
    asm volatile("cp.async.cg.shared.global [%0], [%1], 16;" \
                 :: "r"(dst_u32), "l"(src_ptr) : "memory")
#define CP_COMMIT() asm volatile("cp.async.commit_group;" ::: "memory")
#define CP_WAIT2()  asm volatile("cp.async.wait_group 2;" ::: "memory")

// ============================================================================
// Elementwise tf32 rounding
// ============================================================================
__global__ __launch_bounds__(256) void cvt_tf32_kernel(
    const float4* __restrict__ in, float4* __restrict__ out, int n4)
{
    int i = blockIdx.x * 256 + threadIdx.x;
    if (i < n4) {
        float4 v = in[i];
        v.x = tf32r(v.x); v.y = tf32r(v.y); v.z = tf32r(v.z); v.w = tf32r(v.w);
        out[i] = v;
    }
}

// ============================================================================
// tf32 mma.sync GEMM: C[M,N] = A[M,K] @ B[K,N]  (both row-major, pre-rounded)
// 128x128 CTA tile, BK=16, 256 threads = 8 warps (4M x 2N), warp tile 32x64.
// m16n8k8 tf32 MMA. 4-stage cp.async pipeline.
// Smem banking: As row stride 20 floats, Bs row stride 136 floats — both give
// perfect 32-bank permutations for the fragment load patterns.
// ============================================================================
#define BM 128
#define BN 128
#define BK 16
#define GST 4
#define AS_STRIDE 20
#define BS_STRIDE 136
#define AS_FLOATS (BM * AS_STRIDE)                 // 2560
#define BS_FLOATS (BK * BS_STRIDE)                 // 2176
#define STAGE_FLOATS (AS_FLOATS + BS_FLOATS)       // 4736
#define GEMM_SMEM (GST * STAGE_FLOATS * 4)         // 75776 B

__device__ __forceinline__ void mma_tf32(
    float& c0, float& c1, float& c2, float& c3,
    uint32_t a0, uint32_t a1, uint32_t a2, uint32_t a3,
    uint32_t b0, uint32_t b1)
{
    asm volatile(
        "mma.sync.aligned.m16n8k8.row.col.f32.tf32.tf32.f32 "
        "{%0,%1,%2,%3}, {%4,%5,%6,%7}, {%8,%9}, {%0,%1,%2,%3};"
        : "+f"(c0), "+f"(c1), "+f"(c2), "+f"(c3)
        : "r"(a0), "r"(a1), "r"(a2), "r"(a3), "r"(b0), "r"(b1));
}

__device__ __forceinline__ void gemm_issue_stage(
    uint32_t stage_u, const float* __restrict__ Ab, const float* __restrict__ Bb,
    int K, int N, int k0, int tid)
{
    // A tile: 128 rows x 16 floats, smem stride 20 floats (80 B, 16B-aligned)
    {
        const int m  = tid >> 2;        // 0..63
        const int c4 = tid & 3;         // float4 index within the 16-float row
        const float* ga = Ab + (size_t)m * K + k0 + c4 * 4;
        uint32_t sa = stage_u + (uint32_t)(m * AS_STRIDE + c4 * 4) * 4;
        CP_ASYNC16(sa, ga);
        CP_ASYNC16(sa + 64u * AS_STRIDE * 4u, ga + (size_t)64 * K);
    }
    // B tile: 16 rows x 128 floats, smem stride 136 floats (544 B, 16B-aligned)
    {
        const int kr = tid >> 4;        // 0..15
        const int f4 = tid & 15;        // 0..15 -> covers 32 float4 in 2 steps
        const float* gb = Bb + (size_t)(k0 + kr) * N + f4 * 4;
        uint32_t sb = stage_u + (uint32_t)(AS_FLOATS + kr * BS_STRIDE + f4 * 4) * 4;
        CP_ASYNC16(sb, gb);
        CP_ASYNC16(sb + 64u * 4u, gb + 64);
    }
}

__global__ __launch_bounds__(256, 2) void mma_gemm_kernel(
    const float* __restrict__ A, const float* __restrict__ Bm,
    float* __restrict__ Cm, int N, int K)
{
    extern __shared__ float sm[];
    const int tid   = threadIdx.x;
    const int lane  = tid & 31;
    const int wid   = tid >> 5;
    const int warpM = wid & 3;          // 0..3 -> m offset *32
    const int warpN = wid >> 2;         // 0..1 -> n offset *64

    const float* Ab = A  + (size_t)blockIdx.y * BM * K;
    const float* Bb = Bm + (size_t)blockIdx.x * BN;
    const int KT = K / BK;
    const uint32_t smem_base = smem_u32(sm);

    float acc[2][8][4];
    #pragma unroll
    for (int i = 0; i < 2; i++)
        #pragma unroll
        for (int j = 0; j < 8; j++)
            #pragma unroll
            for (int c = 0; c < 4; c++) acc[i][j][c] = 0.f;

    // Prefill stages 0..GST-2
    #pragma unroll
    for (int s = 0; s < GST - 1; s++) {
        gemm_issue_stage(smem_base + s * STAGE_FLOATS * 4, Ab, Bb, K, N, s * BK, tid);
        CP_COMMIT();
    }

    const int mrow0 = warpM * 32 + (lane >> 2);
    const int ncol0 = warpN * 64 + (lane >> 2);
    const int klow  = lane & 3;

    for (int kt = 0; kt < KT; kt++) {
        const int buf = kt & (GST - 1);
        CP_WAIT2();
        __syncthreads();

        // Issue stage kt+GST-1 into buffer (kt-1)&3 (free since last sync)
        const int nxt = kt + GST - 1;
        if (nxt < KT)
            gemm_issue_stage(smem_base + (nxt & (GST - 1)) * STAGE_FLOATS * 4,
                             Ab, Bb, K, N, nxt * BK, tid);
        CP_COMMIT();

        const float* as = sm + buf * STAGE_FLOATS;
        const float* bs = as + AS_FLOATS;

        #pragma unroll
        for (int ks = 0; ks < 2; ks++) {
            const int kc = ks * 8 + klow;
            uint32_t af[2][4], bf[8][2];
            #pragma unroll
            for (int mt = 0; mt < 2; mt++) {
                const int mr = mrow0 + mt * 16;
                af[mt][0] = __float_as_uint(as[(mr    ) * AS_STRIDE + kc    ]);
                af[mt][1] = __float_as_uint(as[(mr + 8) * AS_STRIDE + kc    ]);
                af[mt][2] = __float_as_uint(as[(mr    ) * AS_STRIDE + kc + 4]);
                af[mt][3] = __float_as_uint(as[(mr + 8) * AS_STRIDE + kc + 4]);
            }
            #pragma unroll
            for (int nt = 0; nt < 8; nt++) {
                const int nc = ncol0 + nt * 8;
                bf[nt][0] = __float_as_uint(bs[(kc    ) * BS_STRIDE + nc]);
                bf[nt][1] = __float_as_uint(bs[(kc + 4) * BS_STRIDE + nc]);
            }
            #pragma unroll
            for (int mt = 0; mt < 2; mt++)
                #pragma unroll
                for (int nt = 0; nt < 8; nt++)
                    mma_tf32(acc[mt][nt][0], acc[mt][nt][1], acc[mt][nt][2], acc[mt][nt][3],
                             af[mt][0], af[mt][1], af[mt][2], af[mt][3],
                             bf[nt][0], bf[nt][1]);
        }
        __syncthreads();
    }

    // Epilogue: c0,c1 -> (row, col..col+1); c2,c3 -> (row+8, ...)
    float* Cb = Cm + (size_t)blockIdx.y * BM * N + (size_t)blockIdx.x * BN;
    const int ccol0 = warpN * 64 + (lane & 3) * 2;
    #pragma unroll
    for (int mt = 0; mt < 2; mt++) {
        const int r = warpM * 32 + mt * 16 + (lane >> 2);
        #pragma unroll
        for (int nt = 0; nt < 8; nt++) {
            const int cc = ccol0 + nt * 8;
            *(float2*)(Cb + (size_t)r * N + cc)       = make_float2(acc[mt][nt][0], acc[mt][nt][1]);
            *(float2*)(Cb + (size_t)(r + 8) * N + cc) = make_float2(acc[mt][nt][2], acc[mt][nt][3]);
        }
    }
}

// ============================================================================
// Fused per-head RMSNorm + RoPE (in place).
// ============================================================================
__global__ __launch_bounds__(128) void rmsnorm_rope_kernel(
    float* __restrict__ X, const float* __restrict__ fc, int nheads)
{
    const int idx = blockIdx.x;
    const int t   = (idx / nheads) % T_;
    float* xp = X + (size_t)idx * D_;
    const int d = threadIdx.x;

    __shared__ float red[4];
    __shared__ float sh[D_];

    float v  = xp[d];
    float sq = v * v;
    #pragma unroll
    for (int o = 16; o > 0; o >>= 1)
        sq += __shfl_xor_sync(0xffffffffu, sq, o);
    if ((d & 31) == 0) red[d >> 5] = sq;
    __syncthreads();
    float ms = (red[0] + red[1] + red[2] + red[3]) * (1.f / (float)D_);
    float xn = v * rsqrtf(ms + 1e-6f);
    sh[d] = xn;
    __syncthreads();

    const int p = d >> 1;
    float c = fc[(size_t)t * D_ + p * 2 + 0];
    float s = fc[(size_t)t * D_ + p * 2 + 1];
    float t0 = sh[2 * p], t1 = sh[2 * p + 1];
    float out = (d & 1) ? (t0 * s + t1 * c) : (t0 * c - t1 * s);
    xp[d] = out;
}

// ============================================================================
// Causal GQA flash attention, fp32 (unchanged; tf32-rounds its output since
// y feeds the tf32 out-projection).
// ============================================================================
#define FA_BM 64
#define FA_BN 64

__global__ __launch_bounds__(256) void flash_kernel(
    const float* __restrict__ Q, const float* __restrict__ Kg,
    const float* __restrict__ Vg, float* __restrict__ Og)
{
    extern __shared__ float smem[];
    float* qs = smem;            // 64*128
    float* kv = smem + 8192;     // 64*128 (K, then V)
    float* ps = smem + 16384;    // 64*65

    const int bh  = blockIdx.y;
    const int b   = bh / H_;
    const int h   = bh % H_;
    const int kvh = h / REP_;
    const int m0  = blockIdx.x * FA_BM;
    const int tid = threadIdx.x;
    const int row = tid >> 2;
    const int quad = tid & 3;
    const float scale = 0.088388347648318447f;

    const float* Qb = Q + ((size_t)(b * T_ + m0) * H_ + h) * D_;
    for (int i = tid; i < FA_BM * 32; i += 256) {
        int r = i >> 5, c = (i & 31) << 2;
        float4 v = *(const float4*)(Qb + (size_t)r * (H_ * D_) + c);
        v.x *= scale; v.y *= scale; v.z *= scale; v.w *= scale;
        *(float4*)(qs + r * 128 + c) = v;
    }

    float acc[32];
    #pragma unroll
    for (int i = 0; i < 32; i++) acc[i] = 0.f;
    float m_i = -1e30f, l_i = 0.f;

    const float* Kb = Kg + ((size_t)b * T_ * HKV_ + kvh) * D_;
    const float* Vb = Vg + ((size_t)b * T_ * HKV_ + kvh) * D_;
    const int nT = blockIdx.x + 1;

    for (int j = 0; j < nT; j++) {
        const int n0 = j * FA_BN;
        __syncthreads();
        for (int i = tid; i < FA_BN * 32; i += 256) {
            int r = i >> 5, c = (i & 31) << 2;
            *(float4*)(kv + r * 128 + c) =
                *(const float4*)(Kb + (size_t)(n0 + r) * (HKV_ * D_) + c);
        }
        __syncthreads();

        float s[16];
        #pragma unroll
        for (int n = 0; n < 16; n++) s[n] = 0.f;
        const float4* qrow = (const float4*)(qs + row * 128);
        #pragma unroll 4
        for (int kk = 0; kk < 32; kk++) {
            float4 qv = qrow[kk];
            #pragma unroll
            for (int n = 0; n < 16; n++) {
                float4 kvv = ((const float4*)(kv + (quad * 16 + n) * 128))[kk];
                s[n] += qv.x * kvv.x + qv.y * kvv.y + qv.z * kvv.z + qv.w * kvv.w;
            }
        }

        if (j == nT - 1) {
            #pragma unroll
            for (int n = 0; n < 16; n++)
                if (n0 + quad * 16 + n > m0 + row) s[n] = -1e30f;
        }

        float mloc = s[0];
        #pragma unroll
        for (int n = 1; n < 16; n++) mloc = fmaxf(mloc, s[n]);
        mloc = fmaxf(mloc, __shfl_xor_sync(0xffffffffu, mloc, 1));
        mloc = fmaxf(mloc, __shfl_xor_sync(0xffffffffu, mloc, 2));
        float m_new = fmaxf(m_i, mloc);
        float alpha = __expf(m_i - m_new);
        float lsum = 0.f;
        float* prow = ps + row * 65 + quad * 16;
        #pragma unroll
        for (int n = 0; n < 16; n++) {
            float p = __expf(s[n] - m_new);
            lsum += p;
            prow[n] = p;
        }
        lsum += __shfl_xor_sync(0xffffffffu, lsum, 1);
        lsum += __shfl_xor_sync(0xffffffffu, lsum, 2);
        l_i = l_i * alpha + lsum;
        m_i = m_new;
        #pragma unroll
        for (int i = 0; i < 32; i++) acc[i] *= alpha;

        __syncthreads();
        for (int i = tid; i < FA_BN * 32; i += 256) {
            int r = i >> 5, c = (i & 31) << 2;
            *(float4*)(kv + r * 128 + c) =
                *(const float4*)(Vb + (size_t)(n0 + r) * (HKV_ * D_) + c);
        }
        __syncthreads();

        const float* prow2 = ps + row * 65;
        for (int n = 0; n < FA_BN; n++) {
            float p = prow2[n];
            const float4* vr = (const float4*)(kv + n * 128 + quad * 4);
            #pragma unroll
            for (int i2 = 0; i2 < 8; i2++) {
                float4 v = vr[i2 * 4];
                acc[i2 * 4 + 0] += p * v.x;
                acc[i2 * 4 + 1] += p * v.y;
                acc[i2 * 4 + 2] += p * v.z;
                acc[i2 * 4 + 3] += p * v.w;
            }
        }
    }

    const float inv = 1.f / l_i;
    float* Ob = Og + ((size_t)(b * T_ + m0 + row) * H_ + h) * D_;
    #pragma unroll
    for (int i2 = 0; i2 < 8; i2++) {
        float4 v = make_float4(tf32r(acc[i2 * 4 + 0] * inv), tf32r(acc[i2 * 4 + 1] * inv),
                               tf32r(acc[i2 * 4 + 2] * inv), tf32r(acc[i2 * 4 + 3] * inv));
        *(float4*)(Ob + i2 * 16 + quad * 4) = v;
    }
}

// ============================================================================
// Launch
// ============================================================================
extern "C" void kernel_launch(void* const* d_in, const int* in_sizes, int n_in,
                              void* d_out, int out_size)
{
    (void)in_sizes; (void)n_in; (void)out_size;
    const float* x  = (const float*)d_in[0];
    const float* fc = (const float*)d_in[1];
    const float* Wq = (const float*)d_in[2];
    const float* Wk = (const float*)d_in[3];
    const float* Wv = (const float*)d_in[4];
    const float* Wc = (const float*)d_in[5];
    float* out = (float*)d_out;

    float *q, *k, *v, *y, *xa, *wq, *wk, *wv, *wc;
    cudaGetSymbolAddress((void**)&q,  g_q);
    cudaGetSymbolAddress((void**)&k,  g_k);
    cudaGetSymbolAddress((void**)&v,  g_v);
    cudaGetSymbolAddress((void**)&y,  g_y);
    cudaGetSymbolAddress((void**)&xa, g_xa);
    cudaGetSymbolAddress((void**)&wq, g_wqr);
    cudaGetSymbolAddress((void**)&wk, g_wkr);
    cudaGetSymbolAddress((void**)&wv, g_wvr);
    cudaGetSymbolAddress((void**)&wc, g_wcr);

    // tf32-round inputs for the MMA path
    cvt_tf32_kernel<<<(M_ * C_ / 4 + 255) / 256, 256>>>((const float4*)x, (float4*)xa, M_ * C_ / 4);
    cvt_tf32_kernel<<<(C_ * H_ * D_ / 4 + 255) / 256, 256>>>((const float4*)Wq, (float4*)wq, C_ * H_ * D_ / 4);
    cvt_tf32_kernel<<<(C_ * HKV_ * D_ / 4 + 255) / 256, 256>>>((const float4*)Wk, (float4*)wk, C_ * HKV_ * D_ / 4);
    cvt_tf32_kernel<<<(C_ * HKV_ * D_ / 4 + 255) / 256, 256>>>((const float4*)Wv, (float4*)wv, C_ * HKV_ * D_ / 4);
    cvt_tf32_kernel<<<(C_ * C_ / 4 + 255) / 256, 256>>>((const float4*)Wc, (float4*)wc, C_ * C_ / 4);

    cudaFuncSetAttribute(mma_gemm_kernel, cudaFuncAttributeMaxDynamicSharedMemorySize, GEMM_SMEM);

    // QKV projections (tf32 mma.sync)
    mma_gemm_kernel<<<dim3((H_ * D_) / BN, M_ / BM), 256, GEMM_SMEM>>>(xa, wq, q, H_ * D_, C_);
    mma_gemm_kernel<<<dim3((HKV_ * D_) / BN, M_ / BM), 256, GEMM_SMEM>>>(xa, wk, k, HKV_ * D_, C_);
    mma_gemm_kernel<<<dim3((HKV_ * D_) / BN, M_ / BM), 256, GEMM_SMEM>>>(xa, wv, v, HKV_ * D_, C_);

    // RMSNorm + RoPE
    rmsnorm_rope_kernel<<<B_ * T_ * H_, 128>>>(q, fc, H_);
    rmsnorm_rope_kernel<<<B_ * T_ * HKV_, 128>>>(k, fc, HKV_);

    // Flash attention (fp32)
    size_t fa_smem = (size_t)(2 * 64 * 128 + 64 * 65) * sizeof(float);
    cudaFuncSetAttribute(flash_kernel, cudaFuncAttributeMaxDynamicSharedMemorySize, (int)fa_smem);
    flash_kernel<<<dim3(T_ / FA_BM, B_ * H_), 256, fa_smem>>>(q, k, v, y);

    // Output projection (tf32 mma.sync)
    mma_gemm_kernel<<<dim3(C_ / BN, M_ / BM), 256, GEMM_SMEM>>>(y, wc, out, C_, C_);
}

// round 4
// speedup vs baseline: 8.0735x; 6.6680x over previous
#include <cuda_runtime.h>
#include <cstdint>

// Problem constants
#define B_   4
#define T_   2048
#define C_   2048
#define H_   16
#define HKV_ 4
#define REP_ 4
#define D_   128
#define M_   (B_*T_)   // 8192 rows

// Scratch (device globals — no allocation allowed)
__device__ float g_q[(size_t)M_ * H_ * D_];
__device__ float g_k[(size_t)M_ * HKV_ * D_];
__device__ float g_v[(size_t)M_ * HKV_ * D_];
__device__ float g_y[(size_t)M_ * C_];
__device__ float g_xa[(size_t)M_ * C_];          // x rounded to tf32
__device__ float g_wqr[(size_t)C_ * (H_ * D_)];  // tf32-rounded weights
__device__ float g_wkr[(size_t)C_ * (HKV_ * D_)];
__device__ float g_wvr[(size_t)C_ * (HKV_ * D_)];
__device__ float g_wcr[(size_t)C_ * C_];

// ============================================================================
// Helpers
// ============================================================================
__device__ __forceinline__ float tf32r(float x) {
    float r; asm("cvt.rna.tf32.f32 %0, %1;" : "=f"(r) : "f"(x)); return r;
}
__device__ __forceinline__ uint32_t smem_u32(const void* p) {
    uint32_t a;
    asm("{ .reg .u64 t; cvta.to.shared.u64 t, %1; cvt.u32.u64 %0, t; }" : "=r"(a) : "l"(p));
    return a;
}
#define CP_ASYNC16(dst_u32, src_ptr) \
    asm volatile("cp.async.cg.shared.global [%0], [%1], 16;" \
                 :: "r"(dst_u32), "l"(src_ptr) : "memory")
#define CP_COMMIT() asm volatile("cp.async.commit_group;" ::: "memory")
#define CP_WAIT2()  asm volatile("cp.async.wait_group 2;" ::: "memory")
#define CP_WAIT0()  asm volatile("cp.async.wait_group 0;" ::: "memory")

__device__ __forceinline__ void mma_tf32(
    float& c0, float& c1, float& c2, float& c3,
    uint32_t a0, uint32_t a1, uint32_t a2, uint32_t a3,
    uint32_t b0, uint32_t b1)
{
    asm volatile(
        "mma.sync.aligned.m16n8k8.row.col.f32.tf32.tf32.f32 "
        "{%0,%1,%2,%3}, {%4,%5,%6,%7}, {%8,%9}, {%0,%1,%2,%3};"
        : "+f"(c0), "+f"(c1), "+f"(c2), "+f"(c3)
        : "r"(a0), "r"(a1), "r"(a2), "r"(a3), "r"(b0), "r"(b1));
}

// ============================================================================
// Elementwise tf32 rounding
// ============================================================================
__global__ __launch_bounds__(256) void cvt_tf32_kernel(
    const float4* __restrict__ in, float4* __restrict__ out, int n4)
{
    int i = blockIdx.x * 256 + threadIdx.x;
    if (i < n4) {
        float4 v = in[i];
        v.x = tf32r(v.x); v.y = tf32r(v.y); v.z = tf32r(v.z); v.w = tf32r(v.w);
        out[i] = v;
    }
}

// ============================================================================
// tf32 mma.sync GEMM: C[M,N] = A[M,K] @ B[K,N]  (row-major, pre-rounded)
// 128x128 CTA tile, BK=16, 256 threads, warp tile 32x64, 4-stage cp.async.
// ============================================================================
#define BM 128
#define BN 128
#define BK 16
#define GST 4
#define AS_STRIDE 20
#define BS_STRIDE 136
#define AS_FLOATS (BM * AS_STRIDE)
#define BS_FLOATS (BK * BS_STRIDE)
#define STAGE_FLOATS (AS_FLOATS + BS_FLOATS)
#define GEMM_SMEM (GST * STAGE_FLOATS * 4)

__device__ __forceinline__ void gemm_issue_stage(
    uint32_t stage_u, const float* __restrict__ Ab, const float* __restrict__ Bb,
    int K, int N, int k0, int tid)
{
    {
        const int m  = tid >> 2;
        const int c4 = tid & 3;
        const float* ga = Ab + (size_t)m * K + k0 + c4 * 4;
        uint32_t sa = stage_u + (uint32_t)(m * AS_STRIDE + c4 * 4) * 4;
        CP_ASYNC16(sa, ga);
        CP_ASYNC16(sa + 64u * AS_STRIDE * 4u, ga + (size_t)64 * K);
    }
    {
        const int kr = tid >> 4;
        const int f4 = tid & 15;
        const float* gb = Bb + (size_t)(k0 + kr) * N + f4 * 4;
        uint32_t sb = stage_u + (uint32_t)(AS_FLOATS + kr * BS_STRIDE + f4 * 4) * 4;
        CP_ASYNC16(sb, gb);
        CP_ASYNC16(sb + 64u * 4u, gb + 64);
    }
}

__global__ __launch_bounds__(256, 2) void mma_gemm_kernel(
    const float* __restrict__ A, const float* __restrict__ Bm,
    float* __restrict__ Cm, int N, int K)
{
    extern __shared__ float sm[];
    const int tid   = threadIdx.x;
    const int lane  = tid & 31;
    const int wid   = tid >> 5;
    const int warpM = wid & 3;
    const int warpN = wid >> 2;

    const float* Ab = A  + (size_t)blockIdx.y * BM * K;
    const float* Bb = Bm + (size_t)blockIdx.x * BN;
    const int KT = K / BK;
    const uint32_t smem_base = smem_u32(sm);

    float acc[2][8][4];
    #pragma unroll
    for (int i = 0; i < 2; i++)
        #pragma unroll
        for (int j = 0; j < 8; j++)
            #pragma unroll
            for (int c = 0; c < 4; c++) acc[i][j][c] = 0.f;

    #pragma unroll
    for (int s = 0; s < GST - 1; s++) {
        gemm_issue_stage(smem_base + s * STAGE_FLOATS * 4, Ab, Bb, K, N, s * BK, tid);
        CP_COMMIT();
    }

    const int mrow0 = warpM * 32 + (lane >> 2);
    const int ncol0 = warpN * 64 + (lane >> 2);
    const int klow  = lane & 3;

    for (int kt = 0; kt < KT; kt++) {
        const int buf = kt & (GST - 1);
        CP_WAIT2();
        __syncthreads();

        const int nxt = kt + GST - 1;
        if (nxt < KT)
            gemm_issue_stage(smem_base + (nxt & (GST - 1)) * STAGE_FLOATS * 4,
                             Ab, Bb, K, N, nxt * BK, tid);
        CP_COMMIT();

        const float* as = sm + buf * STAGE_FLOATS;
        const float* bs = as + AS_FLOATS;

        #pragma unroll
        for (int ks = 0; ks < 2; ks++) {
            const int kc = ks * 8 + klow;
            uint32_t af[2][4], bf[8][2];
            #pragma unroll
            for (int mt = 0; mt < 2; mt++) {
                const int mr = mrow0 + mt * 16;
                af[mt][0] = __float_as_uint(as[(mr    ) * AS_STRIDE + kc    ]);
                af[mt][1] = __float_as_uint(as[(mr + 8) * AS_STRIDE + kc    ]);
                af[mt][2] = __float_as_uint(as[(mr    ) * AS_STRIDE + kc + 4]);
                af[mt][3] = __float_as_uint(as[(mr + 8) * AS_STRIDE + kc + 4]);
            }
            #pragma unroll
            for (int nt = 0; nt < 8; nt++) {
                const int nc = ncol0 + nt * 8;
                bf[nt][0] = __float_as_uint(bs[(kc    ) * BS_STRIDE + nc]);
                bf[nt][1] = __float_as_uint(bs[(kc + 4) * BS_STRIDE + nc]);
            }
            #pragma unroll
            for (int mt = 0; mt < 2; mt++)
                #pragma unroll
                for (int nt = 0; nt < 8; nt++)
                    mma_tf32(acc[mt][nt][0], acc[mt][nt][1], acc[mt][nt][2], acc[mt][nt][3],
                             af[mt][0], af[mt][1], af[mt][2], af[mt][3],
                             bf[nt][0], bf[nt][1]);
        }
        __syncthreads();
    }

    float* Cb = Cm + (size_t)blockIdx.y * BM * N + (size_t)blockIdx.x * BN;
    const int ccol0 = warpN * 64 + (lane & 3) * 2;
    #pragma unroll
    for (int mt = 0; mt < 2; mt++) {
        const int r = warpM * 32 + mt * 16 + (lane >> 2);
        #pragma unroll
        for (int nt = 0; nt < 8; nt++) {
            const int cc = ccol0 + nt * 8;
            *(float2*)(Cb + (size_t)r * N + cc)       = make_float2(acc[mt][nt][0], acc[mt][nt][1]);
            *(float2*)(Cb + (size_t)(r + 8) * N + cc) = make_float2(acc[mt][nt][2], acc[mt][nt][3]);
        }
    }
}

// ============================================================================
// Fused per-head RMSNorm + RoPE (in place), now scales + rna-rounds output
// (q: scale = 1/sqrt(D); k: scale = 1) so flash can consume operands raw.
// ============================================================================
__global__ __launch_bounds__(128) void rmsnorm_rope_kernel(
    float* __restrict__ X, const float* __restrict__ fc, int nheads, float scale)
{
    const int idx = blockIdx.x;
    const int t   = (idx / nheads) % T_;
    float* xp = X + (size_t)idx * D_;
    const int d = threadIdx.x;

    __shared__ float red[4];
    __shared__ float sh[D_];

    float v  = xp[d];
    float sq = v * v;
    #pragma unroll
    for (int o = 16; o > 0; o >>= 1)
        sq += __shfl_xor_sync(0xffffffffu, sq, o);
    if ((d & 31) == 0) red[d >> 5] = sq;
    __syncthreads();
    float ms = (red[0] + red[1] + red[2] + red[3]) * (1.f / (float)D_);
    float xn = v * rsqrtf(ms + 1e-6f);
    sh[d] = xn;
    __syncthreads();

    const int p = d >> 1;
    float c = fc[(size_t)t * D_ + p * 2 + 0];
    float s = fc[(size_t)t * D_ + p * 2 + 1];
    float t0 = sh[2 * p], t1 = sh[2 * p + 1];
    float out = (d & 1) ? (t0 * s + t1 * c) : (t0 * c - t1 * s);
    xp[d] = tf32r(out * scale);
}

// ============================================================================
// Causal GQA flash attention, tf32 mma.sync.
// BM=128 q rows / CTA, BN=64 keys / tile, 256 threads = 8 warps x 16 rows.
// Q fragments register-resident; K smem stride 132, V stride 136
// (both conflict-free for their fragment patterns). P stays in registers,
// reshaped to A-fragments via intra-quad shuffles.
// ============================================================================
#define FKS 132
#define FVS 136
#define FLASH_SMEM ((128 * FKS + 2 * 64 * FKS + 2 * 64 * FVS) * 4)  // 204800 B

__global__ __launch_bounds__(256, 1) void flash_mma_kernel(
    const float* __restrict__ Q, const float* __restrict__ Kg,
    const float* __restrict__ Vg, float* __restrict__ Og)
{
    extern __shared__ float sm[];
    float* Qs = sm;                      // 128 x 132
    float* Ks = sm + 128 * FKS;          // 2 x 64 x 132
    float* Vs = Ks + 2 * 64 * FKS;       // 2 x 64 x 136

    const int tid  = threadIdx.x;
    const int lane = tid & 31, wid = tid >> 5;
    const int r = lane >> 2, c = lane & 3;
    const int b = blockIdx.y / H_, h = blockIdx.y % H_;
    const int kvh = h / REP_;
    const int m0 = blockIdx.x * 128;
    const int wrow = m0 + wid * 16;
    const uint32_t qu = smem_u32(Qs);
    const uint32_t ku = smem_u32(Ks);
    const uint32_t vu = smem_u32(Vs);

    const float* Qb = Q + ((size_t)(b * T_ + m0) * H_ + h) * D_;
    const float* Kb = Kg + ((size_t)b * T_ * HKV_ + kvh) * D_;
    const float* Vb = Vg + ((size_t)b * T_ * HKV_ + kvh) * D_;

    // Q tile (once)
    for (int i = tid; i < 128 * 32; i += 256) {
        int row = i >> 5, c4 = i & 31;
        CP_ASYNC16(qu + (uint32_t)(row * FKS + c4 * 4) * 4,
                   Qb + (size_t)row * (H_ * D_) + c4 * 4);
    }
    // KV tile 0
    for (int i = tid; i < 64 * 32; i += 256) {
        int row = i >> 5, c4 = i & 31;
        CP_ASYNC16(ku + (uint32_t)(row * FKS + c4 * 4) * 4,
                   Kb + (size_t)row * (HKV_ * D_) + c4 * 4);
        CP_ASYNC16(vu + (uint32_t)(row * FVS + c4 * 4) * 4,
                   Vb + (size_t)row * (HKV_ * D_) + c4 * 4);
    }
    CP_COMMIT();

    uint32_t qf[16][4];
    float oa[16][4];
    #pragma unroll
    for (int db = 0; db < 16; db++)
        oa[db][0] = oa[db][1] = oa[db][2] = oa[db][3] = 0.f;
    float m0r = -1e30f, m1r = -1e30f, l0 = 0.f, l1 = 0.f;

    const int nT = 2 * (blockIdx.x + 1);
    const int sA = (lane & ~3) | (c >> 1);
    const int sB = sA + 2;

    for (int j = 0; j < nT; j++) {
        const int buf = j & 1;
        const int n0 = j * 64;
        CP_WAIT0();
        __syncthreads();

        // prefetch next KV tile into the other buffer
        if (j + 1 < nT) {
            const int nb2 = buf ^ 1;
            for (int i = tid; i < 64 * 32; i += 256) {
                int row = i >> 5, c4 = i & 31;
                CP_ASYNC16(ku + (uint32_t)(nb2 * 64 * FKS + row * FKS + c4 * 4) * 4,
                           Kb + (size_t)((j + 1) * 64 + row) * (HKV_ * D_) + c4 * 4);
                CP_ASYNC16(vu + (uint32_t)(nb2 * 64 * FVS + row * FVS + c4 * 4) * 4,
                           Vb + (size_t)((j + 1) * 64 + row) * (HKV_ * D_) + c4 * 4);
            }
            CP_COMMIT();
        }

        if (j == 0) {
            const float* qsw = Qs + (wid * 16 + r) * FKS;
            #pragma unroll
            for (int ks = 0; ks < 16; ks++) {
                qf[ks][0] = __float_as_uint(qsw[ks * 8 + c]);
                qf[ks][1] = __float_as_uint(qsw[8 * FKS + ks * 8 + c]);
                qf[ks][2] = __float_as_uint(qsw[ks * 8 + c + 4]);
                qf[ks][3] = __float_as_uint(qsw[8 * FKS + ks * 8 + c + 4]);
            }
        }

        if (n0 > wrow + 15) continue;   // warp tile fully masked

        // S = Q @ K^T  (per warp: 16 x 64)
        const float* kb = Ks + buf * 64 * FKS;
        float s[8][4];
        #pragma unroll
        for (int nb = 0; nb < 8; nb++)
            s[nb][0] = s[nb][1] = s[nb][2] = s[nb][3] = 0.f;
        #pragma unroll
        for (int ks = 0; ks < 16; ks++) {
            #pragma unroll
            for (int nb = 0; nb < 8; nb++) {
                const float* kp = kb + (nb * 8 + r) * FKS + ks * 8 + c;
                uint32_t b0 = __float_as_uint(kp[0]);
                uint32_t b1 = __float_as_uint(kp[4]);
                mma_tf32(s[nb][0], s[nb][1], s[nb][2], s[nb][3],
                         qf[ks][0], qf[ks][1], qf[ks][2], qf[ks][3], b0, b1);
            }
        }

        // causal mask (only near diagonal)
        if (n0 + 63 > wrow) {
            #pragma unroll
            for (int nb = 0; nb < 8; nb++) {
                int col = n0 + nb * 8 + 2 * c;
                if (col     > wrow + r)     s[nb][0] = -1e30f;
                if (col + 1 > wrow + r)     s[nb][1] = -1e30f;
                if (col     > wrow + r + 8) s[nb][2] = -1e30f;
                if (col + 1 > wrow + r + 8) s[nb][3] = -1e30f;
            }
        }

        // online softmax (rows r and r+8)
        float mx0 = -1e30f, mx1 = -1e30f;
        #pragma unroll
        for (int nb = 0; nb < 8; nb++) {
            mx0 = fmaxf(mx0, fmaxf(s[nb][0], s[nb][1]));
            mx1 = fmaxf(mx1, fmaxf(s[nb][2], s[nb][3]));
        }
        mx0 = fmaxf(mx0, __shfl_xor_sync(0xffffffffu, mx0, 1));
        mx0 = fmaxf(mx0, __shfl_xor_sync(0xffffffffu, mx0, 2));
        mx1 = fmaxf(mx1, __shfl_xor_sync(0xffffffffu, mx1, 1));
        mx1 = fmaxf(mx1, __shfl_xor_sync(0xffffffffu, mx1, 2));
        float mn0 = fmaxf(m0r, mx0), mn1 = fmaxf(m1r, mx1);
        float a0 = __expf(m0r - mn0), a1 = __expf(m1r - mn1);
        float ls0 = 0.f, ls1 = 0.f;
        #pragma unroll
        for (int nb = 0; nb < 8; nb++) {
            s[nb][0] = tf32r(__expf(s[nb][0] - mn0));
            s[nb][1] = tf32r(__expf(s[nb][1] - mn0));
            s[nb][2] = tf32r(__expf(s[nb][2] - mn1));
            s[nb][3] = tf32r(__expf(s[nb][3] - mn1));
            ls0 += s[nb][0] + s[nb][1];
            ls1 += s[nb][2] + s[nb][3];
        }
        ls0 += __shfl_xor_sync(0xffffffffu, ls0, 1);
        ls0 += __shfl_xor_sync(0xffffffffu, ls0, 2);
        ls1 += __shfl_xor_sync(0xffffffffu, ls1, 1);
        ls1 += __shfl_xor_sync(0xffffffffu, ls1, 2);
        l0 = l0 * a0 + ls0; l1 = l1 * a1 + ls1;
        m0r = mn0; m1r = mn1;
        #pragma unroll
        for (int db = 0; db < 16; db++) {
            oa[db][0] *= a0; oa[db][1] *= a0;
            oa[db][2] *= a1; oa[db][3] *= a1;
        }

        // O += P @ V  (P C-frag -> A-frag via intra-quad shuffles)
        const float* vb = Vs + buf * 64 * FVS;
        #pragma unroll
        for (int kb2 = 0; kb2 < 8; kb2++) {
            float e, o_;
            e  = __shfl_sync(0xffffffffu, s[kb2][0], sA);
            o_ = __shfl_sync(0xffffffffu, s[kb2][1], sA);
            uint32_t pa0 = __float_as_uint((c & 1) ? o_ : e);
            e  = __shfl_sync(0xffffffffu, s[kb2][0], sB);
            o_ = __shfl_sync(0xffffffffu, s[kb2][1], sB);
            uint32_t pa2 = __float_as_uint((c & 1) ? o_ : e);
            e  = __shfl_sync(0xffffffffu, s[kb2][2], sA);
            o_ = __shfl_sync(0xffffffffu, s[kb2][3], sA);
            uint32_t pa1 = __float_as_uint((c & 1) ? o_ : e);
            e  = __shfl_sync(0xffffffffu, s[kb2][2], sB);
            o_ = __shfl_sync(0xffffffffu, s[kb2][3], sB);
            uint32_t pa3 = __float_as_uint((c & 1) ? o_ : e);
            const float* vp0 = vb + (kb2 * 8 + c) * FVS + r;
            const float* vp1 = vp0 + 4 * FVS;
            #pragma unroll
            for (int db = 0; db < 16; db++) {
                uint32_t b0 = __float_as_uint(vp0[db * 8]);
                uint32_t b1 = __float_as_uint(vp1[db * 8]);
                mma_tf32(oa[db][0], oa[db][1], oa[db][2], oa[db][3],
                         pa0, pa1, pa2, pa3, b0, b1);
            }
        }
    }

    // epilogue: normalize, tf32-round (y feeds the Wc MMA), store
    const float i0 = 1.f / l0, i1 = 1.f / l1;
    const int row_g = m0 + wid * 16 + r;
    float* Ob = Og + ((size_t)(b * T_ + row_g) * H_ + h) * D_;
    #pragma unroll
    for (int db = 0; db < 16; db++) {
        *(float2*)(Ob + db * 8 + 2 * c) =
            make_float2(tf32r(oa[db][0] * i0), tf32r(oa[db][1] * i0));
        *(float2*)(Ob + (size_t)8 * H_ * D_ + db * 8 + 2 * c) =
            make_float2(tf32r(oa[db][2] * i1), tf32r(oa[db][3] * i1));
    }
}

// ============================================================================
// Launch
// ============================================================================
extern "C" void kernel_launch(void* const* d_in, const int* in_sizes, int n_in,
                              void* d_out, int out_size)
{
    (void)in_sizes; (void)n_in; (void)out_size;
    const float* x  = (const float*)d_in[0];
    const float* fc = (const float*)d_in[1];
    const float* Wq = (const float*)d_in[2];
    const float* Wk = (const float*)d_in[3];
    const float* Wv = (const float*)d_in[4];
    const float* Wc = (const float*)d_in[5];
    float* out = (float*)d_out;

    float *q, *k, *v, *y, *xa, *wq, *wk, *wv, *wc;
    cudaGetSymbolAddress((void**)&q,  g_q);
    cudaGetSymbolAddress((void**)&k,  g_k);
    cudaGetSymbolAddress((void**)&v,  g_v);
    cudaGetSymbolAddress((void**)&y,  g_y);
    cudaGetSymbolAddress((void**)&xa, g_xa);
    cudaGetSymbolAddress((void**)&wq, g_wqr);
    cudaGetSymbolAddress((void**)&wk, g_wkr);
    cudaGetSymbolAddress((void**)&wv, g_wvr);
    cudaGetSymbolAddress((void**)&wc, g_wcr);

    // tf32-round inputs for the MMA path
    cvt_tf32_kernel<<<(M_ * C_ / 4 + 255) / 256, 256>>>((const float4*)x, (float4*)xa, M_ * C_ / 4);
    cvt_tf32_kernel<<<(C_ * H_ * D_ / 4 + 255) / 256, 256>>>((const float4*)Wq, (float4*)wq, C_ * H_ * D_ / 4);
    cvt_tf32_kernel<<<(C_ * HKV_ * D_ / 4 + 255) / 256, 256>>>((const float4*)Wk, (float4*)wk, C_ * HKV_ * D_ / 4);
    cvt_tf32_kernel<<<(C_ * HKV_ * D_ / 4 + 255) / 256, 256>>>((const float4*)Wv, (float4*)wv, C_ * HKV_ * D_ / 4);
    cvt_tf32_kernel<<<(C_ * C_ / 4 + 255) / 256, 256>>>((const float4*)Wc, (float4*)wc, C_ * C_ / 4);

    cudaFuncSetAttribute(mma_gemm_kernel, cudaFuncAttributeMaxDynamicSharedMemorySize, GEMM_SMEM);

    // QKV projections (tf32 mma.sync)
    mma_gemm_kernel<<<dim3((H_ * D_) / BN, M_ / BM), 256, GEMM_SMEM>>>(xa, wq, q, H_ * D_, C_);
    mma_gemm_kernel<<<dim3((HKV_ * D_) / BN, M_ / BM), 256, GEMM_SMEM>>>(xa, wk, k, HKV_ * D_, C_);
    mma_gemm_kernel<<<dim3((HKV_ * D_) / BN, M_ / BM), 256, GEMM_SMEM>>>(xa, wv, v, HKV_ * D_, C_);

    // RMSNorm + RoPE (q pre-scaled by 1/sqrt(D); both rna-rounded for MMA)
    rmsnorm_rope_kernel<<<B_ * T_ * H_, 128>>>(q, fc, H_, 0.088388347648318447f);
    rmsnorm_rope_kernel<<<B_ * T_ * HKV_, 128>>>(k, fc, HKV_, 1.0f);
    // V rounded in place for the PV MMA
    cvt_tf32_kernel<<<(M_ * HKV_ * D_ / 4 + 255) / 256, 256>>>((const float4*)v, (float4*)v, M_ * HKV_ * D_ / 4);

    // Flash attention (tf32 mma.sync)
    cudaFuncSetAttribute(flash_mma_kernel, cudaFuncAttributeMaxDynamicSharedMemorySize, FLASH_SMEM);
    flash_mma_kernel<<<dim3(T_ / 128, B_ * H_), 256, FLASH_SMEM>>>(q, k, v, y);

    // Output projection (tf32 mma.sync)
    mma_gemm_kernel<<<dim3(C_ / BN, M_ / BM), 256, GEMM_SMEM>>>(y, wc, out, C_, C_);
}

// round 5
// speedup vs baseline: 8.6928x; 1.0767x over previous
#include <cuda_runtime.h>
#include <cstdint>

// Problem constants
#define B_   4
#define T_   2048
#define C_   2048
#define H_   16
#define HKV_ 4
#define REP_ 4
#define D_   128
#define M_   (B_*T_)   // 8192 rows

// Scratch (device globals — no allocation allowed)
__device__ float g_q[(size_t)M_ * H_ * D_];
__device__ float g_k[(size_t)M_ * HKV_ * D_];
__device__ float g_v[(size_t)M_ * HKV_ * D_];
__device__ float g_y[(size_t)M_ * C_];
__device__ float g_xa[(size_t)M_ * C_];          // x rounded to tf32
__device__ float g_wqr[(size_t)C_ * (H_ * D_)];  // tf32-rounded weights
__device__ float g_wkr[(size_t)C_ * (HKV_ * D_)];
__device__ float g_wvr[(size_t)C_ * (HKV_ * D_)];
__device__ float g_wcr[(size_t)C_ * C_];

// ============================================================================
// Helpers
// ============================================================================
__device__ __forceinline__ float tf32r(float x) {
    float r; asm("cvt.rna.tf32.f32 %0, %1;" : "=f"(r) : "f"(x)); return r;
}
__device__ __forceinline__ uint32_t smem_u32(const void* p) {
    uint32_t a;
    asm("{ .reg .u64 t; cvta.to.shared.u64 t, %1; cvt.u32.u64 %0, t; }" : "=r"(a) : "l"(p));
    return a;
}
#define CP_ASYNC16(dst_u32, src_ptr) \
    asm volatile("cp.async.cg.shared.global [%0], [%1], 16;" \
                 :: "r"(dst_u32), "l"(src_ptr) : "memory")
#define CP_COMMIT() asm volatile("cp.async.commit_group;" ::: "memory")
#define CP_WAIT2()  asm volatile("cp.async.wait_group 2;" ::: "memory")
#define CP_WAIT0()  asm volatile("cp.async.wait_group 0;" ::: "memory")

__device__ __forceinline__ void mma_tf32(
    float& c0, float& c1, float& c2, float& c3,
    uint32_t a0, uint32_t a1, uint32_t a2, uint32_t a3,
    uint32_t b0, uint32_t b1)
{
    asm volatile(
        "mma.sync.aligned.m16n8k8.row.col.f32.tf32.tf32.f32 "
        "{%0,%1,%2,%3}, {%4,%5,%6,%7}, {%8,%9}, {%0,%1,%2,%3};"
        : "+f"(c0), "+f"(c1), "+f"(c2), "+f"(c3)
        : "r"(a0), "r"(a1), "r"(a2), "r"(a3), "r"(b0), "r"(b1));
}

// ============================================================================
// Elementwise tf32 rounding
// ============================================================================
__global__ __launch_bounds__(256) void cvt_tf32_kernel(
    const float4* __restrict__ in, float4* __restrict__ out, int n4)
{
    int i = blockIdx.x * 256 + threadIdx.x;
    if (i < n4) {
        float4 v = in[i];
        v.x = tf32r(v.x); v.y = tf32r(v.y); v.z = tf32r(v.z); v.w = tf32r(v.w);
        out[i] = v;
    }
}

// ============================================================================
// tf32 mma.sync GEMM: C[M,N] = A[M,K] @ B[K,N]  (row-major, pre-rounded)
// 128x128 CTA tile, BK=16, 128 threads = 4 warps (2M x 2N), warp tile 64x64.
// 4-stage cp.async pipeline. acc[4][8][4] = 128 regs/thread.
// Bank perms: A stride 20 (20r+c mod 32), B stride 136 (8c+r mod 32).
// ============================================================================
#define BM 128
#define BN 128
#define BK 16
#define GST 4
#define AS_STRIDE 20
#define BS_STRIDE 136
#define AS_FLOATS (BM * AS_STRIDE)
#define BS_FLOATS (BK * BS_STRIDE)
#define STAGE_FLOATS (AS_FLOATS + BS_FLOATS)
#define GEMM_SMEM (GST * STAGE_FLOATS * 4)

__device__ __forceinline__ void gemm_issue_stage(
    uint32_t stage_u, const float* __restrict__ Ab, const float* __restrict__ Bb,
    int K, int N, int k0, int tid)
{
    {
        const int m  = tid >> 2;        // 0..31
        const int c4 = tid & 3;
        const float* ga = Ab + (size_t)m * K + k0 + c4 * 4;
        uint32_t sa = stage_u + (uint32_t)(m * AS_STRIDE + c4 * 4) * 4;
        #pragma unroll
        for (int p = 0; p < 4; p++)
            CP_ASYNC16(sa + (uint32_t)(p * 32 * AS_STRIDE) * 4u, ga + (size_t)(p * 32) * K);
    }
    {
        const int kr = tid >> 3;        // 0..15
        const int f4 = tid & 7;         // 0..7
        const float* gb = Bb + (size_t)(k0 + kr) * N + f4 * 4;
        uint32_t sb = stage_u + (uint32_t)(AS_FLOATS + kr * BS_STRIDE + f4 * 4) * 4;
        #pragma unroll
        for (int p = 0; p < 4; p++)
            CP_ASYNC16(sb + (uint32_t)(p * 32) * 4u, gb + p * 32);
    }
}

__global__ __launch_bounds__(128, 2) void mma_gemm_kernel(
    const float* __restrict__ A, const float* __restrict__ Bm,
    float* __restrict__ Cm, int N, int K)
{
    extern __shared__ float sm[];
    const int tid   = threadIdx.x;
    const int lane  = tid & 31;
    const int wid   = tid >> 5;
    const int warpM = wid & 1;          // 0..1 -> m offset *64
    const int warpN = wid >> 1;         // 0..1 -> n offset *64

    const float* Ab = A  + (size_t)blockIdx.y * BM * K;
    const float* Bb = Bm + (size_t)blockIdx.x * BN;
    const int KT = K / BK;
    const uint32_t smem_base = smem_u32(sm);

    float acc[4][8][4];
    #pragma unroll
    for (int i = 0; i < 4; i++)
        #pragma unroll
        for (int j = 0; j < 8; j++)
            #pragma unroll
            for (int c = 0; c < 4; c++) acc[i][j][c] = 0.f;

    #pragma unroll
    for (int s = 0; s < GST - 1; s++) {
        gemm_issue_stage(smem_base + s * STAGE_FLOATS * 4, Ab, Bb, K, N, s * BK, tid);
        CP_COMMIT();
    }

    const int mrow0 = warpM * 64 + (lane >> 2);
    const int ncol0 = warpN * 64 + (lane >> 2);
    const int klow  = lane & 3;

    for (int kt = 0; kt < KT; kt++) {
        const int buf = kt & (GST - 1);
        CP_WAIT2();
        __syncthreads();

        const int nxt = kt + GST - 1;
        if (nxt < KT)
            gemm_issue_stage(smem_base + (nxt & (GST - 1)) * STAGE_FLOATS * 4,
                             Ab, Bb, K, N, nxt * BK, tid);
        CP_COMMIT();

        const float* as = sm + buf * STAGE_FLOATS;
        const float* bs = as + AS_FLOATS;

        #pragma unroll
        for (int ks = 0; ks < 2; ks++) {
            const int kc = ks * 8 + klow;
            uint32_t af[4][4], bf[8][2];
            #pragma unroll
            for (int mt = 0; mt < 4; mt++) {
                const int mr = mrow0 + mt * 16;
                af[mt][0] = __float_as_uint(as[(mr    ) * AS_STRIDE + kc    ]);
                af[mt][1] = __float_as_uint(as[(mr + 8) * AS_STRIDE + kc    ]);
                af[mt][2] = __float_as_uint(as[(mr    ) * AS_STRIDE + kc + 4]);
                af[mt][3] = __float_as_uint(as[(mr + 8) * AS_STRIDE + kc + 4]);
            }
            #pragma unroll
            for (int nt = 0; nt < 8; nt++) {
                const int nc = ncol0 + nt * 8;
                bf[nt][0] = __float_as_uint(bs[(kc    ) * BS_STRIDE + nc]);
                bf[nt][1] = __float_as_uint(bs[(kc + 4) * BS_STRIDE + nc]);
            }
            #pragma unroll
            for (int mt = 0; mt < 4; mt++)
                #pragma unroll
                for (int nt = 0; nt < 8; nt++)
                    mma_tf32(acc[mt][nt][0], acc[mt][nt][1], acc[mt][nt][2], acc[mt][nt][3],
                             af[mt][0], af[mt][1], af[mt][2], af[mt][3],
                             bf[nt][0], bf[nt][1]);
        }
        __syncthreads();
    }

    float* Cb = Cm + (size_t)blockIdx.y * BM * N + (size_t)blockIdx.x * BN;
    const int ccol0 = warpN * 64 + (lane & 3) * 2;
    #pragma unroll
    for (int mt = 0; mt < 4; mt++) {
        const int r = warpM * 64 + mt * 16 + (lane >> 2);
        #pragma unroll
        for (int nt = 0; nt < 8; nt++) {
            const int cc = ccol0 + nt * 8;
            *(float2*)(Cb + (size_t)r * N + cc)       = make_float2(acc[mt][nt][0], acc[mt][nt][1]);
            *(float2*)(Cb + (size_t)(r + 8) * N + cc) = make_float2(acc[mt][nt][2], acc[mt][nt][3]);
        }
    }
}

// ============================================================================
// Fused per-head RMSNorm + RoPE: warp-per-row, 8 rows/block, no smem/syncs.
// Scales + rna-rounds output (q: 1/sqrt(D); k: 1).
// ============================================================================
__global__ __launch_bounds__(256) void rmsnorm_rope_kernel(
    float* __restrict__ X, const float* __restrict__ fc, int nheads, float scale)
{
    const int row  = blockIdx.x * 8 + (threadIdx.x >> 5);   // global head-row
    const int lane = threadIdx.x & 31;
    const int t    = (row / nheads) % T_;
    float* xp = X + (size_t)row * D_;

    float4 v = *(const float4*)(xp + lane * 4);
    float sq = v.x * v.x + v.y * v.y + v.z * v.z + v.w * v.w;
    #pragma unroll
    for (int o = 16; o > 0; o >>= 1)
        sq += __shfl_xor_sync(0xffffffffu, sq, o);
    const float rinv = rsqrtf(sq * (1.f / (float)D_) + 1e-6f);

    float x0 = v.x * rinv, x1 = v.y * rinv, x2 = v.z * rinv, x3 = v.w * rinv;
    // fc[t, 2p, :] for p = 2*lane, 2*lane+1 is exactly this float4
    float4 cs = *(const float4*)(fc + (size_t)t * D_ + lane * 4);
    float o0 = x0 * cs.x - x1 * cs.y;
    float o1 = x0 * cs.y + x1 * cs.x;
    float o2 = x2 * cs.z - x3 * cs.w;
    float o3 = x2 * cs.w + x3 * cs.z;
    *(float4*)(xp + lane * 4) = make_float4(
        tf32r(o0 * scale), tf32r(o1 * scale), tf32r(o2 * scale), tf32r(o3 * scale));
}

// ============================================================================
// Causal GQA flash attention, tf32 mma.sync (unchanged from R4).
// ============================================================================
#define FKS 132
#define FVS 136
#define FLASH_SMEM ((128 * FKS + 2 * 64 * FKS + 2 * 64 * FVS) * 4)  // 204800 B

__global__ __launch_bounds__(256, 1) void flash_mma_kernel(
    const float* __restrict__ Q, const float* __restrict__ Kg,
    const float* __restrict__ Vg, float* __restrict__ Og)
{
    extern __shared__ float sm[];
    float* Qs = sm;                      // 128 x 132
    float* Ks = sm + 128 * FKS;          // 2 x 64 x 132
    float* Vs = Ks + 2 * 64 * FKS;       // 2 x 64 x 136

    const int tid  = threadIdx.x;
    const int lane = tid & 31, wid = tid >> 5;
    const int r = lane >> 2, c = lane & 3;
    const int b = blockIdx.y / H_, h = blockIdx.y % H_;
    const int kvh = h / REP_;
    const int m0 = blockIdx.x * 128;
    const int wrow = m0 + wid * 16;
    const uint32_t qu = smem_u32(Qs);
    const uint32_t ku = smem_u32(Ks);
    const uint32_t vu = smem_u32(Vs);

    const float* Qb = Q + ((size_t)(b * T_ + m0) * H_ + h) * D_;
    const float* Kb = Kg + ((size_t)b * T_ * HKV_ + kvh) * D_;
    const float* Vb = Vg + ((size_t)b * T_ * HKV_ + kvh) * D_;

    for (int i = tid; i < 128 * 32; i += 256) {
        int row = i >> 5, c4 = i & 31;
        CP_ASYNC16(qu + (uint32_t)(row * FKS + c4 * 4) * 4,
                   Qb + (size_t)row * (H_ * D_) + c4 * 4);
    }
    for (int i = tid; i < 64 * 32; i += 256) {
        int row = i >> 5, c4 = i & 31;
        CP_ASYNC16(ku + (uint32_t)(row * FKS + c4 * 4) * 4,
                   Kb + (size_t)row * (HKV_ * D_) + c4 * 4);
        CP_ASYNC16(vu + (uint32_t)(row * FVS + c4 * 4) * 4,
                   Vb + (size_t)row * (HKV_ * D_) + c4 * 4);
    }
    CP_COMMIT();

    uint32_t qf[16][4];
    float oa[16][4];
    #pragma unroll
    for (int db = 0; db < 16; db++)
        oa[db][0] = oa[db][1] = oa[db][2] = oa[db][3] = 0.f;
    float m0r = -1e30f, m1r = -1e30f, l0 = 0.f, l1 = 0.f;

    const int nT = 2 * (blockIdx.x + 1);
    const int sA = (lane & ~3) | (c >> 1);
    const int sB = sA + 2;

    for (int j = 0; j < nT; j++) {
        const int buf = j & 1;
        const int n0 = j * 64;
        CP_WAIT0();
        __syncthreads();

        if (j + 1 < nT) {
            const int nb2 = buf ^ 1;
            for (int i = tid; i < 64 * 32; i += 256) {
                int row = i >> 5, c4 = i & 31;
                CP_ASYNC16(ku + (uint32_t)(nb2 * 64 * FKS + row * FKS + c4 * 4) * 4,
                           Kb + (size_t)((j + 1) * 64 + row) * (HKV_ * D_) + c4 * 4);
                CP_ASYNC16(vu + (uint32_t)(nb2 * 64 * FVS + row * FVS + c4 * 4) * 4,
                           Vb + (size_t)((j + 1) * 64 + row) * (HKV_ * D_) + c4 * 4);
            }
            CP_COMMIT();
        }

        if (j == 0) {
            const float* qsw = Qs + (wid * 16 + r) * FKS;
            #pragma unroll
            for (int ks = 0; ks < 16; ks++) {
                qf[ks][0] = __float_as_uint(qsw[ks * 8 + c]);
                qf[ks][1] = __float_as_uint(qsw[8 * FKS + ks * 8 + c]);
                qf[ks][2] = __float_as_uint(qsw[ks * 8 + c + 4]);
                qf[ks][3] = __float_as_uint(qsw[8 * FKS + ks * 8 + c + 4]);
            }
        }

        if (n0 > wrow + 15) continue;

        const float* kb = Ks + buf * 64 * FKS;
        float s[8][4];
        #pragma unroll
        for (int nb = 0; nb < 8; nb++)
            s[nb][0] = s[nb][1] = s[nb][2] = s[nb][3] = 0.f;
        #pragma unroll
        for (int ks = 0; ks < 16; ks++) {
            #pragma unroll
            for (int nb = 0; nb < 8; nb++) {
                const float* kp = kb + (nb * 8 + r) * FKS + ks * 8 + c;
                uint32_t b0 = __float_as_uint(kp[0]);
                uint32_t b1 = __float_as_uint(kp[4]);
                mma_tf32(s[nb][0], s[nb][1], s[nb][2], s[nb][3],
                         qf[ks][0], qf[ks][1], qf[ks][2], qf[ks][3], b0, b1);
            }
        }

        if (n0 + 63 > wrow) {
            #pragma unroll
            for (int nb = 0; nb < 8; nb++) {
                int col = n0 + nb * 8 + 2 * c;
                if (col     > wrow + r)     s[nb][0] = -1e30f;
                if (col + 1 > wrow + r)     s[nb][1] = -1e30f;
                if (col     > wrow + r + 8) s[nb][2] = -1e30f;
                if (col + 1 > wrow + r + 8) s[nb][3] = -1e30f;
            }
        }

        float mx0 = -1e30f, mx1 = -1e30f;
        #pragma unroll
        for (int nb = 0; nb < 8; nb++) {
            mx0 = fmaxf(mx0, fmaxf(s[nb][0], s[nb][1]));
            mx1 = fmaxf(mx1, fmaxf(s[nb][2], s[nb][3]));
        }
        mx0 = fmaxf(mx0, __shfl_xor_sync(0xffffffffu, mx0, 1));
        mx0 = fmaxf(mx0, __shfl_xor_sync(0xffffffffu, mx0, 2));
        mx1 = fmaxf(mx1, __shfl_xor_sync(0xffffffffu, mx1, 1));
        mx1 = fmaxf(mx1, __shfl_xor_sync(0xffffffffu, mx1, 2));
        float mn0 = fmaxf(m0r, mx0), mn1 = fmaxf(m1r, mx1);
        float a0 = __expf(m0r - mn0), a1 = __expf(m1r - mn1);
        float ls0 = 0.f, ls1 = 0.f;
        #pragma unroll
        for (int nb = 0; nb < 8; nb++) {
            s[nb][0] = tf32r(__expf(s[nb][0] - mn0));
            s[nb][1] = tf32r(__expf(s[nb][1] - mn0));
            s[nb][2] = tf32r(__expf(s[nb][2] - mn1));
            s[nb][3] = tf32r(__expf(s[nb][3] - mn1));
            ls0 += s[nb][0] + s[nb][1];
            ls1 += s[nb][2] + s[nb][3];
        }
        ls0 += __shfl_xor_sync(0xffffffffu, ls0, 1);
        ls0 += __shfl_xor_sync(0xffffffffu, ls0, 2);
        ls1 += __shfl_xor_sync(0xffffffffu, ls1, 1);
        ls1 += __shfl_xor_sync(0xffffffffu, ls1, 2);
        l0 = l0 * a0 + ls0; l1 = l1 * a1 + ls1;
        m0r = mn0; m1r = mn1;
        #pragma unroll
        for (int db = 0; db < 16; db++) {
            oa[db][0] *= a0; oa[db][1] *= a0;
            oa[db][2] *= a1; oa[db][3] *= a1;
        }

        const float* vb = Vs + buf * 64 * FVS;
        #pragma unroll
        for (int kb2 = 0; kb2 < 8; kb2++) {
            float e, o_;
            e  = __shfl_sync(0xffffffffu, s[kb2][0], sA);
            o_ = __shfl_sync(0xffffffffu, s[kb2][1], sA);
            uint32_t pa0 = __float_as_uint((c & 1) ? o_ : e);
            e  = __shfl_sync(0xffffffffu, s[kb2][0], sB);
            o_ = __shfl_sync(0xffffffffu, s[kb2][1], sB);
            uint32_t pa2 = __float_as_uint((c & 1) ? o_ : e);
            e  = __shfl_sync(0xffffffffu, s[kb2][2], sA);
            o_ = __shfl_sync(0xffffffffu, s[kb2][3], sA);
            uint32_t pa1 = __float_as_uint((c & 1) ? o_ : e);
            e  = __shfl_sync(0xffffffffu, s[kb2][2], sB);
            o_ = __shfl_sync(0xffffffffu, s[kb2][3], sB);
            uint32_t pa3 = __float_as_uint((c & 1) ? o_ : e);
            const float* vp0 = vb + (kb2 * 8 + c) * FVS + r;
            const float* vp1 = vp0 + 4 * FVS;
            #pragma unroll
            for (int db = 0; db < 16; db++) {
                uint32_t b0 = __float_as_uint(vp0[db * 8]);
                uint32_t b1 = __float_as_uint(vp1[db * 8]);
                mma_tf32(oa[db][0], oa[db][1], oa[db][2], oa[db][3],
                         pa0, pa1, pa2, pa3, b0, b1);
            }
        }
    }

    const float i0 = 1.f / l0, i1 = 1.f / l1;
    const int row_g = m0 + wid * 16 + r;
    float* Ob = Og + ((size_t)(b * T_ + row_g) * H_ + h) * D_;
    #pragma unroll
    for (int db = 0; db < 16; db++) {
        *(float2*)(Ob + db * 8 + 2 * c) =
            make_float2(tf32r(oa[db][0] * i0), tf32r(oa[db][1] * i0));
        *(float2*)(Ob + (size_t)8 * H_ * D_ + db * 8 + 2 * c) =
            make_float2(tf32r(oa[db][2] * i1), tf32r(oa[db][3] * i1));
    }
}

// ============================================================================
// Launch
// ============================================================================
extern "C" void kernel_launch(void* const* d_in, const int* in_sizes, int n_in,
                              void* d_out, int out_size)
{
    (void)in_sizes; (void)n_in; (void)out_size;
    const float* x  = (const float*)d_in[0];
    const float* fc = (const float*)d_in[1];
    const float* Wq = (const float*)d_in[2];
    const float* Wk = (const float*)d_in[3];
    const float* Wv = (const float*)d_in[4];
    const float* Wc = (const float*)d_in[5];
    float* out = (float*)d_out;

    float *q, *k, *v, *y, *xa, *wq, *wk, *wv, *wc;
    cudaGetSymbolAddress((void**)&q,  g_q);
    cudaGetSymbolAddress((void**)&k,  g_k);
    cudaGetSymbolAddress((void**)&v,  g_v);
    cudaGetSymbolAddress((void**)&y,  g_y);
    cudaGetSymbolAddress((void**)&xa, g_xa);
    cudaGetSymbolAddress((void**)&wq, g_wqr);
    cudaGetSymbolAddress((void**)&wk, g_wkr);
    cudaGetSymbolAddress((void**)&wv, g_wvr);
    cudaGetSymbolAddress((void**)&wc, g_wcr);

    // tf32-round inputs for the MMA path
    cvt_tf32_kernel<<<(M_ * C_ / 4 + 255) / 256, 256>>>((const float4*)x, (float4*)xa, M_ * C_ / 4);
    cvt_tf32_kernel<<<(C_ * H_ * D_ / 4 + 255) / 256, 256>>>((const float4*)Wq, (float4*)wq, C_ * H_ * D_ / 4);
    cvt_tf32_kernel<<<(C_ * HKV_ * D_ / 4 + 255) / 256, 256>>>((const float4*)Wk, (float4*)wk, C_ * HKV_ * D_ / 4);
    cvt_tf32_kernel<<<(C_ * HKV_ * D_ / 4 + 255) / 256, 256>>>((const float4*)Wv, (float4*)wv, C_ * HKV_ * D_ / 4);
    cvt_tf32_kernel<<<(C_ * C_ / 4 + 255) / 256, 256>>>((const float4*)Wc, (float4*)wc, C_ * C_ / 4);

    cudaFuncSetAttribute(mma_gemm_kernel, cudaFuncAttributeMaxDynamicSharedMemorySize, GEMM_SMEM);

    // QKV projections (tf32 mma.sync, 128-thread CTAs)
    mma_gemm_kernel<<<dim3((H_ * D_) / BN, M_ / BM), 128, GEMM_SMEM>>>(xa, wq, q, H_ * D_, C_);
    mma_gemm_kernel<<<dim3((HKV_ * D_) / BN, M_ / BM), 128, GEMM_SMEM>>>(xa, wk, k, HKV_ * D_, C_);
    mma_gemm_kernel<<<dim3((HKV_ * D_) / BN, M_ / BM), 128, GEMM_SMEM>>>(xa, wv, v, HKV_ * D_, C_);

    // RMSNorm + RoPE (warp-per-row; q pre-scaled by 1/sqrt(D))
    rmsnorm_rope_kernel<<<B_ * T_ * H_ / 8, 256>>>(q, fc, H_, 0.088388347648318447f);
    rmsnorm_rope_kernel<<<B_ * T_ * HKV_ / 8, 256>>>(k, fc, HKV_, 1.0f);
    // V rounded in place for the PV MMA
    cvt_tf32_kernel<<<(M_ * HKV_ * D_ / 4 + 255) / 256, 256>>>((const float4*)v, (float4*)v, M_ * HKV_ * D_ / 4);

    // Flash attention (tf32 mma.sync)
    cudaFuncSetAttribute(flash_mma_kernel, cudaFuncAttributeMaxDynamicSharedMemorySize, FLASH_SMEM);
    flash_mma_kernel<<<dim3(T_ / 128, B_ * H_), 256, FLASH_SMEM>>>(q, k, v, y);

    // Output projection (tf32 mma.sync)
    mma_gemm_kernel<<<dim3(C_ / BN, M_ / BM), 128, GEMM_SMEM>>>(y, wc, out, C_, C_);
}

// round 6
// speedup vs baseline: 15.7989x; 1.8175x over previous
#include <cuda_runtime.h>
#include <cuda_fp16.h>
#include <cstdint>

// Problem constants
#define B_   4
#define T_   2048
#define C_   2048
#define H_   16
#define HKV_ 4
#define REP_ 4
#define D_   128
#define M_   (B_*T_)   // 8192 rows

// Scratch (device globals — no allocation allowed)
__device__ float    g_q [(size_t)M_ * H_ * D_];        // fp32 GEMM outputs
__device__ float    g_k [(size_t)M_ * HKV_ * D_];
__device__ float    g_v [(size_t)M_ * HKV_ * D_];
__device__ __half   g_xh[(size_t)M_ * C_];             // x as fp16
__device__ __half   g_qh[(size_t)M_ * H_ * D_];        // normed+roped q (fp16)
__device__ __half   g_kh[(size_t)M_ * HKV_ * D_];      // normed+roped k (fp16)
__device__ uint32_t g_vh[(size_t)B_ * HKV_ * (T_/2) * D_]; // v token-interleaved half2
__device__ __half   g_yh[(size_t)M_ * C_];             // attention out (fp16)
__device__ uint32_t g_wqh[(size_t)(C_/2) * (H_ * D_)]; // weights K-interleaved half2
__device__ uint32_t g_wkh[(size_t)(C_/2) * (HKV_ * D_)];
__device__ uint32_t g_wvh[(size_t)(C_/2) * (HKV_ * D_)];
__device__ uint32_t g_wch[(size_t)(C_/2) * C_];

// ============================================================================
// Helpers
// ============================================================================
__device__ __forceinline__ uint32_t smem_u32(const void* p) {
    uint32_t a;
    asm("{ .reg .u64 t; cvta.to.shared.u64 t, %1; cvt.u32.u64 %0, t; }" : "=r"(a) : "l"(p));
    return a;
}
__device__ __forceinline__ uint32_t h2u(__half2 h) {
    return *reinterpret_cast<uint32_t*>(&h);
}
#define CP_ASYNC16(dst_u32, src_ptr) \
    asm volatile("cp.async.cg.shared.global [%0], [%1], 16;" \
                 :: "r"(dst_u32), "l"(src_ptr) : "memory")
#define CP_COMMIT() asm volatile("cp.async.commit_group;" ::: "memory")
#define CP_WAIT2()  asm volatile("cp.async.wait_group 2;" ::: "memory")
#define CP_WAIT0()  asm volatile("cp.async.wait_group 0;" ::: "memory")

__device__ __forceinline__ void mma_f16(
    float& c0, float& c1, float& c2, float& c3,
    uint32_t a0, uint32_t a1, uint32_t a2, uint32_t a3,
    uint32_t b0, uint32_t b1)
{
    asm volatile(
        "mma.sync.aligned.m16n8k16.row.col.f32.f16.f16.f32 "
        "{%0,%1,%2,%3}, {%4,%5,%6,%7}, {%8,%9}, {%0,%1,%2,%3};"
        : "+f"(c0), "+f"(c1), "+f"(c2), "+f"(c3)
        : "r"(a0), "r"(a1), "r"(a2), "r"(a3), "r"(b0), "r"(b1));
}

// ============================================================================
// Prep kernels (fp32 -> fp16 conversions / layout transforms)
// ============================================================================
// Plain fp32 -> fp16 (row layout preserved)
__global__ __launch_bounds__(256) void cvt_f2h_kernel(
    const float4* __restrict__ in, uint2* __restrict__ out, int n4)
{
    int i = blockIdx.x * 256 + threadIdx.x;
    if (i < n4) {
        float4 v = in[i];
        uint2 u;
        u.x = h2u(__floats2half2_rn(v.x, v.y));
        u.y = h2u(__floats2half2_rn(v.z, v.w));
        out[i] = u;
    }
}

// W[K][N] fp32 -> Wh2[K/2][N] half2 (pairs along K)
__global__ __launch_bounds__(256) void conv_w_h2_kernel(
    const float* __restrict__ W, uint32_t* __restrict__ Wh2, int K, int N)
{
    int idx = blockIdx.x * 256 + threadIdx.x;
    int total = (K / 2) * N;
    if (idx < total) {
        int k2 = idx / N, n = idx - k2 * N;
        float a = W[(size_t)(2 * k2) * N + n];
        float b = W[(size_t)(2 * k2 + 1) * N + n];
        Wh2[idx] = h2u(__floats2half2_rn(a, b));
    }
}

// v (B,T,HKV,D) fp32 -> g_vh [(b*HKV+kvh)][T/2][D] half2 (pairs along T)
__global__ __launch_bounds__(256) void conv_v_h2_kernel(
    const float* __restrict__ V, uint32_t* __restrict__ Vh2)
{
    int idx = blockIdx.x * 256 + threadIdx.x;
    const int total = B_ * HKV_ * (T_ / 2) * D_;
    if (idx < total) {
        int d   = idx & (D_ - 1);
        int t2  = (idx >> 7) & (T_ / 2 - 1);
        int kvh = (idx >> (7 + 10)) & (HKV_ - 1);
        int b   = idx >> (7 + 10 + 2);
        size_t src = ((size_t)(b * T_ + 2 * t2) * HKV_ + kvh) * D_ + d;
        float a = V[src];
        float c = V[src + (size_t)HKV_ * D_];
        Vh2[idx] = h2u(__floats2half2_rn(a, c));
    }
}

// ============================================================================
// fp16 mma.sync GEMM: C[M,N](fp32) = A[M,K](fp16) @ B[K,N](half2-interleaved)
// 128x128 CTA, BK=32 halves, 128 threads = 4 warps (2Mx2N), warp tile 64x64.
// m16n8k16, 4-stage cp.async pipeline.
// Word-level strides: A 20 (16 data + 4 pad), B 136 (128 + 8 pad).
// ============================================================================
#define BM 128
#define BN 128
#define BKH 32
#define GST 4
#define ASW 20
#define BSW 136
#define AS_WORDS (BM * ASW)            // 2560
#define BS_WORDS (16 * BSW)            // 2176
#define STAGE_WORDS (AS_WORDS + BS_WORDS)
#define GEMM_SMEM (GST * STAGE_WORDS * 4)   // 75776 B

__device__ __forceinline__ void gemm_issue_stage(
    uint32_t stage_u, const __half* __restrict__ Ab,
    const uint32_t* __restrict__ Bb2, int K, int N, int kt, int tid)
{
    // A: 128 rows x 32 halves (16 words); 4 chunks/row
    {
        const int m  = tid >> 2;        // 0..31
        const int c4 = tid & 3;
        const __half* ga = Ab + (size_t)m * K + kt * BKH + c4 * 8;
        uint32_t sa = stage_u + (uint32_t)(m * ASW + c4 * 4) * 4;
        #pragma unroll
        for (int p = 0; p < 4; p++)
            CP_ASYNC16(sa + (uint32_t)(p * 32 * ASW) * 4u, ga + (size_t)(p * 32) * K);
    }
    // B: 16 k2-rows x 128 words; 32 chunks/row
    {
        const int kr = tid >> 3;        // 0..15
        const int f4 = tid & 7;         // 0..7
        const uint32_t* gb = Bb2 + (size_t)(kt * 16 + kr) * N + f4 * 4;
        uint32_t sb = stage_u + (uint32_t)(AS_WORDS + kr * BSW + f4 * 4) * 4;
        #pragma unroll
        for (int p = 0; p < 4; p++)
            CP_ASYNC16(sb + (uint32_t)(p * 32) * 4u, gb + p * 32);
    }
}

__global__ __launch_bounds__(128, 2) void mma_gemm_kernel(
    const __half* __restrict__ A, const uint32_t* __restrict__ B2,
    float* __restrict__ Cm, int N, int K)
{
    extern __shared__ uint32_t sw[];
    const int tid   = threadIdx.x;
    const int lane  = tid & 31;
    const int wid   = tid >> 5;
    const int warpM = wid & 1;
    const int warpN = wid >> 1;

    const __half*   Ab  = A  + (size_t)blockIdx.y * BM * K;
    const uint32_t* Bb2 = B2 + (size_t)blockIdx.x * BN;
    const int KT = K / BKH;
    const uint32_t smem_base = smem_u32(sw);

    float acc[4][8][4];
    #pragma unroll
    for (int i = 0; i < 4; i++)
        #pragma unroll
        for (int j = 0; j < 8; j++)
            #pragma unroll
            for (int c = 0; c < 4; c++) acc[i][j][c] = 0.f;

    #pragma unroll
    for (int s = 0; s < GST - 1; s++) {
        gemm_issue_stage(smem_base + s * STAGE_WORDS * 4, Ab, Bb2, K, N, s, tid);
        CP_COMMIT();
    }

    const int r = lane >> 2, c = lane & 3;
    const int mrow0 = warpM * 64 + r;
    const int ncol0 = warpN * 64 + r;

    for (int kt = 0; kt < KT; kt++) {
        const int buf = kt & (GST - 1);
        CP_WAIT2();
        __syncthreads();

        const int nxt = kt + GST - 1;
        if (nxt < KT)
            gemm_issue_stage(smem_base + (nxt & (GST - 1)) * STAGE_WORDS * 4,
                             Ab, Bb2, K, N, nxt, tid);
        CP_COMMIT();

        const uint32_t* as = sw + buf * STAGE_WORDS;
        const uint32_t* bs = as + AS_WORDS;

        #pragma unroll
        for (int ks = 0; ks < 2; ks++) {
            uint32_t af[4][4], bf[8][2];
            #pragma unroll
            for (int mt = 0; mt < 4; mt++) {
                const int mr = mrow0 + mt * 16;
                const uint32_t* ar0 = as + mr * ASW + ks * 8 + c;
                const uint32_t* ar1 = as + (mr + 8) * ASW + ks * 8 + c;
                af[mt][0] = ar0[0];
                af[mt][1] = ar1[0];
                af[mt][2] = ar0[4];
                af[mt][3] = ar1[4];
            }
            #pragma unroll
            for (int nt = 0; nt < 8; nt++) {
                const int nc = ncol0 + nt * 8;
                bf[nt][0] = bs[(ks * 8 + c) * BSW + nc];
                bf[nt][1] = bs[(ks * 8 + 4 + c) * BSW + nc];
            }
            #pragma unroll
            for (int mt = 0; mt < 4; mt++)
                #pragma unroll
                for (int nt = 0; nt < 8; nt++)
                    mma_f16(acc[mt][nt][0], acc[mt][nt][1], acc[mt][nt][2], acc[mt][nt][3],
                            af[mt][0], af[mt][1], af[mt][2], af[mt][3],
                            bf[nt][0], bf[nt][1]);
        }
        __syncthreads();
    }

    float* Cb = Cm + (size_t)blockIdx.y * BM * N + (size_t)blockIdx.x * BN;
    const int ccol0 = warpN * 64 + c * 2;
    #pragma unroll
    for (int mt = 0; mt < 4; mt++) {
        const int rr = warpM * 64 + mt * 16 + r;
        #pragma unroll
        for (int nt = 0; nt < 8; nt++) {
            const int cc = ccol0 + nt * 8;
            *(float2*)(Cb + (size_t)rr * N + cc)       = make_float2(acc[mt][nt][0], acc[mt][nt][1]);
            *(float2*)(Cb + (size_t)(rr + 8) * N + cc) = make_float2(acc[mt][nt][2], acc[mt][nt][3]);
        }
    }
}

// ============================================================================
// RMSNorm + RoPE: warp-per-row, fp32 in -> fp16 out (scaled).
// ============================================================================
__global__ __launch_bounds__(256) void rmsnorm_rope_h_kernel(
    const float* __restrict__ X, __half* __restrict__ XH,
    const float* __restrict__ fc, int nheads, float scale)
{
    const int row  = blockIdx.x * 8 + (threadIdx.x >> 5);
    const int lane = threadIdx.x & 31;
    const int t    = (row / nheads) % T_;
    const float* xp = X + (size_t)row * D_;

    float4 v = *(const float4*)(xp + lane * 4);
    float sq = v.x * v.x + v.y * v.y + v.z * v.z + v.w * v.w;
    #pragma unroll
    for (int o = 16; o > 0; o >>= 1)
        sq += __shfl_xor_sync(0xffffffffu, sq, o);
    const float rinv = rsqrtf(sq * (1.f / (float)D_) + 1e-6f) * scale;

    float x0 = v.x * rinv, x1 = v.y * rinv, x2 = v.z * rinv, x3 = v.w * rinv;
    float4 cs = *(const float4*)(fc + (size_t)t * D_ + lane * 4);
    float o0 = x0 * cs.x - x1 * cs.y;
    float o1 = x0 * cs.y + x1 * cs.x;
    float o2 = x2 * cs.z - x3 * cs.w;
    float o3 = x2 * cs.w + x3 * cs.z;

    uint2 u;
    u.x = h2u(__floats2half2_rn(o0, o1));
    u.y = h2u(__floats2half2_rn(o2, o3));
    *(uint2*)(XH + (size_t)row * D_ + lane * 4) = u;
}

// ============================================================================
// Causal GQA flash attention, fp16 mma.sync (m16n8k16).
// 128 q-rows/CTA, 64 keys/tile, 256 threads = 8 warps x 16 rows.
// Q/K smem stride 68 words (half rows), V stride 136 words (half2 rows).
// P -> A-frag by register packing (no shuffles).
// ============================================================================
#define QKW 68
#define VW  136
#define FLASH_WORDS (128 * QKW + 2 * 64 * QKW + 2 * 32 * VW)   // 26112 words
#define FLASH_SMEM  (FLASH_WORDS * 4)                          // 104448 B

__global__ __launch_bounds__(256, 1) void flash_mma_kernel(
    const __half* __restrict__ Qh, const __half* __restrict__ Kh,
    const uint32_t* __restrict__ Vh2, __half* __restrict__ Oh)
{
    extern __shared__ uint32_t sw[];
    uint32_t* Qs = sw;                       // 128 x 68 words
    uint32_t* Ks = sw + 128 * QKW;           // 2 x 64 x 68
    uint32_t* Vs = Ks + 2 * 64 * QKW;        // 2 x 32 x 136

    const int tid  = threadIdx.x;
    const int lane = tid & 31, wid = tid >> 5;
    const int r = lane >> 2, c = lane & 3;
    const int b = blockIdx.y / H_, h = blockIdx.y % H_;
    const int kvh = h / REP_;
    const int m0 = blockIdx.x * 128;
    const int wrow = m0 + wid * 16;
    const uint32_t qu = smem_u32(Qs);
    const uint32_t ku = smem_u32(Ks);
    const uint32_t vu = smem_u32(Vs);

    const __half* Qb = Qh + ((size_t)(b * T_ + m0) * H_ + h) * D_;
    const __half* Kb = Kh + ((size_t)b * T_ * HKV_ + kvh) * D_;
    const uint32_t* Vb = Vh2 + (size_t)(b * HKV_ + kvh) * (T_ / 2) * D_;

    // Q tile: 128 rows x 16 chunks
    for (int i = tid; i < 128 * 16; i += 256) {
        int row = i >> 4, c4 = i & 15;
        CP_ASYNC16(qu + (uint32_t)(row * QKW + c4 * 4) * 4,
                   Qb + (size_t)row * (H_ * D_) + c4 * 8);
    }
    // KV tile 0
    for (int i = tid; i < 64 * 16; i += 256) {
        int row = i >> 4, c4 = i & 15;
        CP_ASYNC16(ku + (uint32_t)(row * QKW + c4 * 4) * 4,
                   Kb + (size_t)row * (HKV_ * D_) + c4 * 8);
    }
    for (int i = tid; i < 32 * 32; i += 256) {
        int row = i >> 5, c4 = i & 31;
        CP_ASYNC16(vu + (uint32_t)(row * VW + c4 * 4) * 4,
                   Vb + (size_t)row * D_ + c4 * 4);
    }
    CP_COMMIT();

    uint32_t qf[8][4];
    float oa[16][4];
    #pragma unroll
    for (int db = 0; db < 16; db++)
        oa[db][0] = oa[db][1] = oa[db][2] = oa[db][3] = 0.f;
    float m0r = -1e30f, m1r = -1e30f, l0 = 0.f, l1 = 0.f;

    const int nT = 2 * (blockIdx.x + 1);

    for (int j = 0; j < nT; j++) {
        const int buf = j & 1;
        const int n0 = j * 64;
        CP_WAIT0();
        __syncthreads();

        // prefetch next KV tile
        if (j + 1 < nT) {
            const int nb2 = buf ^ 1;
            for (int i = tid; i < 64 * 16; i += 256) {
                int row = i >> 4, c4 = i & 15;
                CP_ASYNC16(ku + (uint32_t)(nb2 * 64 * QKW + row * QKW + c4 * 4) * 4,
                           Kb + (size_t)((j + 1) * 64 + row) * (HKV_ * D_) + c4 * 8);
            }
            for (int i = tid; i < 32 * 32; i += 256) {
                int row = i >> 5, c4 = i & 31;
                CP_ASYNC16(vu + (uint32_t)(nb2 * 32 * VW + row * VW + c4 * 4) * 4,
                           Vb + (size_t)((j + 1) * 32 + row) * D_ + c4 * 4);
            }
            CP_COMMIT();
        }

        if (j == 0) {
            const uint32_t* qsw = Qs + (wid * 16 + r) * QKW;
            #pragma unroll
            for (int ks = 0; ks < 8; ks++) {
                qf[ks][0] = qsw[ks * 8 + c];
                qf[ks][1] = qsw[8 * QKW + ks * 8 + c];
                qf[ks][2] = qsw[ks * 8 + c + 4];
                qf[ks][3] = qsw[8 * QKW + ks * 8 + c + 4];
            }
        }

        if (n0 > wrow + 15) continue;   // fully masked warp tile

        // S = Q @ K^T (16 x 64 per warp)
        const uint32_t* kb = Ks + buf * 64 * QKW;
        float s[8][4];
        #pragma unroll
        for (int nb = 0; nb < 8; nb++)
            s[nb][0] = s[nb][1] = s[nb][2] = s[nb][3] = 0.f;
        #pragma unroll
        for (int ks = 0; ks < 8; ks++) {
            #pragma unroll
            for (int nb = 0; nb < 8; nb++) {
                const uint32_t* kp = kb + (nb * 8 + r) * QKW + ks * 8 + c;
                mma_f16(s[nb][0], s[nb][1], s[nb][2], s[nb][3],
                        qf[ks][0], qf[ks][1], qf[ks][2], qf[ks][3],
                        kp[0], kp[4]);
            }
        }

        // causal mask near diagonal
        if (n0 + 63 > wrow) {
            #pragma unroll
            for (int nb = 0; nb < 8; nb++) {
                int col = n0 + nb * 8 + 2 * c;
                if (col     > wrow + r)     s[nb][0] = -1e30f;
                if (col + 1 > wrow + r)     s[nb][1] = -1e30f;
                if (col     > wrow + r + 8) s[nb][2] = -1e30f;
                if (col + 1 > wrow + r + 8) s[nb][3] = -1e30f;
            }
        }

        // online softmax (rows r and r+8), p rounded to fp16 consistently
        float mx0 = -1e30f, mx1 = -1e30f;
        #pragma unroll
        for (int nb = 0; nb < 8; nb++) {
            mx0 = fmaxf(mx0, fmaxf(s[nb][0], s[nb][1]));
            mx1 = fmaxf(mx1, fmaxf(s[nb][2], s[nb][3]));
        }
        mx0 = fmaxf(mx0, __shfl_xor_sync(0xffffffffu, mx0, 1));
        mx0 = fmaxf(mx0, __shfl_xor_sync(0xffffffffu, mx0, 2));
        mx1 = fmaxf(mx1, __shfl_xor_sync(0xffffffffu, mx1, 1));
        mx1 = fmaxf(mx1, __shfl_xor_sync(0xffffffffu, mx1, 2));
        float mn0 = fmaxf(m0r, mx0), mn1 = fmaxf(m1r, mx1);
        float a0 = __expf(m0r - mn0), a1 = __expf(m1r - mn1);
        float ls0 = 0.f, ls1 = 0.f;
        #pragma unroll
        for (int nb = 0; nb < 8; nb++) {
            s[nb][0] = __half2float(__float2half_rn(__expf(s[nb][0] - mn0)));
            s[nb][1] = __half2float(__float2half_rn(__expf(s[nb][1] - mn0)));
            s[nb][2] = __half2float(__float2half_rn(__expf(s[nb][2] - mn1)));
            s[nb][3] = __half2float(__float2half_rn(__expf(s[nb][3] - mn1)));
            ls0 += s[nb][0] + s[nb][1];
            ls1 += s[nb][2] + s[nb][3];
        }
        ls0 += __shfl_xor_sync(0xffffffffu, ls0, 1);
        ls0 += __shfl_xor_sync(0xffffffffu, ls0, 2);
        ls1 += __shfl_xor_sync(0xffffffffu, ls1, 1);
        ls1 += __shfl_xor_sync(0xffffffffu, ls1, 2);
        l0 = l0 * a0 + ls0; l1 = l1 * a1 + ls1;
        m0r = mn0; m1r = mn1;
        #pragma unroll
        for (int db = 0; db < 16; db++) {
            oa[db][0] *= a0; oa[db][1] *= a0;
            oa[db][2] *= a1; oa[db][3] *= a1;
        }

        // O += P @ V : P packed to fp16 A-frags in registers (no shuffles)
        const uint32_t* vb = Vs + buf * 32 * VW;
        #pragma unroll
        for (int kb2 = 0; kb2 < 4; kb2++) {
            uint32_t pa0 = h2u(__floats2half2_rn(s[2*kb2][0],   s[2*kb2][1]));
            uint32_t pa1 = h2u(__floats2half2_rn(s[2*kb2][2],   s[2*kb2][3]));
            uint32_t pa2 = h2u(__floats2half2_rn(s[2*kb2+1][0], s[2*kb2+1][1]));
            uint32_t pa3 = h2u(__floats2half2_rn(s[2*kb2+1][2], s[2*kb2+1][3]));
            const uint32_t* vp0 = vb + (kb2 * 8 + c) * VW + r;
            const uint32_t* vp1 = vp0 + 4 * VW;
            #pragma unroll
            for (int db = 0; db < 16; db++) {
                mma_f16(oa[db][0], oa[db][1], oa[db][2], oa[db][3],
                        pa0, pa1, pa2, pa3, vp0[db * 8], vp1[db * 8]);
            }
        }
    }

    // epilogue: normalize, store fp16 y
    const float i0 = 1.f / l0, i1 = 1.f / l1;
    const int row_g = m0 + wid * 16 + r;
    __half* Ob = Oh + ((size_t)(b * T_ + row_g) * H_ + h) * D_;
    #pragma unroll
    for (int db = 0; db < 16; db++) {
        *(uint32_t*)(Ob + db * 8 + 2 * c) =
            h2u(__floats2half2_rn(oa[db][0] * i0, oa[db][1] * i0));
        *(uint32_t*)(Ob + (size_t)8 * H_ * D_ + db * 8 + 2 * c) =
            h2u(__floats2half2_rn(oa[db][2] * i1, oa[db][3] * i1));
    }
}

// ============================================================================
// Launch
// ============================================================================
extern "C" void kernel_launch(void* const* d_in, const int* in_sizes, int n_in,
                              void* d_out, int out_size)
{
    (void)in_sizes; (void)n_in; (void)out_size;
    const float* x  = (const float*)d_in[0];
    const float* fc = (const float*)d_in[1];
    const float* Wq = (const float*)d_in[2];
    const float* Wk = (const float*)d_in[3];
    const float* Wv = (const float*)d_in[4];
    const float* Wc = (const float*)d_in[5];
    float* out = (float*)d_out;

    float *q, *k, *v;
    __half *xh, *qh, *kh, *yh;
    uint32_t *vh, *wqh, *wkh, *wvh, *wch;
    cudaGetSymbolAddress((void**)&q,   g_q);
    cudaGetSymbolAddress((void**)&k,   g_k);
    cudaGetSymbolAddress((void**)&v,   g_v);
    cudaGetSymbolAddress((void**)&xh,  g_xh);
    cudaGetSymbolAddress((void**)&qh,  g_qh);
    cudaGetSymbolAddress((void**)&kh,  g_kh);
    cudaGetSymbolAddress((void**)&vh,  g_vh);
    cudaGetSymbolAddress((void**)&yh,  g_yh);
    cudaGetSymbolAddress((void**)&wqh, g_wqh);
    cudaGetSymbolAddress((void**)&wkh, g_wkh);
    cudaGetSymbolAddress((void**)&wvh, g_wvh);
    cudaGetSymbolAddress((void**)&wch, g_wch);

    // Prep: x -> fp16, weights -> K-interleaved half2
    cvt_f2h_kernel<<<(M_ * C_ / 4 + 255) / 256, 256>>>(
        (const float4*)x, (uint2*)xh, M_ * C_ / 4);
    conv_w_h2_kernel<<<((C_/2) * H_ * D_ + 255) / 256, 256>>>(Wq, wqh, C_, H_ * D_);
    conv_w_h2_kernel<<<((C_/2) * HKV_ * D_ + 255) / 256, 256>>>(Wk, wkh, C_, HKV_ * D_);
    conv_w_h2_kernel<<<((C_/2) * HKV_ * D_ + 255) / 256, 256>>>(Wv, wvh, C_, HKV_ * D_);
    conv_w_h2_kernel<<<((C_/2) * C_ + 255) / 256, 256>>>(Wc, wch, C_, C_);

    cudaFuncSetAttribute(mma_gemm_kernel, cudaFuncAttributeMaxDynamicSharedMemorySize, GEMM_SMEM);

    // QKV projections (fp16 mma)
    mma_gemm_kernel<<<dim3((H_ * D_) / BN, M_ / BM), 128, GEMM_SMEM>>>(xh, wqh, q, H_ * D_, C_);
    mma_gemm_kernel<<<dim3((HKV_ * D_) / BN, M_ / BM), 128, GEMM_SMEM>>>(xh, wkh, k, HKV_ * D_, C_);
    mma_gemm_kernel<<<dim3((HKV_ * D_) / BN, M_ / BM), 128, GEMM_SMEM>>>(xh, wvh, v, HKV_ * D_, C_);

    // RMSNorm + RoPE -> fp16 (q pre-scaled by 1/sqrt(D)); v -> interleaved half2
    rmsnorm_rope_h_kernel<<<B_ * T_ * H_ / 8, 256>>>(q, qh, fc, H_, 0.088388347648318447f);
    rmsnorm_rope_h_kernel<<<B_ * T_ * HKV_ / 8, 256>>>(k, kh, fc, HKV_, 1.0f);
    conv_v_h2_kernel<<<(B_ * HKV_ * (T_/2) * D_ + 255) / 256, 256>>>(v, vh);

    // Flash attention (fp16 mma)
    cudaFuncSetAttribute(flash_mma_kernel, cudaFuncAttributeMaxDynamicSharedMemorySize, FLASH_SMEM);
    flash_mma_kernel<<<dim3(T_ / 128, B_ * H_), 256, FLASH_SMEM>>>(qh, kh, vh, yh);

    // Output projection (fp16 mma, fp32 out)
    mma_gemm_kernel<<<dim3(C_ / BN, M_ / BM), 128, GEMM_SMEM>>>(yh, wch, out, C_, C_);
}

// round 7
// speedup vs baseline: 17.1939x; 1.0883x over previous
#include <cuda_runtime.h>
#include <cuda_fp16.h>
#include <cstdint>

// Problem constants
#define B_   4
#define T_   2048
#define C_   2048
#define H_   16
#define HKV_ 4
#define REP_ 4
#define D_   128
#define M_   (B_*T_)   // 8192 rows
#define K2C  (C_/2)    // 1024 half2 words along K

// Scratch (device globals — no allocation allowed)
__device__ __half   g_xh[(size_t)M_ * C_];                 // x as fp16
__device__ __half   g_qg[(size_t)M_ * H_ * D_];            // raw q (fp16, GEMM out)
__device__ __half   g_kg[(size_t)M_ * HKV_ * D_];
__device__ __half   g_vg[(size_t)M_ * HKV_ * D_];
__device__ __half   g_qh[(size_t)M_ * H_ * D_];            // normed+roped q
__device__ __half   g_kh[(size_t)M_ * HKV_ * D_];
__device__ uint32_t g_vh[(size_t)B_ * HKV_ * D_ * (T_/2)]; // V as [bk][d][t2] half2
__device__ __half   g_yh[(size_t)M_ * C_];                 // attention out
__device__ uint32_t g_wqt[(size_t)(H_ * D_) * K2C];        // W^T as [n][k2] half2
__device__ uint32_t g_wkt[(size_t)(HKV_ * D_) * K2C];
__device__ uint32_t g_wvt[(size_t)(HKV_ * D_) * K2C];
__device__ uint32_t g_wct[(size_t)C_ * K2C];

// ============================================================================
// Helpers
// ============================================================================
__device__ __forceinline__ uint32_t smem_u32(const void* p) {
    uint32_t a;
    asm("{ .reg .u64 t; cvta.to.shared.u64 t, %1; cvt.u32.u64 %0, t; }" : "=r"(a) : "l"(p));
    return a;
}
__device__ __forceinline__ uint32_t h2u(__half2 h) {
    return *reinterpret_cast<uint32_t*>(&h);
}
#define CP_ASYNC16(dst_u32, src_ptr) \
    asm volatile("cp.async.cg.shared.global [%0], [%1], 16;" \
                 :: "r"(dst_u32), "l"(src_ptr) : "memory")
#define CP_COMMIT() asm volatile("cp.async.commit_group;" ::: "memory")
#define CP_WAIT2()  asm volatile("cp.async.wait_group 2;" ::: "memory")
#define CP_WAIT0()  asm volatile("cp.async.wait_group 0;" ::: "memory")

__device__ __forceinline__ void mma_f16(
    float& c0, float& c1, float& c2, float& c3,
    uint32_t a0, uint32_t a1, uint32_t a2, uint32_t a3,
    uint32_t b0, uint32_t b1)
{
    asm volatile(
        "mma.sync.aligned.m16n8k16.row.col.f32.f16.f16.f32 "
        "{%0,%1,%2,%3}, {%4,%5,%6,%7}, {%8,%9}, {%0,%1,%2,%3};"
        : "+f"(c0), "+f"(c1), "+f"(c2), "+f"(c3)
        : "r"(a0), "r"(a1), "r"(a2), "r"(a3), "r"(b0), "r"(b1));
}
__device__ __forceinline__ void ldsm4(
    uint32_t& r0, uint32_t& r1, uint32_t& r2, uint32_t& r3, uint32_t a)
{
    asm volatile("ldmatrix.sync.aligned.m8n8.x4.shared.b16 {%0,%1,%2,%3}, [%4];"
                 : "=r"(r0), "=r"(r1), "=r"(r2), "=r"(r3) : "r"(a));
}
__device__ __forceinline__ void store2(float* p, float a, float b) {
    *(float2*)p = make_float2(a, b);
}
__device__ __forceinline__ void store2(__half* p, float a, float b) {
    *(uint32_t*)p = h2u(__floats2half2_rn(a, b));
}

// ============================================================================
// Prep kernels
// ============================================================================
__global__ __launch_bounds__(256) void cvt_f2h_kernel(
    const float4* __restrict__ in, uint2* __restrict__ out, int n4)
{
    int i = blockIdx.x * 256 + threadIdx.x;
    if (i < n4) {
        float4 v = in[i];
        uint2 u;
        u.x = h2u(__floats2half2_rn(v.x, v.y));
        u.y = h2u(__floats2half2_rn(v.z, v.w));
        out[i] = u;
    }
}

// W[K][N] fp32 -> Wt2[N][K/2] half2 (pairs along K), tiled transpose
__global__ __launch_bounds__(256) void conv_wt_kernel(
    const float* __restrict__ W, uint32_t* __restrict__ Wt2, int K, int N)
{
    __shared__ uint32_t ts[32][33];
    const int n0 = blockIdx.x * 32, k20 = blockIdx.y * 32;
    const int tx = threadIdx.x, ty = threadIdx.y;
    #pragma unroll
    for (int i = 0; i < 4; i++) {
        int k2 = k20 + ty + i * 8;
        float a = W[(size_t)(2 * k2) * N + n0 + tx];
        float b = W[(size_t)(2 * k2 + 1) * N + n0 + tx];
        ts[ty + i * 8][tx] = h2u(__floats2half2_rn(a, b));
    }
    __syncthreads();
    const int K2 = K / 2;
    #pragma unroll
    for (int i = 0; i < 4; i++)
        Wt2[(size_t)(n0 + ty + i * 8) * K2 + k20 + tx] = ts[tx][ty + i * 8];
}

// v (B,T,HKV,D) fp16 -> [bk][d][T/2] half2 (pairs along T)
__global__ __launch_bounds__(256) void conv_v_kernel(
    const __half* __restrict__ V, uint32_t* __restrict__ Vt2)
{
    int idx = blockIdx.x * 256 + threadIdx.x;
    const int total = B_ * HKV_ * D_ * (T_ / 2);
    if (idx < total) {
        int t2  = idx & (T_ / 2 - 1);
        int d   = (idx >> 10) & (D_ - 1);
        int kvh = (idx >> 17) & (HKV_ - 1);
        int b   = idx >> 19;
        size_t src = ((size_t)(b * T_ + 2 * t2) * HKV_ + kvh) * D_ + d;
        Vt2[idx] = h2u(__halves2half2(V[src], V[src + (size_t)HKV_ * D_]));
    }
}

// ============================================================================
// fp16 mma.sync GEMM via ldmatrix: C[M,N] = A[M,K](fp16) @ Wt2[N][K/2]^T
// 128x128 CTA, BK=32 halves, 128 threads = 4 warps (2Mx2N), warp tile 64x64.
// A and B smem tiles are both 128 rows x 16 words, stride 20 words.
// ============================================================================
#define BM 128
#define BN 128
#define GST 4
#define ASW 20
#define BS_OFF (BM * ASW)               // 2560 words
#define STAGE_WORDS (2 * BM * ASW)      // 5120 words
#define GEMM_SMEM (GST * STAGE_WORDS * 4)  // 81920 B

__device__ __forceinline__ void gemm_issue_stage(
    uint32_t stage_u, const __half* __restrict__ Ab,
    const uint32_t* __restrict__ Bb2, int K, int kt, int tid)
{
    const int K2 = K / 2;
    const int rr = tid >> 2;        // 0..31
    const int c4 = tid & 3;
    const __half* ga = Ab + (size_t)rr * K + kt * 32 + c4 * 8;
    uint32_t sa = stage_u + (uint32_t)(rr * ASW + c4 * 4) * 4;
    #pragma unroll
    for (int p = 0; p < 4; p++)
        CP_ASYNC16(sa + (uint32_t)(p * 32 * ASW) * 4u, ga + (size_t)(p * 32) * K);
    const uint32_t* gb = Bb2 + (size_t)rr * K2 + kt * 16 + c4 * 4;
    uint32_t sb = stage_u + (uint32_t)(BS_OFF + rr * ASW + c4 * 4) * 4;
    #pragma unroll
    for (int p = 0; p < 4; p++)
        CP_ASYNC16(sb + (uint32_t)(p * 32 * ASW) * 4u, gb + (size_t)(p * 32) * K2);
}

template <typename OutT>
__global__ __launch_bounds__(128, 2) void mma_gemm_kernel(
    const __half* __restrict__ A, const uint32_t* __restrict__ B2,
    OutT* __restrict__ Cm, int N, int K)
{
    extern __shared__ uint32_t sw[];
    const int tid   = threadIdx.x;
    const int lane  = tid & 31;
    const int wid   = tid >> 5;
    const int warpM = wid & 1;
    const int warpN = wid >> 1;

    const __half*   Ab  = A  + (size_t)blockIdx.y * BM * K;
    const uint32_t* Bb2 = B2 + (size_t)blockIdx.x * BN * (K / 2);
    const int KT = K / 32;
    const uint32_t smem_base = smem_u32(sw);

    float acc[4][8][4];
    #pragma unroll
    for (int i = 0; i < 4; i++)
        #pragma unroll
        for (int j = 0; j < 8; j++)
            #pragma unroll
            for (int c = 0; c < 4; c++) acc[i][j][c] = 0.f;

    #pragma unroll
    for (int s = 0; s < GST - 1; s++) {
        gemm_issue_stage(smem_base + s * STAGE_WORDS * 4, Ab, Bb2, K, s, tid);
        CP_COMMIT();
    }

    // ldmatrix per-lane word offsets (A-type and B-type patterns)
    const uint32_t aoff = (uint32_t)((warpM * 64 + (lane & 15)) * ASW + (lane >> 4) * 4) * 4;
    const uint32_t boff = (uint32_t)((BS_OFF + (warpN * 64 + (lane & 7) + ((lane >> 4) << 3)) * ASW)
                                     + ((lane >> 3) & 1) * 4) * 4;

    for (int kt = 0; kt < KT; kt++) {
        const int buf = kt & (GST - 1);
        CP_WAIT2();
        __syncthreads();

        const int nxt = kt + GST - 1;
        if (nxt < KT)
            gemm_issue_stage(smem_base + (nxt & (GST - 1)) * STAGE_WORDS * 4,
                             Ab, Bb2, K, nxt, tid);
        CP_COMMIT();

        const uint32_t stage_u = smem_base + buf * STAGE_WORDS * 4;
        #pragma unroll
        for (int ks = 0; ks < 2; ks++) {
            uint32_t af[4][4], bf[8][2];
            #pragma unroll
            for (int mt = 0; mt < 4; mt++)
                ldsm4(af[mt][0], af[mt][1], af[mt][2], af[mt][3],
                      stage_u + aoff + (uint32_t)(mt * 16 * ASW + ks * 8) * 4);
            #pragma unroll
            for (int np = 0; np < 4; np++)
                ldsm4(bf[2*np][0], bf[2*np][1], bf[2*np+1][0], bf[2*np+1][1],
                      stage_u + boff + (uint32_t)(np * 16 * ASW + ks * 8) * 4);
            #pragma unroll
            for (int mt = 0; mt < 4; mt++)
                #pragma unroll
                for (int nt = 0; nt < 8; nt++)
                    mma_f16(acc[mt][nt][0], acc[mt][nt][1], acc[mt][nt][2], acc[mt][nt][3],
                            af[mt][0], af[mt][1], af[mt][2], af[mt][3],
                            bf[nt][0], bf[nt][1]);
        }
        __syncthreads();
    }

    OutT* Cb = Cm + (size_t)blockIdx.y * BM * N + (size_t)blockIdx.x * BN;
    const int r = lane >> 2, c = lane & 3;
    const int ccol0 = warpN * 64 + c * 2;
    #pragma unroll
    for (int mt = 0; mt < 4; mt++) {
        const int rr = warpM * 64 + mt * 16 + r;
        #pragma unroll
        for (int nt = 0; nt < 8; nt++) {
            const int cc = ccol0 + nt * 8;
            store2(Cb + (size_t)rr * N + cc,       acc[mt][nt][0], acc[mt][nt][1]);
            store2(Cb + (size_t)(rr + 8) * N + cc, acc[mt][nt][2], acc[mt][nt][3]);
        }
    }
}

// ============================================================================
// RMSNorm + RoPE: warp-per-row, fp16 in -> fp16 out (scaled).
// ============================================================================
__global__ __launch_bounds__(256) void rmsnorm_rope_h_kernel(
    const __half* __restrict__ X, __half* __restrict__ XH,
    const float* __restrict__ fc, int nheads, float scale)
{
    const int row  = blockIdx.x * 8 + (threadIdx.x >> 5);
    const int lane = threadIdx.x & 31;
    const int t    = (row / nheads) % T_;
    const __half* xp = X + (size_t)row * D_;

    uint2 u = *(const uint2*)(xp + lane * 4);
    __half2 hx = *(__half2*)&u.x, hy = *(__half2*)&u.y;
    float x0 = __low2float(hx), x1 = __high2float(hx);
    float x2 = __low2float(hy), x3 = __high2float(hy);
    float sq = x0 * x0 + x1 * x1 + x2 * x2 + x3 * x3;
    #pragma unroll
    for (int o = 16; o > 0; o >>= 1)
        sq += __shfl_xor_sync(0xffffffffu, sq, o);
    const float rinv = rsqrtf(sq * (1.f / (float)D_) + 1e-6f) * scale;

    x0 *= rinv; x1 *= rinv; x2 *= rinv; x3 *= rinv;
    float4 cs = *(const float4*)(fc + (size_t)t * D_ + lane * 4);
    float o0 = x0 * cs.x - x1 * cs.y;
    float o1 = x0 * cs.y + x1 * cs.x;
    float o2 = x2 * cs.z - x3 * cs.w;
    float o3 = x2 * cs.w + x3 * cs.z;

    uint2 w;
    w.x = h2u(__floats2half2_rn(o0, o1));
    w.y = h2u(__floats2half2_rn(o2, o3));
    *(uint2*)(XH + (size_t)row * D_ + lane * 4) = w;
}

// ============================================================================
// Causal GQA flash attention, fp16 mma.sync + ldmatrix.
// 128 q-rows/CTA, 64 keys/tile, 256 threads = 8 warps x 16 rows.
// Q/K smem: [row][d2] stride 68 words. V smem: [d][t2] stride 36 words.
// ============================================================================
#define QKW 68
#define VSW 36
#define VBUF (128 * VSW)   // 4608 words per buffer
#define FLASH_WORDS (128 * QKW + 2 * 64 * QKW + 2 * VBUF)   // 26624
#define FLASH_SMEM  (FLASH_WORDS * 4)                       // 106496 B

__global__ __launch_bounds__(256, 1) void flash_mma_kernel(
    const __half* __restrict__ Qh, const __half* __restrict__ Kh,
    const uint32_t* __restrict__ Vt2, __half* __restrict__ Oh)
{
    extern __shared__ uint32_t sw[];
    uint32_t* Qs = sw;                       // 128 x 68
    uint32_t* Ks = sw + 128 * QKW;           // 2 x 64 x 68
    uint32_t* Vs = Ks + 2 * 64 * QKW;        // 2 x 128 x 36

    const int tid  = threadIdx.x;
    const int lane = tid & 31, wid = tid >> 5;
    const int r = lane >> 2, c = lane & 3;
    const int b = blockIdx.y / H_, h = blockIdx.y % H_;
    const int kvh = h / REP_;
    const int m0 = blockIdx.x * 128;
    const int wrow = m0 + wid * 16;
    const uint32_t qu = smem_u32(Qs);
    const uint32_t ku = smem_u32(Ks);
    const uint32_t vu = smem_u32(Vs);

    const __half* Qb = Qh + ((size_t)(b * T_ + m0) * H_ + h) * D_;
    const __half* Kb = Kh + ((size_t)b * T_ * HKV_ + kvh) * D_;
    const uint32_t* Vb = Vt2 + (size_t)(b * HKV_ + kvh) * D_ * (T_ / 2);

    // Q tile
    for (int i = tid; i < 128 * 16; i += 256) {
        int row = i >> 4, c4 = i & 15;
        CP_ASYNC16(qu + (uint32_t)(row * QKW + c4 * 4) * 4,
                   Qb + (size_t)row * (H_ * D_) + c4 * 8);
    }
    // KV tile 0
    for (int i = tid; i < 64 * 16; i += 256) {
        int row = i >> 4, c4 = i & 15;
        CP_ASYNC16(ku + (uint32_t)(row * QKW + c4 * 4) * 4,
                   Kb + (size_t)row * (HKV_ * D_) + c4 * 8);
    }
    for (int i = tid; i < 128 * 8; i += 256) {
        int row = i >> 3, c4 = i & 7;
        CP_ASYNC16(vu + (uint32_t)(row * VSW + c4 * 4) * 4,
                   Vb + (size_t)row * (T_ / 2) + c4 * 4);
    }
    CP_COMMIT();

    // ldmatrix per-lane offsets
    const uint32_t qoff = (uint32_t)((wid * 16 + (lane & 15)) * QKW + (lane >> 4) * 4) * 4;
    const uint32_t koff = (uint32_t)(((lane & 7) + ((lane >> 4) << 3)) * QKW
                                     + ((lane >> 3) & 1) * 4) * 4;
    const uint32_t voff = (uint32_t)(((lane & 7) + ((lane >> 4) << 3)) * VSW
                                     + ((lane >> 3) & 1) * 4) * 4;

    uint32_t qf[8][4];
    float oa[16][4];
    #pragma unroll
    for (int db = 0; db < 16; db++)
        oa[db][0] = oa[db][1] = oa[db][2] = oa[db][3] = 0.f;
    float m0r = -1e30f, m1r = -1e30f, l0 = 0.f, l1 = 0.f;

    const int nT = 2 * (blockIdx.x + 1);

    for (int j = 0; j < nT; j++) {
        const int buf = j & 1;
        const int n0 = j * 64;
        CP_WAIT0();
        __syncthreads();

        if (j + 1 < nT) {
            const int nb2 = buf ^ 1;
            for (int i = tid; i < 64 * 16; i += 256) {
                int row = i >> 4, c4 = i & 15;
                CP_ASYNC16(ku + (uint32_t)(nb2 * 64 * QKW + row * QKW + c4 * 4) * 4,
                           Kb + (size_t)((j + 1) * 64 + row) * (HKV_ * D_) + c4 * 8);
            }
            for (int i = tid; i < 128 * 8; i += 256) {
                int row = i >> 3, c4 = i & 7;
                CP_ASYNC16(vu + (uint32_t)(nb2 * VBUF + row * VSW + c4 * 4) * 4,
                           Vb + (size_t)row * (T_ / 2) + (j + 1) * 32 + c4 * 4);
            }
            CP_COMMIT();
        }

        if (j == 0) {
            #pragma unroll
            for (int ks = 0; ks < 8; ks++)
                ldsm4(qf[ks][0], qf[ks][1], qf[ks][2], qf[ks][3],
                      qu + qoff + (uint32_t)(ks * 8) * 4);
        }

        if (n0 > wrow + 15) continue;   // fully masked warp tile

        // S = Q @ K^T
        const uint32_t kbase = ku + (uint32_t)(buf * 64 * QKW) * 4 + koff;
        float s[8][4];
        #pragma unroll
        for (int nb = 0; nb < 8; nb++)
            s[nb][0] = s[nb][1] = s[nb][2] = s[nb][3] = 0.f;
        #pragma unroll
        for (int ks = 0; ks < 8; ks++) {
            uint32_t kf[8][2];
            #pragma unroll
            for (int np = 0; np < 4; np++)
                ldsm4(kf[2*np][0], kf[2*np][1], kf[2*np+1][0], kf[2*np+1][1],
                      kbase + (uint32_t)(np * 16 * QKW + ks * 8) * 4);
            #pragma unroll
            for (int nb = 0; nb < 8; nb++)
                mma_f16(s[nb][0], s[nb][1], s[nb][2], s[nb][3],
                        qf[ks][0], qf[ks][1], qf[ks][2], qf[ks][3],
                        kf[nb][0], kf[nb][1]);
        }

        // causal mask near diagonal
        if (n0 + 63 > wrow) {
            #pragma unroll
            for (int nb = 0; nb < 8; nb++) {
                int col = n0 + nb * 8 + 2 * c;
                if (col     > wrow + r)     s[nb][0] = -1e30f;
                if (col + 1 > wrow + r)     s[nb][1] = -1e30f;
                if (col     > wrow + r + 8) s[nb][2] = -1e30f;
                if (col + 1 > wrow + r + 8) s[nb][3] = -1e30f;
            }
        }

        // online softmax (rows r and r+8)
        float mx0 = -1e30f, mx1 = -1e30f;
        #pragma unroll
        for (int nb = 0; nb < 8; nb++) {
            mx0 = fmaxf(mx0, fmaxf(s[nb][0], s[nb][1]));
            mx1 = fmaxf(mx1, fmaxf(s[nb][2], s[nb][3]));
        }
        mx0 = fmaxf(mx0, __shfl_xor_sync(0xffffffffu, mx0, 1));
        mx0 = fmaxf(mx0, __shfl_xor_sync(0xffffffffu, mx0, 2));
        mx1 = fmaxf(mx1, __shfl_xor_sync(0xffffffffu, mx1, 1));
        mx1 = fmaxf(mx1, __shfl_xor_sync(0xffffffffu, mx1, 2));
        float mn0 = fmaxf(m0r, mx0), mn1 = fmaxf(m1r, mx1);
        float a0 = __expf(m0r - mn0), a1 = __expf(m1r - mn1);
        float ls0 = 0.f, ls1 = 0.f;
        #pragma unroll
        for (int nb = 0; nb < 8; nb++) {
            s[nb][0] = __half2float(__float2half_rn(__expf(s[nb][0] - mn0)));
            s[nb][1] = __half2float(__float2half_rn(__expf(s[nb][1] - mn0)));
            s[nb][2] = __half2float(__float2half_rn(__expf(s[nb][2] - mn1)));
            s[nb][3] = __half2float(__float2half_rn(__expf(s[nb][3] - mn1)));
            ls0 += s[nb][0] + s[nb][1];
            ls1 += s[nb][2] + s[nb][3];
        }
        ls0 += __shfl_xor_sync(0xffffffffu, ls0, 1);
        ls0 += __shfl_xor_sync(0xffffffffu, ls0, 2);
        ls1 += __shfl_xor_sync(0xffffffffu, ls1, 1);
        ls1 += __shfl_xor_sync(0xffffffffu, ls1, 2);
        l0 = l0 * a0 + ls0; l1 = l1 * a1 + ls1;
        m0r = mn0; m1r = mn1;
        #pragma unroll
        for (int db = 0; db < 16; db++) {
            oa[db][0] *= a0; oa[db][1] *= a0;
            oa[db][2] *= a1; oa[db][3] *= a1;
        }

        // O += P @ V : P packed to fp16 A-frags in registers; V frags via ldmatrix
        const uint32_t vbase = vu + (uint32_t)(buf * VBUF) * 4 + voff;
        #pragma unroll
        for (int kb2 = 0; kb2 < 4; kb2++) {
            uint32_t pa0 = h2u(__floats2half2_rn(s[2*kb2][0],   s[2*kb2][1]));
            uint32_t pa1 = h2u(__floats2half2_rn(s[2*kb2][2],   s[2*kb2][3]));
            uint32_t pa2 = h2u(__floats2half2_rn(s[2*kb2+1][0], s[2*kb2+1][1]));
            uint32_t pa3 = h2u(__floats2half2_rn(s[2*kb2+1][2], s[2*kb2+1][3]));
            #pragma unroll
            for (int dp = 0; dp < 8; dp++) {
                uint32_t v0, v1, v2, v3;
                ldsm4(v0, v1, v2, v3,
                      vbase + (uint32_t)(dp * 16 * VSW + kb2 * 8) * 4);
                mma_f16(oa[2*dp][0], oa[2*dp][1], oa[2*dp][2], oa[2*dp][3],
                        pa0, pa1, pa2, pa3, v0, v1);
                mma_f16(oa[2*dp+1][0], oa[2*dp+1][1], oa[2*dp+1][2], oa[2*dp+1][3],
                        pa0, pa1, pa2, pa3, v2, v3);
            }
        }
    }

    // epilogue: normalize, store fp16 y
    const float i0 = 1.f / l0, i1 = 1.f / l1;
    const int row_g = m0 + wid * 16 + r;
    __half* Ob = Oh + ((size_t)(b * T_ + row_g) * H_ + h) * D_;
    #pragma unroll
    for (int db = 0; db < 16; db++) {
        *(uint32_t*)(Ob + db * 8 + 2 * c) =
            h2u(__floats2half2_rn(oa[db][0] * i0, oa[db][1] * i0));
        *(uint32_t*)(Ob + (size_t)8 * H_ * D_ + db * 8 + 2 * c) =
            h2u(__floats2half2_rn(oa[db][2] * i1, oa[db][3] * i1));
    }
}

// ============================================================================
// Launch
// ============================================================================
extern "C" void kernel_launch(void* const* d_in, const int* in_sizes, int n_in,
                              void* d_out, int out_size)
{
    (void)in_sizes; (void)n_in; (void)out_size;
    const float* x  = (const float*)d_in[0];
    const float* fc = (const float*)d_in[1];
    const float* Wq = (const float*)d_in[2];
    const float* Wk = (const float*)d_in[3];
    const float* Wv = (const float*)d_in[4];
    const float* Wc = (const float*)d_in[5];
    float* out = (float*)d_out;

    __half *xh, *qg, *kg, *vg, *qh, *kh, *yh;
    uint32_t *vh, *wqt, *wkt, *wvt, *wct;
    cudaGetSymbolAddress((void**)&xh,  g_xh);
    cudaGetSymbolAddress((void**)&qg,  g_qg);
    cudaGetSymbolAddress((void**)&kg,  g_kg);
    cudaGetSymbolAddress((void**)&vg,  g_vg);
    cudaGetSymbolAddress((void**)&qh,  g_qh);
    cudaGetSymbolAddress((void**)&kh,  g_kh);
    cudaGetSymbolAddress((void**)&vh,  g_vh);
    cudaGetSymbolAddress((void**)&yh,  g_yh);
    cudaGetSymbolAddress((void**)&wqt, g_wqt);
    cudaGetSymbolAddress((void**)&wkt, g_wkt);
    cudaGetSymbolAddress((void**)&wvt, g_wvt);
    cudaGetSymbolAddress((void**)&wct, g_wct);

    // Prep: x -> fp16; weights -> transposed [N][K/2] half2
    cvt_f2h_kernel<<<(M_ * C_ / 4 + 255) / 256, 256>>>(
        (const float4*)x, (uint2*)xh, M_ * C_ / 4);
    conv_wt_kernel<<<dim3((H_ * D_) / 32, K2C / 32), dim3(32, 8)>>>(Wq, wqt, C_, H_ * D_);
    conv_wt_kernel<<<dim3((HKV_ * D_) / 32, K2C / 32), dim3(32, 8)>>>(Wk, wkt, C_, HKV_ * D_);
    conv_wt_kernel<<<dim3((HKV_ * D_) / 32, K2C / 32), dim3(32, 8)>>>(Wv, wvt, C_, HKV_ * D_);
    conv_wt_kernel<<<dim3(C_ / 32, K2C / 32), dim3(32, 8)>>>(Wc, wct, C_, C_);

    cudaFuncSetAttribute(mma_gemm_kernel<__half>,
                         cudaFuncAttributeMaxDynamicSharedMemorySize, GEMM_SMEM);
    cudaFuncSetAttribute(mma_gemm_kernel<float>,
                         cudaFuncAttributeMaxDynamicSharedMemorySize, GEMM_SMEM);

    // QKV projections (fp16 out)
    mma_gemm_kernel<__half><<<dim3((H_ * D_) / BN, M_ / BM), 128, GEMM_SMEM>>>(xh, wqt, qg, H_ * D_, C_);
    mma_gemm_kernel<__half><<<dim3((HKV_ * D_) / BN, M_ / BM), 128, GEMM_SMEM>>>(xh, wkt, kg, HKV_ * D_, C_);
    mma_gemm_kernel<__half><<<dim3((HKV_ * D_) / BN, M_ / BM), 128, GEMM_SMEM>>>(xh, wvt, vg, HKV_ * D_, C_);

    // RMSNorm + RoPE (q pre-scaled by 1/sqrt(D)); V -> [d][t2] half2
    rmsnorm_rope_h_kernel<<<B_ * T_ * H_ / 8, 256>>>(qg, qh, fc, H_, 0.088388347648318447f);
    rmsnorm_rope_h_kernel<<<B_ * T_ * HKV_ / 8, 256>>>(kg, kh, fc, HKV_, 1.0f);
    conv_v_kernel<<<(B_ * HKV_ * D_ * (T_/2) + 255) / 256, 256>>>(vg, vh);

    // Flash attention
    cudaFuncSetAttribute(flash_mma_kernel, cudaFuncAttributeMaxDynamicSharedMemorySize, FLASH_SMEM);
    flash_mma_kernel<<<dim3(T_ / 128, B_ * H_), 256, FLASH_SMEM>>>(qh, kh, vh, yh);

    // Output projection (fp32 out)
    mma_gemm_kernel<float><<<dim3(C_ / BN, M_ / BM), 128, GEMM_SMEM>>>(yh, wct, out, C_, C_);
}

// round 8
// speedup vs baseline: 17.9948x; 1.0466x over previous
#include <cuda_runtime.h>
#include <cuda_fp16.h>
#include <cstdint>

// Problem constants
#define B_   4
#define T_   2048
#define C_   2048
#define H_   16
#define HKV_ 4
#define REP_ 4
#define D_   128
#define M_   (B_*T_)   // 8192 rows
#define K2C  (C_/2)    // 1024 half2 words along K

// Scratch (device globals — no allocation allowed)
__device__ __half   g_xh[(size_t)M_ * C_];                 // x as fp16
__device__ __half   g_vg[(size_t)M_ * HKV_ * D_];          // raw v (fp16)
__device__ __half   g_qh[(size_t)M_ * H_ * D_];            // normed+roped q
__device__ __half   g_kh[(size_t)M_ * HKV_ * D_];
__device__ uint32_t g_vh[(size_t)B_ * HKV_ * D_ * (T_/2)]; // V as [bk][d][t2] half2
__device__ __half   g_yh[(size_t)M_ * C_];                 // attention out
__device__ uint32_t g_wqt[(size_t)(H_ * D_) * K2C];        // W^T as [n][k2] half2
__device__ uint32_t g_wkt[(size_t)(HKV_ * D_) * K2C];
__device__ uint32_t g_wvt[(size_t)(HKV_ * D_) * K2C];
__device__ uint32_t g_wct[(size_t)C_ * K2C];

// ============================================================================
// Helpers
// ============================================================================
__device__ __forceinline__ uint32_t smem_u32(const void* p) {
    uint32_t a;
    asm("{ .reg .u64 t; cvta.to.shared.u64 t, %1; cvt.u32.u64 %0, t; }" : "=r"(a) : "l"(p));
    return a;
}
__device__ __forceinline__ uint32_t h2u(__half2 h) {
    return *reinterpret_cast<uint32_t*>(&h);
}
#define CP_ASYNC16(dst_u32, src_ptr) \
    asm volatile("cp.async.cg.shared.global [%0], [%1], 16;" \
                 :: "r"(dst_u32), "l"(src_ptr) : "memory")
#define CP_COMMIT() asm volatile("cp.async.commit_group;" ::: "memory")
#define CP_WAIT2()  asm volatile("cp.async.wait_group 2;" ::: "memory")
#define CP_WAIT0()  asm volatile("cp.async.wait_group 0;" ::: "memory")

__device__ __forceinline__ void mma_f16(
    float& c0, float& c1, float& c2, float& c3,
    uint32_t a0, uint32_t a1, uint32_t a2, uint32_t a3,
    uint32_t b0, uint32_t b1)
{
    asm volatile(
        "mma.sync.aligned.m16n8k16.row.col.f32.f16.f16.f32 "
        "{%0,%1,%2,%3}, {%4,%5,%6,%7}, {%8,%9}, {%0,%1,%2,%3};"
        : "+f"(c0), "+f"(c1), "+f"(c2), "+f"(c3)
        : "r"(a0), "r"(a1), "r"(a2), "r"(a3), "r"(b0), "r"(b1));
}
__device__ __forceinline__ void ldsm4(
    uint32_t& r0, uint32_t& r1, uint32_t& r2, uint32_t& r3, uint32_t a)
{
    asm volatile("ldmatrix.sync.aligned.m8n8.x4.shared.b16 {%0,%1,%2,%3}, [%4];"
                 : "=r"(r0), "=r"(r1), "=r"(r2), "=r"(r3) : "r"(a));
}
__device__ __forceinline__ void store2(float* p, float a, float b) {
    *(float2*)p = make_float2(a, b);
}
__device__ __forceinline__ void store2(__half* p, float a, float b) {
    *(uint32_t*)p = h2u(__floats2half2_rn(a, b));
}

// ============================================================================
// Prep kernels
// ============================================================================
__global__ __launch_bounds__(256) void cvt_f2h_kernel(
    const float4* __restrict__ in, uint2* __restrict__ out, int n4)
{
    int i = blockIdx.x * 256 + threadIdx.x;
    if (i < n4) {
        float4 v = in[i];
        uint2 u;
        u.x = h2u(__floats2half2_rn(v.x, v.y));
        u.y = h2u(__floats2half2_rn(v.z, v.w));
        out[i] = u;
    }
}

// W[K][N] fp32 -> Wt2[N][K/2] half2 (pairs along K), tiled transpose
__global__ __launch_bounds__(256) void conv_wt_kernel(
    const float* __restrict__ W, uint32_t* __restrict__ Wt2, int K, int N)
{
    __shared__ uint32_t ts[32][33];
    const int n0 = blockIdx.x * 32, k20 = blockIdx.y * 32;
    const int tx = threadIdx.x, ty = threadIdx.y;
    #pragma unroll
    for (int i = 0; i < 4; i++) {
        int k2 = k20 + ty + i * 8;
        float a = W[(size_t)(2 * k2) * N + n0 + tx];
        float b = W[(size_t)(2 * k2 + 1) * N + n0 + tx];
        ts[ty + i * 8][tx] = h2u(__floats2half2_rn(a, b));
    }
    __syncthreads();
    const int K2 = K / 2;
    #pragma unroll
    for (int i = 0; i < 4; i++)
        Wt2[(size_t)(n0 + ty + i * 8) * K2 + k20 + tx] = ts[tx][ty + i * 8];
}

// v (B,T,HKV,D) fp16 -> [bk][d][T/2] half2 (pairs along T)
__global__ __launch_bounds__(256) void conv_v_kernel(
    const __half* __restrict__ V, uint32_t* __restrict__ Vt2)
{
    int idx = blockIdx.x * 256 + threadIdx.x;
    const int total = B_ * HKV_ * D_ * (T_ / 2);
    if (idx < total) {
        int t2  = idx & (T_ / 2 - 1);
        int d   = (idx >> 10) & (D_ - 1);
        int kvh = (idx >> 17) & (HKV_ - 1);
        int b   = idx >> 19;
        size_t src = ((size_t)(b * T_ + 2 * t2) * HKV_ + kvh) * D_ + d;
        Vt2[idx] = h2u(__halves2half2(V[src], V[src + (size_t)HKV_ * D_]));
    }
}

// ============================================================================
// GEMM machinery: 128x128 CTA, BK=32 halves, 128 threads = 4 warps (2Mx2N),
// warp tile 64x64, m16n8k16 via ldmatrix, 4-stage cp.async.
// ============================================================================
#define BM 128
#define BN 128
#define GST 4
#define ASW 20
#define BS_OFF (BM * ASW)               // 2560 words
#define STAGE_WORDS (2 * BM * ASW)      // 5120 words
#define GEMM_SMEM (GST * STAGE_WORDS * 4)  // 81920 B

__device__ __forceinline__ void gemm_issue_stage(
    uint32_t stage_u, const __half* __restrict__ Ab,
    const uint32_t* __restrict__ Bb2, int K, int kt, int tid)
{
    const int K2 = K / 2;
    const int rr = tid >> 2;
    const int c4 = tid & 3;
    const __half* ga = Ab + (size_t)rr * K + kt * 32 + c4 * 8;
    uint32_t sa = stage_u + (uint32_t)(rr * ASW + c4 * 4) * 4;
    #pragma unroll
    for (int p = 0; p < 4; p++)
        CP_ASYNC16(sa + (uint32_t)(p * 32 * ASW) * 4u, ga + (size_t)(p * 32) * K);
    const uint32_t* gb = Bb2 + (size_t)rr * K2 + kt * 16 + c4 * 4;
    uint32_t sb = stage_u + (uint32_t)(BS_OFF + rr * ASW + c4 * 4) * 4;
    #pragma unroll
    for (int p = 0; p < 4; p++)
        CP_ASYNC16(sb + (uint32_t)(p * 32 * ASW) * 4u, gb + (size_t)(p * 32) * K2);
}

// Shared mainloop: accumulates the 128x128 tile into acc.
__device__ __forceinline__ void gemm_mainloop(
    uint32_t* sw, const __half* Ab, const uint32_t* Bb2, int K,
    float acc[4][8][4], int tid)
{
    const int lane  = tid & 31;
    const int wid   = tid >> 5;
    const int warpM = wid & 1;
    const int warpN = wid >> 1;
    const int KT = K / 32;
    const uint32_t smem_base = smem_u32(sw);

    #pragma unroll
    for (int s = 0; s < GST - 1; s++) {
        gemm_issue_stage(smem_base + s * STAGE_WORDS * 4, Ab, Bb2, K, s, tid);
        CP_COMMIT();
    }

    const uint32_t aoff = (uint32_t)((warpM * 64 + (lane & 15)) * ASW + (lane >> 4) * 4) * 4;
    const uint32_t boff = (uint32_t)((BS_OFF + (warpN * 64 + (lane & 7) + ((lane >> 4) << 3)) * ASW)
                                     + ((lane >> 3) & 1) * 4) * 4;

    for (int kt = 0; kt < KT; kt++) {
        const int buf = kt & (GST - 1);
        CP_WAIT2();
        __syncthreads();

        const int nxt = kt + GST - 1;
        if (nxt < KT)
            gemm_issue_stage(smem_base + (nxt & (GST - 1)) * STAGE_WORDS * 4,
                             Ab, Bb2, K, nxt, tid);
        CP_COMMIT();

        const uint32_t stage_u = smem_base + buf * STAGE_WORDS * 4;
        #pragma unroll
        for (int ks = 0; ks < 2; ks++) {
            uint32_t af[4][4], bf[8][2];
            #pragma unroll
            for (int mt = 0; mt < 4; mt++)
                ldsm4(af[mt][0], af[mt][1], af[mt][2], af[mt][3],
                      stage_u + aoff + (uint32_t)(mt * 16 * ASW + ks * 8) * 4);
            #pragma unroll
            for (int np = 0; np < 4; np++)
                ldsm4(bf[2*np][0], bf[2*np][1], bf[2*np+1][0], bf[2*np+1][1],
                      stage_u + boff + (uint32_t)(np * 16 * ASW + ks * 8) * 4);
            #pragma unroll
            for (int mt = 0; mt < 4; mt++)
                #pragma unroll
                for (int nt = 0; nt < 8; nt++)
                    mma_f16(acc[mt][nt][0], acc[mt][nt][1], acc[mt][nt][2], acc[mt][nt][3],
                            af[mt][0], af[mt][1], af[mt][2], af[mt][3],
                            bf[nt][0], bf[nt][1]);
        }
        __syncthreads();
    }
}

// ============================================================================
// Fused QKV GEMM: grid (24, 64). x-blocks 0..15 -> q (norm+rope, scaled),
// 16..19 -> k (norm+rope), 20..23 -> v (plain fp16).
// ============================================================================
__global__ __launch_bounds__(128, 2) void qkv_gemm_kernel(
    const __half* __restrict__ A,
    const uint32_t* __restrict__ Wq2, const uint32_t* __restrict__ Wk2,
    const uint32_t* __restrict__ Wv2,
    __half* __restrict__ Qh, __half* __restrict__ Kh, __half* __restrict__ Vg,
    const float* __restrict__ fc)
{
    extern __shared__ uint32_t sw[];
    const int bx  = blockIdx.x;
    const int tid = threadIdx.x;
    const int lane = tid & 31, wid = tid >> 5;
    const int warpM = wid & 1, warpN = wid >> 1;

    const uint32_t* B2;
    __half* Cm;
    int ncol, N;
    bool norm;
    float scale;
    if (bx < 16)      { B2 = Wq2; Cm = Qh; ncol = bx;      N = H_ * D_;   norm = true;  scale = 0.088388347648318447f; }
    else if (bx < 20) { B2 = Wk2; Cm = Kh; ncol = bx - 16; N = HKV_ * D_; norm = true;  scale = 1.0f; }
    else              { B2 = Wv2; Cm = Vg; ncol = bx - 20; N = HKV_ * D_; norm = false; scale = 1.0f; }

    const __half*   Ab  = A  + (size_t)blockIdx.y * BM * C_;
    const uint32_t* Bb2 = B2 + (size_t)ncol * BN * K2C;

    float acc[4][8][4];
    #pragma unroll
    for (int i = 0; i < 4; i++)
        #pragma unroll
        for (int j = 0; j < 8; j++)
            #pragma unroll
            for (int c = 0; c < 4; c++) acc[i][j][c] = 0.f;

    gemm_mainloop(sw, Ab, Bb2, C_, acc, tid);

    const int r = lane >> 2, c = lane & 3;
    const int ccol0 = warpN * 64 + c * 2;
    __half* Cb = Cm + (size_t)blockIdx.y * BM * N + (size_t)ncol * BN;

    if (!norm) {
        #pragma unroll
        for (int mt = 0; mt < 4; mt++) {
            const int rr = warpM * 64 + mt * 16 + r;
            #pragma unroll
            for (int nt = 0; nt < 8; nt++) {
                const int cc = ccol0 + nt * 8;
                store2(Cb + (size_t)rr * N + cc,       acc[mt][nt][0], acc[mt][nt][1]);
                store2(Cb + (size_t)(rr + 8) * N + cc, acc[mt][nt][2], acc[mt][nt][3]);
            }
        }
        return;
    }

    // --- fused RMSNorm + RoPE epilogue (BN == D == 128: one head per tile) ---
    float* red = (float*)sw;   // [2][128] partial row sums (warpN halves)
    #pragma unroll
    for (int mt = 0; mt < 4; mt++) {
        float p0 = 0.f, p1 = 0.f;
        #pragma unroll
        for (int nt = 0; nt < 8; nt++) {
            p0 += acc[mt][nt][0] * acc[mt][nt][0] + acc[mt][nt][1] * acc[mt][nt][1];
            p1 += acc[mt][nt][2] * acc[mt][nt][2] + acc[mt][nt][3] * acc[mt][nt][3];
        }
        p0 += __shfl_xor_sync(0xffffffffu, p0, 1);
        p0 += __shfl_xor_sync(0xffffffffu, p0, 2);
        p1 += __shfl_xor_sync(0xffffffffu, p1, 1);
        p1 += __shfl_xor_sync(0xffffffffu, p1, 2);
        if (c == 0) {
            const int row = warpM * 64 + mt * 16 + r;
            red[warpN * 128 + row]     = p0;
            red[warpN * 128 + row + 8] = p1;
        }
    }
    __syncthreads();

    #pragma unroll
    for (int mt = 0; mt < 4; mt++) {
        const int row0 = warpM * 64 + mt * 16 + r;
        const int row1 = row0 + 8;
        const float ms0 = (red[row0] + red[128 + row0]) * (1.f / (float)D_);
        const float ms1 = (red[row1] + red[128 + row1]) * (1.f / (float)D_);
        const float ri0 = rsqrtf(ms0 + 1e-6f) * scale;
        const float ri1 = rsqrtf(ms1 + 1e-6f) * scale;
        const int t0 = (blockIdx.y * BM + row0) & (T_ - 1);
        const int t1 = (blockIdx.y * BM + row1) & (T_ - 1);
        #pragma unroll
        for (int nt = 0; nt < 8; nt++) {
            const int cc = ccol0 + nt * 8;   // even: rope pair (cc, cc+1)
            float2 cs0 = *(const float2*)(fc + (size_t)t0 * D_ + cc);
            float2 cs1 = *(const float2*)(fc + (size_t)t1 * D_ + cc);
            float a0 = acc[mt][nt][0], a1 = acc[mt][nt][1];
            float b0 = acc[mt][nt][2], b1 = acc[mt][nt][3];
            store2(Cb + (size_t)row0 * N + cc,
                   (a0 * cs0.x - a1 * cs0.y) * ri0, (a0 * cs0.y + a1 * cs0.x) * ri0);
            store2(Cb + (size_t)row1 * N + cc,
                   (b0 * cs1.x - b1 * cs1.y) * ri1, (b0 * cs1.y + b1 * cs1.x) * ri1);
        }
    }
}

// ============================================================================
// Plain GEMM (for the output projection, fp32 out)
// ============================================================================
__global__ __launch_bounds__(128, 2) void wc_gemm_kernel(
    const __half* __restrict__ A, const uint32_t* __restrict__ B2,
    float* __restrict__ Cm)
{
    extern __shared__ uint32_t sw[];
    const int tid = threadIdx.x;
    const int lane = tid & 31, wid = tid >> 5;
    const int warpM = wid & 1, warpN = wid >> 1;

    const __half*   Ab  = A  + (size_t)blockIdx.y * BM * C_;
    const uint32_t* Bb2 = B2 + (size_t)blockIdx.x * BN * K2C;

    float acc[4][8][4];
    #pragma unroll
    for (int i = 0; i < 4; i++)
        #pragma unroll
        for (int j = 0; j < 8; j++)
            #pragma unroll
            for (int c = 0; c < 4; c++) acc[i][j][c] = 0.f;

    gemm_mainloop(sw, Ab, Bb2, C_, acc, tid);

    float* Cb = Cm + (size_t)blockIdx.y * BM * C_ + (size_t)blockIdx.x * BN;
    const int r = lane >> 2, c = lane & 3;
    const int ccol0 = warpN * 64 + c * 2;
    #pragma unroll
    for (int mt = 0; mt < 4; mt++) {
        const int rr = warpM * 64 + mt * 16 + r;
        #pragma unroll
        for (int nt = 0; nt < 8; nt++) {
            const int cc = ccol0 + nt * 8;
            store2(Cb + (size_t)rr * C_ + cc,       acc[mt][nt][0], acc[mt][nt][1]);
            store2(Cb + (size_t)(rr + 8) * C_ + cc, acc[mt][nt][2], acc[mt][nt][3]);
        }
    }
}

// ============================================================================
// Causal GQA flash attention, fp16 mma.sync + ldmatrix (unchanged from R7).
// ============================================================================
#define QKW 68
#define VSW 36
#define VBUF (128 * VSW)
#define FLASH_WORDS (128 * QKW + 2 * 64 * QKW + 2 * VBUF)
#define FLASH_SMEM  (FLASH_WORDS * 4)

__global__ __launch_bounds__(256, 1) void flash_mma_kernel(
    const __half* __restrict__ Qh, const __half* __restrict__ Kh,
    const uint32_t* __restrict__ Vt2, __half* __restrict__ Oh)
{
    extern __shared__ uint32_t sw[];
    uint32_t* Qs = sw;
    uint32_t* Ks = sw + 128 * QKW;
    uint32_t* Vs = Ks + 2 * 64 * QKW;

    const int tid  = threadIdx.x;
    const int lane = tid & 31, wid = tid >> 5;
    const int r = lane >> 2, c = lane & 3;
    const int b = blockIdx.y / H_, h = blockIdx.y % H_;
    const int kvh = h / REP_;
    const int m0 = blockIdx.x * 128;
    const int wrow = m0 + wid * 16;
    const uint32_t qu = smem_u32(Qs);
    const uint32_t ku = smem_u32(Ks);
    const uint32_t vu = smem_u32(Vs);

    const __half* Qb = Qh + ((size_t)(b * T_ + m0) * H_ + h) * D_;
    const __half* Kb = Kh + ((size_t)b * T_ * HKV_ + kvh) * D_;
    const uint32_t* Vb = Vt2 + (size_t)(b * HKV_ + kvh) * D_ * (T_ / 2);

    for (int i = tid; i < 128 * 16; i += 256) {
        int row = i >> 4, c4 = i & 15;
        CP_ASYNC16(qu + (uint32_t)(row * QKW + c4 * 4) * 4,
                   Qb + (size_t)row * (H_ * D_) + c4 * 8);
    }
    for (int i = tid; i < 64 * 16; i += 256) {
        int row = i >> 4, c4 = i & 15;
        CP_ASYNC16(ku + (uint32_t)(row * QKW + c4 * 4) * 4,
                   Kb + (size_t)row * (HKV_ * D_) + c4 * 8);
    }
    for (int i = tid; i < 128 * 8; i += 256) {
        int row = i >> 3, c4 = i & 7;
        CP_ASYNC16(vu + (uint32_t)(row * VSW + c4 * 4) * 4,
                   Vb + (size_t)row * (T_ / 2) + c4 * 4);
    }
    CP_COMMIT();

    const uint32_t qoff = (uint32_t)((wid * 16 + (lane & 15)) * QKW + (lane >> 4) * 4) * 4;
    const uint32_t koff = (uint32_t)(((lane & 7) + ((lane >> 4) << 3)) * QKW
                                     + ((lane >> 3) & 1) * 4) * 4;
    const uint32_t voff = (uint32_t)(((lane & 7) + ((lane >> 4) << 3)) * VSW
                                     + ((lane >> 3) & 1) * 4) * 4;

    uint32_t qf[8][4];
    float oa[16][4];
    #pragma unroll
    for (int db = 0; db < 16; db++)
        oa[db][0] = oa[db][1] = oa[db][2] = oa[db][3] = 0.f;
    float m0r = -1e30f, m1r = -1e30f, l0 = 0.f, l1 = 0.f;

    const int nT = 2 * (blockIdx.x + 1);

    for (int j = 0; j < nT; j++) {
        const int buf = j & 1;
        const int n0 = j * 64;
        CP_WAIT0();
        __syncthreads();

        if (j + 1 < nT) {
            const int nb2 = buf ^ 1;
            for (int i = tid; i < 64 * 16; i += 256) {
                int row = i >> 4, c4 = i & 15;
                CP_ASYNC16(ku + (uint32_t)(nb2 * 64 * QKW + row * QKW + c4 * 4) * 4,
                           Kb + (size_t)((j + 1) * 64 + row) * (HKV_ * D_) + c4 * 8);
            }
            for (int i = tid; i < 128 * 8; i += 256) {
                int row = i >> 3, c4 = i & 7;
                CP_ASYNC16(vu + (uint32_t)(nb2 * VBUF + row * VSW + c4 * 4) * 4,
                           Vb + (size_t)row * (T_ / 2) + (j + 1) * 32 + c4 * 4);
            }
            CP_COMMIT();
        }

        if (j == 0) {
            #pragma unroll
            for (int ks = 0; ks < 8; ks++)
                ldsm4(qf[ks][0], qf[ks][1], qf[ks][2], qf[ks][3],
                      qu + qoff + (uint32_t)(ks * 8) * 4);
        }

        if (n0 > wrow + 15) continue;

        const uint32_t kbase = ku + (uint32_t)(buf * 64 * QKW) * 4 + koff;
        float s[8][4];
        #pragma unroll
        for (int nb = 0; nb < 8; nb++)
            s[nb][0] = s[nb][1] = s[nb][2] = s[nb][3] = 0.f;
        #pragma unroll
        for (int ks = 0; ks < 8; ks++) {
            uint32_t kf[8][2];
            #pragma unroll
            for (int np = 0; np < 4; np++)
                ldsm4(kf[2*np][0], kf[2*np][1], kf[2*np+1][0], kf[2*np+1][1],
                      kbase + (uint32_t)(np * 16 * QKW + ks * 8) * 4);
            #pragma unroll
            for (int nb = 0; nb < 8; nb++)
                mma_f16(s[nb][0], s[nb][1], s[nb][2], s[nb][3],
                        qf[ks][0], qf[ks][1], qf[ks][2], qf[ks][3],
                        kf[nb][0], kf[nb][1]);
        }

        if (n0 + 63 > wrow) {
            #pragma unroll
            for (int nb = 0; nb < 8; nb++) {
                int col = n0 + nb * 8 + 2 * c;
                if (col     > wrow + r)     s[nb][0] = -1e30f;
                if (col + 1 > wrow + r)     s[nb][1] = -1e30f;
                if (col     > wrow + r + 8) s[nb][2] = -1e30f;
                if (col + 1 > wrow + r + 8) s[nb][3] = -1e30f;
            }
        }

        float mx0 = -1e30f, mx1 = -1e30f;
        #pragma unroll
        for (int nb = 0; nb < 8; nb++) {
            mx0 = fmaxf(mx0, fmaxf(s[nb][0], s[nb][1]));
            mx1 = fmaxf(mx1, fmaxf(s[nb][2], s[nb][3]));
        }
        mx0 = fmaxf(mx0, __shfl_xor_sync(0xffffffffu, mx0, 1));
        mx0 = fmaxf(mx0, __shfl_xor_sync(0xffffffffu, mx0, 2));
        mx1 = fmaxf(mx1, __shfl_xor_sync(0xffffffffu, mx1, 1));
        mx1 = fmaxf(mx1, __shfl_xor_sync(0xffffffffu, mx1, 2));
        float mn0 = fmaxf(m0r, mx0), mn1 = fmaxf(m1r, mx1);
        float a0 = __expf(m0r - mn0), a1 = __expf(m1r - mn1);
        float ls0 = 0.f, ls1 = 0.f;
        #pragma unroll
        for (int nb = 0; nb < 8; nb++) {
            s[nb][0] = __half2float(__float2half_rn(__expf(s[nb][0] - mn0)));
            s[nb][1] = __half2float(__float2half_rn(__expf(s[nb][1] - mn0)));
            s[nb][2] = __half2float(__float2half_rn(__expf(s[nb][2] - mn1)));
            s[nb][3] = __half2float(__float2half_rn(__expf(s[nb][3] - mn1)));
            ls0 += s[nb][0] + s[nb][1];
            ls1 += s[nb][2] + s[nb][3];
        }
        ls0 += __shfl_xor_sync(0xffffffffu, ls0, 1);
        ls0 += __shfl_xor_sync(0xffffffffu, ls0, 2);
        ls1 += __shfl_xor_sync(0xffffffffu, ls1, 1);
        ls1 += __shfl_xor_sync(0xffffffffu, ls1, 2);
        l0 = l0 * a0 + ls0; l1 = l1 * a1 + ls1;
        m0r = mn0; m1r = mn1;
        #pragma unroll
        for (int db = 0; db < 16; db++) {
            oa[db][0] *= a0; oa[db][1] *= a0;
            oa[db][2] *= a1; oa[db][3] *= a1;
        }

        const uint32_t vbase = vu + (uint32_t)(buf * VBUF) * 4 + voff;
        #pragma unroll
        for (int kb2 = 0; kb2 < 4; kb2++) {
            uint32_t pa0 = h2u(__floats2half2_rn(s[2*kb2][0],   s[2*kb2][1]));
            uint32_t pa1 = h2u(__floats2half2_rn(s[2*kb2][2],   s[2*kb2][3]));
            uint32_t pa2 = h2u(__floats2half2_rn(s[2*kb2+1][0], s[2*kb2+1][1]));
            uint32_t pa3 = h2u(__floats2half2_rn(s[2*kb2+1][2], s[2*kb2+1][3]));
            #pragma unroll
            for (int dp = 0; dp < 8; dp++) {
                uint32_t v0, v1, v2, v3;
                ldsm4(v0, v1, v2, v3,
                      vbase + (uint32_t)(dp * 16 * VSW + kb2 * 8) * 4);
                mma_f16(oa[2*dp][0], oa[2*dp][1], oa[2*dp][2], oa[2*dp][3],
                        pa0, pa1, pa2, pa3, v0, v1);
                mma_f16(oa[2*dp+1][0], oa[2*dp+1][1], oa[2*dp+1][2], oa[2*dp+1][3],
                        pa0, pa1, pa2, pa3, v2, v3);
            }
        }
    }

    const float i0 = 1.f / l0, i1 = 1.f / l1;
    const int row_g = m0 + wid * 16 + r;
    __half* Ob = Oh + ((size_t)(b * T_ + row_g) * H_ + h) * D_;
    #pragma unroll
    for (int db = 0; db < 16; db++) {
        *(uint32_t*)(Ob + db * 8 + 2 * c) =
            h2u(__floats2half2_rn(oa[db][0] * i0, oa[db][1] * i0));
        *(uint32_t*)(Ob + (size_t)8 * H_ * D_ + db * 8 + 2 * c) =
            h2u(__floats2half2_rn(oa[db][2] * i1, oa[db][3] * i1));
    }
}

// ============================================================================
// Launch
// ============================================================================
extern "C" void kernel_launch(void* const* d_in, const int* in_sizes, int n_in,
                              void* d_out, int out_size)
{
    (void)in_sizes; (void)n_in; (void)out_size;
    const float* x  = (const float*)d_in[0];
    const float* fc = (const float*)d_in[1];
    const float* Wq = (const float*)d_in[2];
    const float* Wk = (const float*)d_in[3];
    const float* Wv = (const float*)d_in[4];
    const float* Wc = (const float*)d_in[5];
    float* out = (float*)d_out;

    __half *xh, *vg, *qh, *kh, *yh;
    uint32_t *vh, *wqt, *wkt, *wvt, *wct;
    cudaGetSymbolAddress((void**)&xh,  g_xh);
    cudaGetSymbolAddress((void**)&vg,  g_vg);
    cudaGetSymbolAddress((void**)&qh,  g_qh);
    cudaGetSymbolAddress((void**)&kh,  g_kh);
    cudaGetSymbolAddress((void**)&vh,  g_vh);
    cudaGetSymbolAddress((void**)&yh,  g_yh);
    cudaGetSymbolAddress((void**)&wqt, g_wqt);
    cudaGetSymbolAddress((void**)&wkt, g_wkt);
    cudaGetSymbolAddress((void**)&wvt, g_wvt);
    cudaGetSymbolAddress((void**)&wct, g_wct);

    // Prep
    cvt_f2h_kernel<<<(M_ * C_ / 4 + 255) / 256, 256>>>(
        (const float4*)x, (uint2*)xh, M_ * C_ / 4);
    conv_wt_kernel<<<dim3((H_ * D_) / 32, K2C / 32), dim3(32, 8)>>>(Wq, wqt, C_, H_ * D_);
    conv_wt_kernel<<<dim3((HKV_ * D_) / 32, K2C / 32), dim3(32, 8)>>>(Wk, wkt, C_, HKV_ * D_);
    conv_wt_kernel<<<dim3((HKV_ * D_) / 32, K2C / 32), dim3(32, 8)>>>(Wv, wvt, C_, HKV_ * D_);
    conv_wt_kernel<<<dim3(C_ / 32, K2C / 32), dim3(32, 8)>>>(Wc, wct, C_, C_);

    cudaFuncSetAttribute(qkv_gemm_kernel, cudaFuncAttributeMaxDynamicSharedMemorySize, GEMM_SMEM);
    cudaFuncSetAttribute(wc_gemm_kernel, cudaFuncAttributeMaxDynamicSharedMemorySize, GEMM_SMEM);

    // Fused QKV projection + RMSNorm + RoPE epilogue
    qkv_gemm_kernel<<<dim3(24, M_ / BM), 128, GEMM_SMEM>>>(
        xh, wqt, wkt, wvt, qh, kh, vg, fc);

    // V -> [bk][d][t2] half2
    conv_v_kernel<<<(B_ * HKV_ * D_ * (T_/2) + 255) / 256, 256>>>(vg, vh);

    // Flash attention
    cudaFuncSetAttribute(flash_mma_kernel, cudaFuncAttributeMaxDynamicSharedMemorySize, FLASH_SMEM);
    flash_mma_kernel<<<dim3(T_ / 128, B_ * H_), 256, FLASH_SMEM>>>(qh, kh, vh, yh);

    // Output projection (fp32 out)
    wc_gemm_kernel<<<dim3(C_ / BN, M_ / BM), 128, GEMM_SMEM>>>(yh, wct, out);
}

// round 9
// speedup vs baseline: 18.3110x; 1.0176x over previous
#include <cuda_runtime.h>
#include <cuda_fp16.h>
#include <cstdint>

// Problem constants
#define B_   4
#define T_   2048
#define C_   2048
#define H_   16
#define HKV_ 4
#define REP_ 4
#define D_   128
#define M_   (B_*T_)   // 8192 rows
#define K2C  (C_/2)    // 1024 half2 words along K

// q scale: 1/sqrt(D) * log2(e)  (softmax done in exp2 domain)
#define QSCALE (0.088388347648318447f * 1.4426950408889634f)

// Scratch (device globals — no allocation allowed)
__device__ __half   g_xh[(size_t)M_ * C_];                 // x as fp16
__device__ __half   g_vg[(size_t)M_ * HKV_ * D_];          // raw v (fp16)
__device__ __half   g_qh[(size_t)M_ * H_ * D_];            // normed+roped q
__device__ __half   g_kh[(size_t)M_ * HKV_ * D_];
__device__ uint32_t g_vh[(size_t)B_ * HKV_ * D_ * (T_/2)]; // V as [bk][d][t2] half2
__device__ __half   g_yh[(size_t)M_ * C_];                 // attention out
__device__ uint32_t g_wqt[(size_t)(H_ * D_) * K2C];        // W^T as [n][k2] half2
__device__ uint32_t g_wkt[(size_t)(HKV_ * D_) * K2C];
__device__ uint32_t g_wvt[(size_t)(HKV_ * D_) * K2C];
__device__ uint32_t g_wct[(size_t)C_ * K2C];
__device__ int      g_cnt[64];                             // per (b, q-tile) flash completion

// ============================================================================
// Helpers
// ============================================================================
__device__ __forceinline__ uint32_t smem_u32(const void* p) {
    uint32_t a;
    asm("{ .reg .u64 t; cvta.to.shared.u64 t, %1; cvt.u32.u64 %0, t; }" : "=r"(a) : "l"(p));
    return a;
}
__device__ __forceinline__ uint32_t h2u(__half2 h) {
    return *reinterpret_cast<uint32_t*>(&h);
}
#define CP_ASYNC16(dst_u32, src_ptr) \
    asm volatile("cp.async.cg.shared.global [%0], [%1], 16;" \
                 :: "r"(dst_u32), "l"(src_ptr) : "memory")
#define CP_COMMIT() asm volatile("cp.async.commit_group;" ::: "memory")
#define CP_WAIT2()  asm volatile("cp.async.wait_group 2;" ::: "memory")
#define CP_WAIT0()  asm volatile("cp.async.wait_group 0;" ::: "memory")

__device__ __forceinline__ void mma_f16(
    float& c0, float& c1, float& c2, float& c3,
    uint32_t a0, uint32_t a1, uint32_t a2, uint32_t a3,
    uint32_t b0, uint32_t b1)
{
    asm volatile(
        "mma.sync.aligned.m16n8k16.row.col.f32.f16.f16.f32 "
        "{%0,%1,%2,%3}, {%4,%5,%6,%7}, {%8,%9}, {%0,%1,%2,%3};"
        : "+f"(c0), "+f"(c1), "+f"(c2), "+f"(c3)
        : "r"(a0), "r"(a1), "r"(a2), "r"(a3), "r"(b0), "r"(b1));
}
__device__ __forceinline__ void ldsm4(
    uint32_t& r0, uint32_t& r1, uint32_t& r2, uint32_t& r3, uint32_t a)
{
    asm volatile("ldmatrix.sync.aligned.m8n8.x4.shared.b16 {%0,%1,%2,%3}, [%4];"
                 : "=r"(r0), "=r"(r1), "=r"(r2), "=r"(r3) : "r"(a));
}
__device__ __forceinline__ void store2(float* p, float a, float b) {
    *(float2*)p = make_float2(a, b);
}
__device__ __forceinline__ void store2(__half* p, float a, float b) {
    *(uint32_t*)p = h2u(__floats2half2_rn(a, b));
}

// ============================================================================
// Prep kernels
// ============================================================================
__global__ __launch_bounds__(256) void cvt_f2h_kernel(
    const float4* __restrict__ in, uint2* __restrict__ out, int n4)
{
    int i = blockIdx.x * 256 + threadIdx.x;
    if (i < n4) {
        float4 v = in[i];
        uint2 u;
        u.x = h2u(__floats2half2_rn(v.x, v.y));
        u.y = h2u(__floats2half2_rn(v.z, v.w));
        out[i] = u;
    }
}

__global__ __launch_bounds__(256) void conv_wt_kernel(
    const float* __restrict__ W, uint32_t* __restrict__ Wt2, int K, int N)
{
    __shared__ uint32_t ts[32][33];
    const int n0 = blockIdx.x * 32, k20 = blockIdx.y * 32;
    const int tx = threadIdx.x, ty = threadIdx.y;
    #pragma unroll
    for (int i = 0; i < 4; i++) {
        int k2 = k20 + ty + i * 8;
        float a = W[(size_t)(2 * k2) * N + n0 + tx];
        float b = W[(size_t)(2 * k2 + 1) * N + n0 + tx];
        ts[ty + i * 8][tx] = h2u(__floats2half2_rn(a, b));
    }
    __syncthreads();
    const int K2 = K / 2;
    #pragma unroll
    for (int i = 0; i < 4; i++)
        Wt2[(size_t)(n0 + ty + i * 8) * K2 + k20 + tx] = ts[tx][ty + i * 8];
}

__global__ __launch_bounds__(256) void conv_v_kernel(
    const __half* __restrict__ V, uint32_t* __restrict__ Vt2)
{
    int idx = blockIdx.x * 256 + threadIdx.x;
    const int total = B_ * HKV_ * D_ * (T_ / 2);
    if (idx < total) {
        int t2  = idx & (T_ / 2 - 1);
        int d   = (idx >> 10) & (D_ - 1);
        int kvh = (idx >> 17) & (HKV_ - 1);
        int b   = idx >> 19;
        size_t src = ((size_t)(b * T_ + 2 * t2) * HKV_ + kvh) * D_ + d;
        Vt2[idx] = h2u(__halves2half2(V[src], V[src + (size_t)HKV_ * D_]));
    }
}

__global__ void zero_cnt_kernel() {
    if (threadIdx.x < 64) g_cnt[threadIdx.x] = 0;
}

// ============================================================================
// GEMM machinery (128-thread variant for QKV): 128x128 CTA, BK=32 halves,
// 4 warps (2Mx2N), warp tile 64x64, m16n8k16 via ldmatrix, 4-stage cp.async.
// ============================================================================
#define BM 128
#define BN 128
#define GST 4
#define ASW 20
#define BS_OFF (BM * ASW)               // 2560 words
#define STAGE_WORDS (2 * BM * ASW)      // 5120 words
#define GEMM_SMEM (GST * STAGE_WORDS * 4)  // 81920 B

__device__ __forceinline__ void gemm_issue_stage(
    uint32_t stage_u, const __half* __restrict__ Ab,
    const uint32_t* __restrict__ Bb2, int K, int kt, int tid)
{
    const int K2 = K / 2;
    const int rr = tid >> 2;
    const int c4 = tid & 3;
    const __half* ga = Ab + (size_t)rr * K + kt * 32 + c4 * 8;
    uint32_t sa = stage_u + (uint32_t)(rr * ASW + c4 * 4) * 4;
    #pragma unroll
    for (int p = 0; p < 4; p++)
        CP_ASYNC16(sa + (uint32_t)(p * 32 * ASW) * 4u, ga + (size_t)(p * 32) * K);
    const uint32_t* gb = Bb2 + (size_t)rr * K2 + kt * 16 + c4 * 4;
    uint32_t sb = stage_u + (uint32_t)(BS_OFF + rr * ASW + c4 * 4) * 4;
    #pragma unroll
    for (int p = 0; p < 4; p++)
        CP_ASYNC16(sb + (uint32_t)(p * 32 * ASW) * 4u, gb + (size_t)(p * 32) * K2);
}

__device__ __forceinline__ void gemm_mainloop(
    uint32_t* sw, const __half* Ab, const uint32_t* Bb2, int K,
    float acc[4][8][4], int tid)
{
    const int lane  = tid & 31;
    const int wid   = tid >> 5;
    const int warpM = wid & 1;
    const int warpN = wid >> 1;
    const int KT = K / 32;
    const uint32_t smem_base = smem_u32(sw);

    #pragma unroll
    for (int s = 0; s < GST - 1; s++) {
        gemm_issue_stage(smem_base + s * STAGE_WORDS * 4, Ab, Bb2, K, s, tid);
        CP_COMMIT();
    }

    const uint32_t aoff = (uint32_t)((warpM * 64 + (lane & 15)) * ASW + (lane >> 4) * 4) * 4;
    const uint32_t boff = (uint32_t)((BS_OFF + (warpN * 64 + (lane & 7) + ((lane >> 4) << 3)) * ASW)
                                     + ((lane >> 3) & 1) * 4) * 4;

    for (int kt = 0; kt < KT; kt++) {
        const int buf = kt & (GST - 1);
        CP_WAIT2();
        __syncthreads();

        const int nxt = kt + GST - 1;
        if (nxt < KT)
            gemm_issue_stage(smem_base + (nxt & (GST - 1)) * STAGE_WORDS * 4,
                             Ab, Bb2, K, nxt, tid);
        CP_COMMIT();

        const uint32_t stage_u = smem_base + buf * STAGE_WORDS * 4;
        #pragma unroll
        for (int ks = 0; ks < 2; ks++) {
            uint32_t af[4][4], bf[8][2];
            #pragma unroll
            for (int mt = 0; mt < 4; mt++)
                ldsm4(af[mt][0], af[mt][1], af[mt][2], af[mt][3],
                      stage_u + aoff + (uint32_t)(mt * 16 * ASW + ks * 8) * 4);
            #pragma unroll
            for (int np = 0; np < 4; np++)
                ldsm4(bf[2*np][0], bf[2*np][1], bf[2*np+1][0], bf[2*np+1][1],
                      stage_u + boff + (uint32_t)(np * 16 * ASW + ks * 8) * 4);
            #pragma unroll
            for (int mt = 0; mt < 4; mt++)
                #pragma unroll
                for (int nt = 0; nt < 8; nt++)
                    mma_f16(acc[mt][nt][0], acc[mt][nt][1], acc[mt][nt][2], acc[mt][nt][3],
                            af[mt][0], af[mt][1], af[mt][2], af[mt][3],
                            bf[nt][0], bf[nt][1]);
        }
        __syncthreads();
    }
}

// ============================================================================
// Fused QKV GEMM: grid (24, 64). x-blocks 0..15 -> q (norm+rope, scaled),
// 16..19 -> k (norm+rope), 20..23 -> v (plain fp16).
// ============================================================================
__global__ __launch_bounds__(128, 2) void qkv_gemm_kernel(
    const __half* __restrict__ A,
    const uint32_t* __restrict__ Wq2, const uint32_t* __restrict__ Wk2,
    const uint32_t* __restrict__ Wv2,
    __half* __restrict__ Qh, __half* __restrict__ Kh, __half* __restrict__ Vg,
    const float* __restrict__ fc)
{
    extern __shared__ uint32_t sw[];
    const int bx  = blockIdx.x;
    const int tid = threadIdx.x;
    const int lane = tid & 31, wid = tid >> 5;
    const int warpM = wid & 1, warpN = wid >> 1;

    const uint32_t* B2;
    __half* Cm;
    int ncol, N;
    bool norm;
    float scale;
    if (bx < 16)      { B2 = Wq2; Cm = Qh; ncol = bx;      N = H_ * D_;   norm = true;  scale = QSCALE; }
    else if (bx < 20) { B2 = Wk2; Cm = Kh; ncol = bx - 16; N = HKV_ * D_; norm = true;  scale = 1.0f; }
    else              { B2 = Wv2; Cm = Vg; ncol = bx - 20; N = HKV_ * D_; norm = false; scale = 1.0f; }

    const __half*   Ab  = A  + (size_t)blockIdx.y * BM * C_;
    const uint32_t* Bb2 = B2 + (size_t)ncol * BN * K2C;

    float acc[4][8][4];
    #pragma unroll
    for (int i = 0; i < 4; i++)
        #pragma unroll
        for (int j = 0; j < 8; j++)
            #pragma unroll
            for (int c = 0; c < 4; c++) acc[i][j][c] = 0.f;

    gemm_mainloop(sw, Ab, Bb2, C_, acc, tid);

    const int r = lane >> 2, c = lane & 3;
    const int ccol0 = warpN * 64 + c * 2;
    __half* Cb = Cm + (size_t)blockIdx.y * BM * N + (size_t)ncol * BN;

    if (!norm) {
        #pragma unroll
        for (int mt = 0; mt < 4; mt++) {
            const int rr = warpM * 64 + mt * 16 + r;
            #pragma unroll
            for (int nt = 0; nt < 8; nt++) {
                const int cc = ccol0 + nt * 8;
                store2(Cb + (size_t)rr * N + cc,       acc[mt][nt][0], acc[mt][nt][1]);
                store2(Cb + (size_t)(rr + 8) * N + cc, acc[mt][nt][2], acc[mt][nt][3]);
            }
        }
        return;
    }

    // --- fused RMSNorm + RoPE epilogue (BN == D == 128: one head per tile) ---
    float* red = (float*)sw;
    #pragma unroll
    for (int mt = 0; mt < 4; mt++) {
        float p0 = 0.f, p1 = 0.f;
        #pragma unroll
        for (int nt = 0; nt < 8; nt++) {
            p0 += acc[mt][nt][0] * acc[mt][nt][0] + acc[mt][nt][1] * acc[mt][nt][1];
            p1 += acc[mt][nt][2] * acc[mt][nt][2] + acc[mt][nt][3] * acc[mt][nt][3];
        }
        p0 += __shfl_xor_sync(0xffffffffu, p0, 1);
        p0 += __shfl_xor_sync(0xffffffffu, p0, 2);
        p1 += __shfl_xor_sync(0xffffffffu, p1, 1);
        p1 += __shfl_xor_sync(0xffffffffu, p1, 2);
        if (c == 0) {
            const int row = warpM * 64 + mt * 16 + r;
            red[warpN * 128 + row]     = p0;
            red[warpN * 128 + row + 8] = p1;
        }
    }
    __syncthreads();

    #pragma unroll
    for (int mt = 0; mt < 4; mt++) {
        const int row0 = warpM * 64 + mt * 16 + r;
        const int row1 = row0 + 8;
        const float ms0 = (red[row0] + red[128 + row0]) * (1.f / (float)D_);
        const float ms1 = (red[row1] + red[128 + row1]) * (1.f / (float)D_);
        const float ri0 = rsqrtf(ms0 + 1e-6f) * scale;
        const float ri1 = rsqrtf(ms1 + 1e-6f) * scale;
        const int t0 = (blockIdx.y * BM + row0) & (T_ - 1);
        const int t1 = (blockIdx.y * BM + row1) & (T_ - 1);
        #pragma unroll
        for (int nt = 0; nt < 8; nt++) {
            const int cc = ccol0 + nt * 8;
            float2 cs0 = *(const float2*)(fc + (size_t)t0 * D_ + cc);
            float2 cs1 = *(const float2*)(fc + (size_t)t1 * D_ + cc);
            float a0 = acc[mt][nt][0], a1 = acc[mt][nt][1];
            float b0 = acc[mt][nt][2], b1 = acc[mt][nt][3];
            store2(Cb + (size_t)row0 * N + cc,
                   (a0 * cs0.x - a1 * cs0.y) * ri0, (a0 * cs0.y + a1 * cs0.x) * ri0);
            store2(Cb + (size_t)row1 * N + cc,
                   (b0 * cs1.x - b1 * cs1.y) * ri1, (b0 * cs1.y + b1 * cs1.x) * ri1);
        }
    }
}

// ============================================================================
// Fused flash-attention + output-projection kernel.
// grid = 2048, 256 threads:
//   bid 0..1023   : flash blocks, qt = bid>>6 (ascending: light tiles first),
//                   bh = bid&63. On completion: fence + atomicAdd(g_cnt[b*16+qt]).
//   bid 1024..2047: Wc GEMM blocks, ordered by q-tile readiness; spin until
//                   g_cnt[by]==16 (all 16 heads of that row-block done).
// ============================================================================
#define QKW 68
#define VSW 36
#define VBUF (128 * VSW)
#define FLASH_WORDS (128 * QKW + 2 * 64 * QKW + 2 * VBUF)
#define FLASH_SMEM  (FLASH_WORDS * 4)   // 106496 B (>= GEMM_SMEM)

// 256-thread GEMM stage issue (A rows from yh, B = Wc^T)
__device__ __forceinline__ void wc_issue_stage_256(
    uint32_t stage_u, const __half* __restrict__ Ab,
    const uint32_t* __restrict__ Bb2, int kt, int tid)
{
    const int rr = tid >> 2;        // 0..63
    const int c4 = tid & 3;
    const __half* ga = Ab + (size_t)rr * C_ + kt * 32 + c4 * 8;
    uint32_t sa = stage_u + (uint32_t)(rr * ASW + c4 * 4) * 4;
    CP_ASYNC16(sa, ga);
    CP_ASYNC16(sa + (uint32_t)(64 * ASW) * 4u, ga + (size_t)64 * C_);
    const uint32_t* gb = Bb2 + (size_t)rr * K2C + kt * 16 + c4 * 4;
    uint32_t sb = stage_u + (uint32_t)(BS_OFF + rr * ASW + c4 * 4) * 4;
    CP_ASYNC16(sb, gb);
    CP_ASYNC16(sb + (uint32_t)(64 * ASW) * 4u, gb + (size_t)64 * K2C);
}

__global__ __launch_bounds__(256, 1) void flash_wc_kernel(
    const __half* __restrict__ Qh, const __half* __restrict__ Kh,
    const uint32_t* __restrict__ Vt2, __half* __restrict__ Oh,
    const uint32_t* __restrict__ Wc2, float* __restrict__ Out)
{
    extern __shared__ uint32_t sw[];
    const int tid  = threadIdx.x;
    const int lane = tid & 31, wid = tid >> 5;

    if (blockIdx.x < 1024) {
        // ------------------------- flash role -------------------------
        const int qt = blockIdx.x >> 6;
        const int bh = blockIdx.x & 63;
        uint32_t* Qs = sw;
        uint32_t* Ks = sw + 128 * QKW;
        uint32_t* Vs = Ks + 2 * 64 * QKW;

        const int r = lane >> 2, c = lane & 3;
        const int b = bh / H_, h = bh % H_;
        const int kvh = h / REP_;
        const int m0 = qt * 128;
        const int wrow = m0 + wid * 16;
        const uint32_t qu = smem_u32(Qs);
        const uint32_t ku = smem_u32(Ks);
        const uint32_t vu = smem_u32(Vs);

        const __half* Qb = Qh + ((size_t)(b * T_ + m0) * H_ + h) * D_;
        const __half* Kb = Kh + ((size_t)b * T_ * HKV_ + kvh) * D_;
        const uint32_t* Vb = Vt2 + (size_t)(b * HKV_ + kvh) * D_ * (T_ / 2);

        for (int i = tid; i < 128 * 16; i += 256) {
            int row = i >> 4, c4 = i & 15;
            CP_ASYNC16(qu + (uint32_t)(row * QKW + c4 * 4) * 4,
                       Qb + (size_t)row * (H_ * D_) + c4 * 8);
        }
        for (int i = tid; i < 64 * 16; i += 256) {
            int row = i >> 4, c4 = i & 15;
            CP_ASYNC16(ku + (uint32_t)(row * QKW + c4 * 4) * 4,
                       Kb + (size_t)row * (HKV_ * D_) + c4 * 8);
        }
        for (int i = tid; i < 128 * 8; i += 256) {
            int row = i >> 3, c4 = i & 7;
            CP_ASYNC16(vu + (uint32_t)(row * VSW + c4 * 4) * 4,
                       Vb + (size_t)row * (T_ / 2) + c4 * 4);
        }
        CP_COMMIT();

        const uint32_t qoff = (uint32_t)((wid * 16 + (lane & 15)) * QKW + (lane >> 4) * 4) * 4;
        const uint32_t koff = (uint32_t)(((lane & 7) + ((lane >> 4) << 3)) * QKW
                                         + ((lane >> 3) & 1) * 4) * 4;
        const uint32_t voff = (uint32_t)(((lane & 7) + ((lane >> 4) << 3)) * VSW
                                         + ((lane >> 3) & 1) * 4) * 4;

        uint32_t qf[8][4];
        float oa[16][4];
        #pragma unroll
        for (int db = 0; db < 16; db++)
            oa[db][0] = oa[db][1] = oa[db][2] = oa[db][3] = 0.f;
        float m0r = -1e30f, m1r = -1e30f, l0 = 0.f, l1 = 0.f;

        const int nT = 2 * (qt + 1);

        for (int j = 0; j < nT; j++) {
            const int buf = j & 1;
            const int n0 = j * 64;
            CP_WAIT0();
            __syncthreads();

            if (j + 1 < nT) {
                const int nb2 = buf ^ 1;
                for (int i = tid; i < 64 * 16; i += 256) {
                    int row = i >> 4, c4 = i & 15;
                    CP_ASYNC16(ku + (uint32_t)(nb2 * 64 * QKW + row * QKW + c4 * 4) * 4,
                               Kb + (size_t)((j + 1) * 64 + row) * (HKV_ * D_) + c4 * 8);
                }
                for (int i = tid; i < 128 * 8; i += 256) {
                    int row = i >> 3, c4 = i & 7;
                    CP_ASYNC16(vu + (uint32_t)(nb2 * VBUF + row * VSW + c4 * 4) * 4,
                               Vb + (size_t)row * (T_ / 2) + (j + 1) * 32 + c4 * 4);
                }
                CP_COMMIT();
            }

            if (j == 0) {
                #pragma unroll
                for (int ks = 0; ks < 8; ks++)
                    ldsm4(qf[ks][0], qf[ks][1], qf[ks][2], qf[ks][3],
                          qu + qoff + (uint32_t)(ks * 8) * 4);
            }

            if (n0 > wrow + 15) continue;

            const uint32_t kbase = ku + (uint32_t)(buf * 64 * QKW) * 4 + koff;
            float s[8][4];
            #pragma unroll
            for (int nb = 0; nb < 8; nb++)
                s[nb][0] = s[nb][1] = s[nb][2] = s[nb][3] = 0.f;
            #pragma unroll
            for (int ks = 0; ks < 8; ks++) {
                uint32_t kf[8][2];
                #pragma unroll
                for (int np = 0; np < 4; np++)
                    ldsm4(kf[2*np][0], kf[2*np][1], kf[2*np+1][0], kf[2*np+1][1],
                          kbase + (uint32_t)(np * 16 * QKW + ks * 8) * 4);
                #pragma unroll
                for (int nb = 0; nb < 8; nb++)
                    mma_f16(s[nb][0], s[nb][1], s[nb][2], s[nb][3],
                            qf[ks][0], qf[ks][1], qf[ks][2], qf[ks][3],
                            kf[nb][0], kf[nb][1]);
            }

            if (n0 + 63 > wrow) {
                #pragma unroll
                for (int nb = 0; nb < 8; nb++) {
                    int col = n0 + nb * 8 + 2 * c;
                    if (col     > wrow + r)     s[nb][0] = -1e30f;
                    if (col + 1 > wrow + r)     s[nb][1] = -1e30f;
                    if (col     > wrow + r + 8) s[nb][2] = -1e30f;
                    if (col + 1 > wrow + r + 8) s[nb][3] = -1e30f;
                }
            }

            float mx0 = -1e30f, mx1 = -1e30f;
            #pragma unroll
            for (int nb = 0; nb < 8; nb++) {
                mx0 = fmaxf(mx0, fmaxf(s[nb][0], s[nb][1]));
                mx1 = fmaxf(mx1, fmaxf(s[nb][2], s[nb][3]));
            }
            mx0 = fmaxf(mx0, __shfl_xor_sync(0xffffffffu, mx0, 1));
            mx0 = fmaxf(mx0, __shfl_xor_sync(0xffffffffu, mx0, 2));
            mx1 = fmaxf(mx1, __shfl_xor_sync(0xffffffffu, mx1, 1));
            mx1 = fmaxf(mx1, __shfl_xor_sync(0xffffffffu, mx1, 2));
            float mn0 = fmaxf(m0r, mx0), mn1 = fmaxf(m1r, mx1);
            float a0 = exp2f(m0r - mn0), a1 = exp2f(m1r - mn1);
            float ls0 = 0.f, ls1 = 0.f;
            #pragma unroll
            for (int nb = 0; nb < 8; nb++) {
                s[nb][0] = __half2float(__float2half_rn(exp2f(s[nb][0] - mn0)));
                s[nb][1] = __half2float(__float2half_rn(exp2f(s[nb][1] - mn0)));
                s[nb][2] = __half2float(__float2half_rn(exp2f(s[nb][2] - mn1)));
                s[nb][3] = __half2float(__float2half_rn(exp2f(s[nb][3] - mn1)));
                ls0 += s[nb][0] + s[nb][1];
                ls1 += s[nb][2] + s[nb][3];
            }
            ls0 += __shfl_xor_sync(0xffffffffu, ls0, 1);
            ls0 += __shfl_xor_sync(0xffffffffu, ls0, 2);
            ls1 += __shfl_xor_sync(0xffffffffu, ls1, 1);
            ls1 += __shfl_xor_sync(0xffffffffu, ls1, 2);
            l0 = l0 * a0 + ls0; l1 = l1 * a1 + ls1;
            m0r = mn0; m1r = mn1;
            #pragma unroll
            for (int db = 0; db < 16; db++) {
                oa[db][0] *= a0; oa[db][1] *= a0;
                oa[db][2] *= a1; oa[db][3] *= a1;
            }

            const uint32_t vbase = vu + (uint32_t)(buf * VBUF) * 4 + voff;
            #pragma unroll
            for (int kb2 = 0; kb2 < 4; kb2++) {
                uint32_t pa0 = h2u(__floats2half2_rn(s[2*kb2][0],   s[2*kb2][1]));
                uint32_t pa1 = h2u(__floats2half2_rn(s[2*kb2][2],   s[2*kb2][3]));
                uint32_t pa2 = h2u(__floats2half2_rn(s[2*kb2+1][0], s[2*kb2+1][1]));
                uint32_t pa3 = h2u(__floats2half2_rn(s[2*kb2+1][2], s[2*kb2+1][3]));
                #pragma unroll
                for (int dp = 0; dp < 8; dp++) {
                    uint32_t v0, v1, v2, v3;
                    ldsm4(v0, v1, v2, v3,
                          vbase + (uint32_t)(dp * 16 * VSW + kb2 * 8) * 4);
                    mma_f16(oa[2*dp][0], oa[2*dp][1], oa[2*dp][2], oa[2*dp][3],
                            pa0, pa1, pa2, pa3, v0, v1);
                    mma_f16(oa[2*dp+1][0], oa[2*dp+1][1], oa[2*dp+1][2], oa[2*dp+1][3],
                            pa0, pa1, pa2, pa3, v2, v3);
                }
            }
        }

        const float i0 = 1.f / l0, i1 = 1.f / l1;
        const int row_g = m0 + wid * 16 + r;
        __half* Ob = Oh + ((size_t)(b * T_ + row_g) * H_ + h) * D_;
        #pragma unroll
        for (int db = 0; db < 16; db++) {
            *(uint32_t*)(Ob + db * 8 + 2 * c) =
                h2u(__floats2half2_rn(oa[db][0] * i0, oa[db][1] * i0));
            *(uint32_t*)(Ob + (size_t)8 * H_ * D_ + db * 8 + 2 * c) =
                h2u(__floats2half2_rn(oa[db][2] * i1, oa[db][3] * i1));
        }

        // signal: row-block (b, qt) has one more head complete
        __threadfence();
        __syncthreads();
        if (tid == 0) atomicAdd(&g_cnt[b * 16 + qt], 1);

    } else {
        // ------------------------- Wc GEMM role -------------------------
        const int wcid = (int)blockIdx.x - 1024;
        const int qt  = wcid >> 6;          // readiness order: light q-tiles first
        const int rem = wcid & 63;
        const int b   = rem >> 4;
        const int bx  = rem & 15;
        const int by  = b * 16 + qt;        // M row-block (0..63)

        if (tid == 0) {
            while (atomicAdd(&g_cnt[by], 0) < 16) __nanosleep(256);
        }
        __syncthreads();

        const __half*   Ab  = Oh  + (size_t)by * BM * C_;
        const uint32_t* Bb2 = Wc2 + (size_t)bx * BN * K2C;
        const int warpM = wid & 3, warpN = wid >> 2;

        float acc[2][8][4];
        #pragma unroll
        for (int i = 0; i < 2; i++)
            #pragma unroll
            for (int j = 0; j < 8; j++)
                #pragma unroll
                for (int cc = 0; cc < 4; cc++) acc[i][j][cc] = 0.f;

        const uint32_t smem_base = smem_u32(sw);
        #pragma unroll
        for (int s = 0; s < GST - 1; s++) {
            wc_issue_stage_256(smem_base + s * STAGE_WORDS * 4, Ab, Bb2, s, tid);
            CP_COMMIT();
        }

        const uint32_t aoff = (uint32_t)((warpM * 32 + (lane & 15)) * ASW + (lane >> 4) * 4) * 4;
        const uint32_t boff = (uint32_t)((BS_OFF + (warpN * 64 + (lane & 7) + ((lane >> 4) << 3)) * ASW)
                                         + ((lane >> 3) & 1) * 4) * 4;

        const int KT = C_ / 32;
        for (int kt = 0; kt < KT; kt++) {
            const int buf = kt & (GST - 1);
            CP_WAIT2();
            __syncthreads();

            const int nxt = kt + GST - 1;
            if (nxt < KT)
                wc_issue_stage_256(smem_base + (nxt & (GST - 1)) * STAGE_WORDS * 4,
                                   Ab, Bb2, nxt, tid);
            CP_COMMIT();

            const uint32_t stage_u = smem_base + buf * STAGE_WORDS * 4;
            #pragma unroll
            for (int ks = 0; ks < 2; ks++) {
                uint32_t af[2][4], bf[8][2];
                #pragma unroll
                for (int mt = 0; mt < 2; mt++)
                    ldsm4(af[mt][0], af[mt][1], af[mt][2], af[mt][3],
                          stage_u + aoff + (uint32_t)(mt * 16 * ASW + ks * 8) * 4);
                #pragma unroll
                for (int np = 0; np < 4; np++)
                    ldsm4(bf[2*np][0], bf[2*np][1], bf[2*np+1][0], bf[2*np+1][1],
                          stage_u + boff + (uint32_t)(np * 16 * ASW + ks * 8) * 4);
                #pragma unroll
                for (int mt = 0; mt < 2; mt++)
                    #pragma unroll
                    for (int nt = 0; nt < 8; nt++)
                        mma_f16(acc[mt][nt][0], acc[mt][nt][1], acc[mt][nt][2], acc[mt][nt][3],
                                af[mt][0], af[mt][1], af[mt][2], af[mt][3],
                                bf[nt][0], bf[nt][1]);
            }
            __syncthreads();
        }

        float* Cb = Out + (size_t)by * BM * C_ + (size_t)bx * BN;
        const int r = lane >> 2, c = lane & 3;
        const int ccol0 = warpN * 64 + c * 2;
        #pragma unroll
        for (int mt = 0; mt < 2; mt++) {
            const int rr = warpM * 32 + mt * 16 + r;
            #pragma unroll
            for (int nt = 0; nt < 8; nt++) {
                const int cc = ccol0 + nt * 8;
                store2(Cb + (size_t)rr * C_ + cc,       acc[mt][nt][0], acc[mt][nt][1]);
                store2(Cb + (size_t)(rr + 8) * C_ + cc, acc[mt][nt][2], acc[mt][nt][3]);
            }
        }
    }
}

// ============================================================================
// Launch
// ============================================================================
extern "C" void kernel_launch(void* const* d_in, const int* in_sizes, int n_in,
                              void* d_out, int out_size)
{
    (void)in_sizes; (void)n_in; (void)out_size;
    const float* x  = (const float*)d_in[0];
    const float* fc = (const float*)d_in[1];
    const float* Wq = (const float*)d_in[2];
    const float* Wk = (const float*)d_in[3];
    const float* Wv = (const float*)d_in[4];
    const float* Wc = (const float*)d_in[5];
    float* out = (float*)d_out;

    __half *xh, *vg, *qh, *kh, *yh;
    uint32_t *vh, *wqt, *wkt, *wvt, *wct;
    cudaGetSymbolAddress((void**)&xh,  g_xh);
    cudaGetSymbolAddress((void**)&vg,  g_vg);
    cudaGetSymbolAddress((void**)&qh,  g_qh);
    cudaGetSymbolAddress((void**)&kh,  g_kh);
    cudaGetSymbolAddress((void**)&vh,  g_vh);
    cudaGetSymbolAddress((void**)&yh,  g_yh);
    cudaGetSymbolAddress((void**)&wqt, g_wqt);
    cudaGetSymbolAddress((void**)&wkt, g_wkt);
    cudaGetSymbolAddress((void**)&wvt, g_wvt);
    cudaGetSymbolAddress((void**)&wct, g_wct);

    // Prep
    zero_cnt_kernel<<<1, 64>>>();
    cvt_f2h_kernel<<<(M_ * C_ / 4 + 255) / 256, 256>>>(
        (const float4*)x, (uint2*)xh, M_ * C_ / 4);
    conv_wt_kernel<<<dim3((H_ * D_) / 32, K2C / 32), dim3(32, 8)>>>(Wq, wqt, C_, H_ * D_);
    conv_wt_kernel<<<dim3((HKV_ * D_) / 32, K2C / 32), dim3(32, 8)>>>(Wk, wkt, C_, HKV_ * D_);
    conv_wt_kernel<<<dim3((HKV_ * D_) / 32, K2C / 32), dim3(32, 8)>>>(Wv, wvt, C_, HKV_ * D_);
    conv_wt_kernel<<<dim3(C_ / 32, K2C / 32), dim3(32, 8)>>>(Wc, wct, C_, C_);

    cudaFuncSetAttribute(qkv_gemm_kernel, cudaFuncAttributeMaxDynamicSharedMemorySize, GEMM_SMEM);
    cudaFuncSetAttribute(flash_wc_kernel, cudaFuncAttributeMaxDynamicSharedMemorySize, FLASH_SMEM);

    // Fused QKV projection + RMSNorm + RoPE epilogue
    qkv_gemm_kernel<<<dim3(24, M_ / BM), 128, GEMM_SMEM>>>(
        xh, wqt, wkt, wvt, qh, kh, vg, fc);

    // V -> [bk][d][t2] half2
    conv_v_kernel<<<(B_ * HKV_ * D_ * (T_/2) + 255) / 256, 256>>>(vg, vh);

    // Fused flash attention + output projection (dataflow-overlapped)
    flash_wc_kernel<<<2048, 256, FLASH_SMEM>>>(qh, kh, vh, yh, wct, out);
}

// round 10
// speedup vs baseline: 18.4919x; 1.0099x over previous
#include <cuda_runtime.h>
#include <cuda_fp16.h>
#include <cstdint>

// Problem constants
#define B_   4
#define T_   2048
#define C_   2048
#define H_   16
#define HKV_ 4
#define REP_ 4
#define D_   128
#define M_   (B_*T_)   // 8192 rows
#define K2C  (C_/2)    // 1024 half2 words along K

// q scale: 1/sqrt(D) * log2(e)  (softmax done in exp2 domain)
#define QSCALE (0.088388347648318447f * 1.4426950408889634f)

// Scratch (device globals — no allocation allowed)
__device__ __half   g_xh[(size_t)M_ * C_];                 // x as fp16
__device__ __half   g_vg[(size_t)M_ * HKV_ * D_];          // raw v (fp16)
__device__ __half   g_qh[(size_t)M_ * H_ * D_];            // normed+roped q
__device__ __half   g_kh[(size_t)M_ * HKV_ * D_];
__device__ uint32_t g_vh[(size_t)B_ * HKV_ * D_ * (T_/2)]; // V as [bk][d][t2] half2
__device__ __half   g_yh[(size_t)M_ * C_];                 // attention out
__device__ uint32_t g_wqt[(size_t)(H_ * D_) * K2C];        // W^T as [n][k2] half2
__device__ uint32_t g_wkt[(size_t)(HKV_ * D_) * K2C];
__device__ uint32_t g_wvt[(size_t)(HKV_ * D_) * K2C];
__device__ uint32_t g_wct[(size_t)C_ * K2C];
__device__ int      g_cnt[64];                             // per (b, q-tile) flash completion

// ============================================================================
// Helpers
// ============================================================================
__device__ __forceinline__ uint32_t smem_u32(const void* p) {
    uint32_t a;
    asm("{ .reg .u64 t; cvta.to.shared.u64 t, %1; cvt.u32.u64 %0, t; }" : "=r"(a) : "l"(p));
    return a;
}
__device__ __forceinline__ uint32_t h2u(__half2 h) {
    return *reinterpret_cast<uint32_t*>(&h);
}
__device__ __forceinline__ uint32_t ex2_f16x2(uint32_t x) {
    uint32_t r; asm("ex2.approx.f16x2 %0, %1;" : "=r"(r) : "r"(x)); return r;
}
#define CP_ASYNC16(dst_u32, src_ptr) \
    asm volatile("cp.async.cg.shared.global [%0], [%1], 16;" \
                 :: "r"(dst_u32), "l"(src_ptr) : "memory")
#define CP_COMMIT() asm volatile("cp.async.commit_group;" ::: "memory")
#define CP_WAIT2()  asm volatile("cp.async.wait_group 2;" ::: "memory")
#define CP_WAIT0()  asm volatile("cp.async.wait_group 0;" ::: "memory")

__device__ __forceinline__ void mma_f16(
    float& c0, float& c1, float& c2, float& c3,
    uint32_t a0, uint32_t a1, uint32_t a2, uint32_t a3,
    uint32_t b0, uint32_t b1)
{
    asm volatile(
        "mma.sync.aligned.m16n8k16.row.col.f32.f16.f16.f32 "
        "{%0,%1,%2,%3}, {%4,%5,%6,%7}, {%8,%9}, {%0,%1,%2,%3};"
        : "+f"(c0), "+f"(c1), "+f"(c2), "+f"(c3)
        : "r"(a0), "r"(a1), "r"(a2), "r"(a3), "r"(b0), "r"(b1));
}
__device__ __forceinline__ void ldsm4(
    uint32_t& r0, uint32_t& r1, uint32_t& r2, uint32_t& r3, uint32_t a)
{
    asm volatile("ldmatrix.sync.aligned.m8n8.x4.shared.b16 {%0,%1,%2,%3}, [%4];"
                 : "=r"(r0), "=r"(r1), "=r"(r2), "=r"(r3) : "r"(a));
}
__device__ __forceinline__ void store2(float* p, float a, float b) {
    *(float2*)p = make_float2(a, b);
}
__device__ __forceinline__ void store2(__half* p, float a, float b) {
    *(uint32_t*)p = h2u(__floats2half2_rn(a, b));
}

// ============================================================================
// Prep kernels
// ============================================================================
__global__ __launch_bounds__(256) void cvt_f2h_kernel(
    const float4* __restrict__ in, uint2* __restrict__ out, int n4)
{
    int i = blockIdx.x * 256 + threadIdx.x;
    if (i < n4) {
        float4 v = in[i];
        uint2 u;
        u.x = h2u(__floats2half2_rn(v.x, v.y));
        u.y = h2u(__floats2half2_rn(v.z, v.w));
        out[i] = u;
    }
}

__global__ __launch_bounds__(256) void conv_wt_kernel(
    const float* __restrict__ W, uint32_t* __restrict__ Wt2, int K, int N)
{
    __shared__ uint32_t ts[32][33];
    const int n0 = blockIdx.x * 32, k20 = blockIdx.y * 32;
    const int tx = threadIdx.x, ty = threadIdx.y;
    #pragma unroll
    for (int i = 0; i < 4; i++) {
        int k2 = k20 + ty + i * 8;
        float a = W[(size_t)(2 * k2) * N + n0 + tx];
        float b = W[(size_t)(2 * k2 + 1) * N + n0 + tx];
        ts[ty + i * 8][tx] = h2u(__floats2half2_rn(a, b));
    }
    __syncthreads();
    const int K2 = K / 2;
    #pragma unroll
    for (int i = 0; i < 4; i++)
        Wt2[(size_t)(n0 + ty + i * 8) * K2 + k20 + tx] = ts[tx][ty + i * 8];
}

// v transpose + counter zeroing (cnt must be 0 before flash_wc each replay)
__global__ __launch_bounds__(256) void conv_v_kernel(
    const __half* __restrict__ V, uint32_t* __restrict__ Vt2)
{
    if (blockIdx.x == 0 && threadIdx.x < 64) g_cnt[threadIdx.x] = 0;
    int idx = blockIdx.x * 256 + threadIdx.x;
    const int total = B_ * HKV_ * D_ * (T_ / 2);
    if (idx < total) {
        int t2  = idx & (T_ / 2 - 1);
        int d   = (idx >> 10) & (D_ - 1);
        int kvh = (idx >> 17) & (HKV_ - 1);
        int b   = idx >> 19;
        size_t src = ((size_t)(b * T_ + 2 * t2) * HKV_ + kvh) * D_ + d;
        Vt2[idx] = h2u(__halves2half2(V[src], V[src + (size_t)HKV_ * D_]));
    }
}

// ============================================================================
// GEMM machinery (128-thread variant for QKV): 128x128 CTA, BK=32 halves,
// 4 warps (2Mx2N), warp tile 64x64, m16n8k16 via ldmatrix, 4-stage cp.async.
// ============================================================================
#define BM 128
#define BN 128
#define GST 4
#define ASW 20
#define BS_OFF (BM * ASW)               // 2560 words
#define STAGE_WORDS (2 * BM * ASW)      // 5120 words
#define GEMM_SMEM (GST * STAGE_WORDS * 4)  // 81920 B

__device__ __forceinline__ void gemm_issue_stage(
    uint32_t stage_u, const __half* __restrict__ Ab,
    const uint32_t* __restrict__ Bb2, int K, int kt, int tid)
{
    const int K2 = K / 2;
    const int rr = tid >> 2;
    const int c4 = tid & 3;
    const __half* ga = Ab + (size_t)rr * K + kt * 32 + c4 * 8;
    uint32_t sa = stage_u + (uint32_t)(rr * ASW + c4 * 4) * 4;
    #pragma unroll
    for (int p = 0; p < 4; p++)
        CP_ASYNC16(sa + (uint32_t)(p * 32 * ASW) * 4u, ga + (size_t)(p * 32) * K);
    const uint32_t* gb = Bb2 + (size_t)rr * K2 + kt * 16 + c4 * 4;
    uint32_t sb = stage_u + (uint32_t)(BS_OFF + rr * ASW + c4 * 4) * 4;
    #pragma unroll
    for (int p = 0; p < 4; p++)
        CP_ASYNC16(sb + (uint32_t)(p * 32 * ASW) * 4u, gb + (size_t)(p * 32) * K2);
}

__device__ __forceinline__ void gemm_mainloop(
    uint32_t* sw, const __half* Ab, const uint32_t* Bb2, int K,
    float acc[4][8][4], int tid)
{
    const int lane  = tid & 31;
    const int wid   = tid >> 5;
    const int warpM = wid & 1;
    const int warpN = wid >> 1;
    const int KT = K / 32;
    const uint32_t smem_base = smem_u32(sw);

    #pragma unroll
    for (int s = 0; s < GST - 1; s++) {
        gemm_issue_stage(smem_base + s * STAGE_WORDS * 4, Ab, Bb2, K, s, tid);
        CP_COMMIT();
    }

    const uint32_t aoff = (uint32_t)((warpM * 64 + (lane & 15)) * ASW + (lane >> 4) * 4) * 4;
    const uint32_t boff = (uint32_t)((BS_OFF + (warpN * 64 + (lane & 7) + ((lane >> 4) << 3)) * ASW)
                                     + ((lane >> 3) & 1) * 4) * 4;

    for (int kt = 0; kt < KT; kt++) {
        const int buf = kt & (GST - 1);
        CP_WAIT2();
        __syncthreads();

        const int nxt = kt + GST - 1;
        if (nxt < KT)
            gemm_issue_stage(smem_base + (nxt & (GST - 1)) * STAGE_WORDS * 4,
                             Ab, Bb2, K, nxt, tid);
        CP_COMMIT();

        const uint32_t stage_u = smem_base + buf * STAGE_WORDS * 4;
        #pragma unroll
        for (int ks = 0; ks < 2; ks++) {
            uint32_t af[4][4], bf[8][2];
            #pragma unroll
            for (int mt = 0; mt < 4; mt++)
                ldsm4(af[mt][0], af[mt][1], af[mt][2], af[mt][3],
                      stage_u + aoff + (uint32_t)(mt * 16 * ASW + ks * 8) * 4);
            #pragma unroll
            for (int np = 0; np < 4; np++)
                ldsm4(bf[2*np][0], bf[2*np][1], bf[2*np+1][0], bf[2*np+1][1],
                      stage_u + boff + (uint32_t)(np * 16 * ASW + ks * 8) * 4);
            #pragma unroll
            for (int mt = 0; mt < 4; mt++)
                #pragma unroll
                for (int nt = 0; nt < 8; nt++)
                    mma_f16(acc[mt][nt][0], acc[mt][nt][1], acc[mt][nt][2], acc[mt][nt][3],
                            af[mt][0], af[mt][1], af[mt][2], af[mt][3],
                            bf[nt][0], bf[nt][1]);
        }
        __syncthreads();
    }
}

// ============================================================================
// Fused QKV GEMM: grid (24, 64). x-blocks 0..15 -> q (norm+rope, scaled),
// 16..19 -> k (norm+rope), 20..23 -> v (plain fp16).
// ============================================================================
__global__ __launch_bounds__(128, 2) void qkv_gemm_kernel(
    const __half* __restrict__ A,
    const uint32_t* __restrict__ Wq2, const uint32_t* __restrict__ Wk2,
    const uint32_t* __restrict__ Wv2,
    __half* __restrict__ Qh, __half* __restrict__ Kh, __half* __restrict__ Vg,
    const float* __restrict__ fc)
{
    extern __shared__ uint32_t sw[];
    const int bx  = blockIdx.x;
    const int tid = threadIdx.x;
    const int lane = tid & 31, wid = tid >> 5;
    const int warpM = wid & 1, warpN = wid >> 1;

    const uint32_t* B2;
    __half* Cm;
    int ncol, N;
    bool norm;
    float scale;
    if (bx < 16)      { B2 = Wq2; Cm = Qh; ncol = bx;      N = H_ * D_;   norm = true;  scale = QSCALE; }
    else if (bx < 20) { B2 = Wk2; Cm = Kh; ncol = bx - 16; N = HKV_ * D_; norm = true;  scale = 1.0f; }
    else              { B2 = Wv2; Cm = Vg; ncol = bx - 20; N = HKV_ * D_; norm = false; scale = 1.0f; }

    const __half*   Ab  = A  + (size_t)blockIdx.y * BM * C_;
    const uint32_t* Bb2 = B2 + (size_t)ncol * BN * K2C;

    float acc[4][8][4];
    #pragma unroll
    for (int i = 0; i < 4; i++)
        #pragma unroll
        for (int j = 0; j < 8; j++)
            #pragma unroll
            for (int c = 0; c < 4; c++) acc[i][j][c] = 0.f;

    gemm_mainloop(sw, Ab, Bb2, C_, acc, tid);

    const int r = lane >> 2, c = lane & 3;
    const int ccol0 = warpN * 64 + c * 2;
    __half* Cb = Cm + (size_t)blockIdx.y * BM * N + (size_t)ncol * BN;

    if (!norm) {
        #pragma unroll
        for (int mt = 0; mt < 4; mt++) {
            const int rr = warpM * 64 + mt * 16 + r;
            #pragma unroll
            for (int nt = 0; nt < 8; nt++) {
                const int cc = ccol0 + nt * 8;
                store2(Cb + (size_t)rr * N + cc,       acc[mt][nt][0], acc[mt][nt][1]);
                store2(Cb + (size_t)(rr + 8) * N + cc, acc[mt][nt][2], acc[mt][nt][3]);
            }
        }
        return;
    }

    // --- fused RMSNorm + RoPE epilogue (BN == D == 128: one head per tile) ---
    float* red = (float*)sw;
    #pragma unroll
    for (int mt = 0; mt < 4; mt++) {
        float p0 = 0.f, p1 = 0.f;
        #pragma unroll
        for (int nt = 0; nt < 8; nt++) {
            p0 += acc[mt][nt][0] * acc[mt][nt][0] + acc[mt][nt][1] * acc[mt][nt][1];
            p1 += acc[mt][nt][2] * acc[mt][nt][2] + acc[mt][nt][3] * acc[mt][nt][3];
        }
        p0 += __shfl_xor_sync(0xffffffffu, p0, 1);
        p0 += __shfl_xor_sync(0xffffffffu, p0, 2);
        p1 += __shfl_xor_sync(0xffffffffu, p1, 1);
        p1 += __shfl_xor_sync(0xffffffffu, p1, 2);
        if (c == 0) {
            const int row = warpM * 64 + mt * 16 + r;
            red[warpN * 128 + row]     = p0;
            red[warpN * 128 + row + 8] = p1;
        }
    }
    __syncthreads();

    #pragma unroll
    for (int mt = 0; mt < 4; mt++) {
        const int row0 = warpM * 64 + mt * 16 + r;
        const int row1 = row0 + 8;
        const float ms0 = (red[row0] + red[128 + row0]) * (1.f / (float)D_);
        const float ms1 = (red[row1] + red[128 + row1]) * (1.f / (float)D_);
        const float ri0 = rsqrtf(ms0 + 1e-6f) * scale;
        const float ri1 = rsqrtf(ms1 + 1e-6f) * scale;
        const int t0 = (blockIdx.y * BM + row0) & (T_ - 1);
        const int t1 = (blockIdx.y * BM + row1) & (T_ - 1);
        #pragma unroll
        for (int nt = 0; nt < 8; nt++) {
            const int cc = ccol0 + nt * 8;
            float2 cs0 = *(const float2*)(fc + (size_t)t0 * D_ + cc);
            float2 cs1 = *(const float2*)(fc + (size_t)t1 * D_ + cc);
            float a0 = acc[mt][nt][0], a1 = acc[mt][nt][1];
            float b0 = acc[mt][nt][2], b1 = acc[mt][nt][3];
            store2(Cb + (size_t)row0 * N + cc,
                   (a0 * cs0.x - a1 * cs0.y) * ri0, (a0 * cs0.y + a1 * cs0.x) * ri0);
            store2(Cb + (size_t)row1 * N + cc,
                   (b0 * cs1.x - b1 * cs1.y) * ri1, (b0 * cs1.y + b1 * cs1.x) * ri1);
        }
    }
}

// ============================================================================
// Fused flash-attention + output-projection kernel.
// grid = 2048, 256 threads. LPT order: qt DESCENDING in both roles.
//   bid 0..1023   : flash blocks, qt = 15 - (bid>>6), bh = bid&63.
//   bid 1024..2047: Wc GEMM blocks, qt = 15 - (wcid>>6); spin until
//                   g_cnt[b*16+qt]==16.
// ============================================================================
#define QKW 68
#define VSW 36
#define VBUF (128 * VSW)
#define FLASH_WORDS (128 * QKW + 2 * 64 * QKW + 2 * VBUF)
#define FLASH_SMEM  (FLASH_WORDS * 4)   // 106496 B (>= GEMM_SMEM)

__device__ __forceinline__ void wc_issue_stage_256(
    uint32_t stage_u, const __half* __restrict__ Ab,
    const uint32_t* __restrict__ Bb2, int kt, int tid)
{
    const int rr = tid >> 2;        // 0..63
    const int c4 = tid & 3;
    const __half* ga = Ab + (size_t)rr * C_ + kt * 32 + c4 * 8;
    uint32_t sa = stage_u + (uint32_t)(rr * ASW + c4 * 4) * 4;
    CP_ASYNC16(sa, ga);
    CP_ASYNC16(sa + (uint32_t)(64 * ASW) * 4u, ga + (size_t)64 * C_);
    const uint32_t* gb = Bb2 + (size_t)rr * K2C + kt * 16 + c4 * 4;
    uint32_t sb = stage_u + (uint32_t)(BS_OFF + rr * ASW + c4 * 4) * 4;
    CP_ASYNC16(sb, gb);
    CP_ASYNC16(sb + (uint32_t)(64 * ASW) * 4u, gb + (size_t)64 * K2C);
}

__global__ __launch_bounds__(256, 1) void flash_wc_kernel(
    const __half* __restrict__ Qh, const __half* __restrict__ Kh,
    const uint32_t* __restrict__ Vt2, __half* __restrict__ Oh,
    const uint32_t* __restrict__ Wc2, float* __restrict__ Out)
{
    extern __shared__ uint32_t sw[];
    const int tid  = threadIdx.x;
    const int lane = tid & 31, wid = tid >> 5;

    if (blockIdx.x < 1024) {
        // ------------------------- flash role -------------------------
        const int qt = 15 - (int)(blockIdx.x >> 6);   // LPT: heavy tiles first
        const int bh = blockIdx.x & 63;
        uint32_t* Qs = sw;
        uint32_t* Ks = sw + 128 * QKW;
        uint32_t* Vs = Ks + 2 * 64 * QKW;

        const int r = lane >> 2, c = lane & 3;
        const int b = bh / H_, h = bh % H_;
        const int kvh = h / REP_;
        const int m0 = qt * 128;
        const int wrow = m0 + wid * 16;
        const uint32_t qu = smem_u32(Qs);
        const uint32_t ku = smem_u32(Ks);
        const uint32_t vu = smem_u32(Vs);

        const __half* Qb = Qh + ((size_t)(b * T_ + m0) * H_ + h) * D_;
        const __half* Kb = Kh + ((size_t)b * T_ * HKV_ + kvh) * D_;
        const uint32_t* Vb = Vt2 + (size_t)(b * HKV_ + kvh) * D_ * (T_ / 2);

        for (int i = tid; i < 128 * 16; i += 256) {
            int row = i >> 4, c4 = i & 15;
            CP_ASYNC16(qu + (uint32_t)(row * QKW + c4 * 4) * 4,
                       Qb + (size_t)row * (H_ * D_) + c4 * 8);
        }
        for (int i = tid; i < 64 * 16; i += 256) {
            int row = i >> 4, c4 = i & 15;
            CP_ASYNC16(ku + (uint32_t)(row * QKW + c4 * 4) * 4,
                       Kb + (size_t)row * (HKV_ * D_) + c4 * 8);
        }
        for (int i = tid; i < 128 * 8; i += 256) {
            int row = i >> 3, c4 = i & 7;
            CP_ASYNC16(vu + (uint32_t)(row * VSW + c4 * 4) * 4,
                       Vb + (size_t)row * (T_ / 2) + c4 * 4);
        }
        CP_COMMIT();

        const uint32_t qoff = (uint32_t)((wid * 16 + (lane & 15)) * QKW + (lane >> 4) * 4) * 4;
        const uint32_t koff = (uint32_t)(((lane & 7) + ((lane >> 4) << 3)) * QKW
                                         + ((lane >> 3) & 1) * 4) * 4;
        const uint32_t voff = (uint32_t)(((lane & 7) + ((lane >> 4) << 3)) * VSW
                                         + ((lane >> 3) & 1) * 4) * 4;

        uint32_t qf[8][4];
        float oa[16][4];
        #pragma unroll
        for (int db = 0; db < 16; db++)
            oa[db][0] = oa[db][1] = oa[db][2] = oa[db][3] = 0.f;
        float m0r = -1e30f, m1r = -1e30f, l0 = 0.f, l1 = 0.f;

        const int nT = 2 * (qt + 1);

        for (int j = 0; j < nT; j++) {
            const int buf = j & 1;
            const int n0 = j * 64;
            CP_WAIT0();
            __syncthreads();

            if (j + 1 < nT) {
                const int nb2 = buf ^ 1;
                for (int i = tid; i < 64 * 16; i += 256) {
                    int row = i >> 4, c4 = i & 15;
                    CP_ASYNC16(ku + (uint32_t)(nb2 * 64 * QKW + row * QKW + c4 * 4) * 4,
                               Kb + (size_t)((j + 1) * 64 + row) * (HKV_ * D_) + c4 * 8);
                }
                for (int i = tid; i < 128 * 8; i += 256) {
                    int row = i >> 3, c4 = i & 7;
                    CP_ASYNC16(vu + (uint32_t)(nb2 * VBUF + row * VSW + c4 * 4) * 4,
                               Vb + (size_t)row * (T_ / 2) + (j + 1) * 32 + c4 * 4);
                }
                CP_COMMIT();
            }

            if (j == 0) {
                #pragma unroll
                for (int ks = 0; ks < 8; ks++)
                    ldsm4(qf[ks][0], qf[ks][1], qf[ks][2], qf[ks][3],
                          qu + qoff + (uint32_t)(ks * 8) * 4);
            }

            if (n0 > wrow + 15) continue;

            const uint32_t kbase = ku + (uint32_t)(buf * 64 * QKW) * 4 + koff;
            float s[8][4];
            #pragma unroll
            for (int nb = 0; nb < 8; nb++)
                s[nb][0] = s[nb][1] = s[nb][2] = s[nb][3] = 0.f;
            #pragma unroll
            for (int ks = 0; ks < 8; ks++) {
                uint32_t kf[8][2];
                #pragma unroll
                for (int np = 0; np < 4; np++)
                    ldsm4(kf[2*np][0], kf[2*np][1], kf[2*np+1][0], kf[2*np+1][1],
                          kbase + (uint32_t)(np * 16 * QKW + ks * 8) * 4);
                #pragma unroll
                for (int nb = 0; nb < 8; nb++)
                    mma_f16(s[nb][0], s[nb][1], s[nb][2], s[nb][3],
                            qf[ks][0], qf[ks][1], qf[ks][2], qf[ks][3],
                            kf[nb][0], kf[nb][1]);
            }

            if (n0 + 63 > wrow) {
                #pragma unroll
                for (int nb = 0; nb < 8; nb++) {
                    int col = n0 + nb * 8 + 2 * c;
                    if (col     > wrow + r)     s[nb][0] = -1e30f;
                    if (col + 1 > wrow + r)     s[nb][1] = -1e30f;
                    if (col     > wrow + r + 8) s[nb][2] = -1e30f;
                    if (col + 1 > wrow + r + 8) s[nb][3] = -1e30f;
                }
            }

            float mx0 = -1e30f, mx1 = -1e30f;
            #pragma unroll
            for (int nb = 0; nb < 8; nb++) {
                mx0 = fmaxf(mx0, fmaxf(s[nb][0], s[nb][1]));
                mx1 = fmaxf(mx1, fmaxf(s[nb][2], s[nb][3]));
            }
            mx0 = fmaxf(mx0, __shfl_xor_sync(0xffffffffu, mx0, 1));
            mx0 = fmaxf(mx0, __shfl_xor_sync(0xffffffffu, mx0, 2));
            mx1 = fmaxf(mx1, __shfl_xor_sync(0xffffffffu, mx1, 1));
            mx1 = fmaxf(mx1, __shfl_xor_sync(0xffffffffu, mx1, 2));
            float mn0 = fmaxf(m0r, mx0), mn1 = fmaxf(m1r, mx1);
            float a0 = exp2f(m0r - mn0), a1 = exp2f(m1r - mn1);

            // p = exp2(s - m) computed in fp16x2 — output IS the PV A-fragment
            uint32_t pf[8][2];
            float ls0 = 0.f, ls1 = 0.f;
            #pragma unroll
            for (int nb = 0; nb < 8; nb++) {
                uint32_t p01 = ex2_f16x2(h2u(__floats2half2_rn(s[nb][0] - mn0, s[nb][1] - mn0)));
                uint32_t p23 = ex2_f16x2(h2u(__floats2half2_rn(s[nb][2] - mn1, s[nb][3] - mn1)));
                pf[nb][0] = p01;
                pf[nb][1] = p23;
                float2 f01 = __half22float2(*(__half2*)&p01);
                float2 f23 = __half22float2(*(__half2*)&p23);
                ls0 += f01.x + f01.y;
                ls1 += f23.x + f23.y;
            }
            ls0 += __shfl_xor_sync(0xffffffffu, ls0, 1);
            ls0 += __shfl_xor_sync(0xffffffffu, ls0, 2);
            ls1 += __shfl_xor_sync(0xffffffffu, ls1, 1);
            ls1 += __shfl_xor_sync(0xffffffffu, ls1, 2);
            l0 = l0 * a0 + ls0; l1 = l1 * a1 + ls1;
            m0r = mn0; m1r = mn1;
            #pragma unroll
            for (int db = 0; db < 16; db++) {
                oa[db][0] *= a0; oa[db][1] *= a0;
                oa[db][2] *= a1; oa[db][3] *= a1;
            }

            const uint32_t vbase = vu + (uint32_t)(buf * VBUF) * 4 + voff;
            #pragma unroll
            for (int kb2 = 0; kb2 < 4; kb2++) {
                uint32_t pa0 = pf[2*kb2][0];
                uint32_t pa1 = pf[2*kb2][1];
                uint32_t pa2 = pf[2*kb2+1][0];
                uint32_t pa3 = pf[2*kb2+1][1];
                #pragma unroll
                for (int dp = 0; dp < 8; dp++) {
                    uint32_t v0, v1, v2, v3;
                    ldsm4(v0, v1, v2, v3,
                          vbase + (uint32_t)(dp * 16 * VSW + kb2 * 8) * 4);
                    mma_f16(oa[2*dp][0], oa[2*dp][1], oa[2*dp][2], oa[2*dp][3],
                            pa0, pa1, pa2, pa3, v0, v1);
                    mma_f16(oa[2*dp+1][0], oa[2*dp+1][1], oa[2*dp+1][2], oa[2*dp+1][3],
                            pa0, pa1, pa2, pa3, v2, v3);
                }
            }
        }

        const float i0 = 1.f / l0, i1 = 1.f / l1;
        const int row_g = m0 + wid * 16 + r;
        __half* Ob = Oh + ((size_t)(b * T_ + row_g) * H_ + h) * D_;
        #pragma unroll
        for (int db = 0; db < 16; db++) {
            *(uint32_t*)(Ob + db * 8 + 2 * c) =
                h2u(__floats2half2_rn(oa[db][0] * i0, oa[db][1] * i0));
            *(uint32_t*)(Ob + (size_t)8 * H_ * D_ + db * 8 + 2 * c) =
                h2u(__floats2half2_rn(oa[db][2] * i1, oa[db][3] * i1));
        }

        __threadfence();
        __syncthreads();
        if (tid == 0) atomicAdd(&g_cnt[b * 16 + qt], 1);

    } else {
        // ------------------------- Wc GEMM role -------------------------
        const int wcid = (int)blockIdx.x - 1024;
        const int qt  = 15 - (wcid >> 6);   // match flash readiness order
        const int rem = wcid & 63;
        const int b   = rem >> 4;
        const int bx  = rem & 15;
        const int by  = b * 16 + qt;

        if (tid == 0) {
            while (atomicAdd(&g_cnt[by], 0) < 16) __nanosleep(256);
        }
        __syncthreads();

        const __half*   Ab  = Oh  + (size_t)by * BM * C_;
        const uint32_t* Bb2 = Wc2 + (size_t)bx * BN * K2C;
        const int warpM = wid & 3, warpN = wid >> 2;

        float acc[2][8][4];
        #pragma unroll
        for (int i = 0; i < 2; i++)
            #pragma unroll
            for (int j = 0; j < 8; j++)
                #pragma unroll
                for (int cc = 0; cc < 4; cc++) acc[i][j][cc] = 0.f;

        const uint32_t smem_base = smem_u32(sw);
        #pragma unroll
        for (int s = 0; s < GST - 1; s++) {
            wc_issue_stage_256(smem_base + s * STAGE_WORDS * 4, Ab, Bb2, s, tid);
            CP_COMMIT();
        }

        const uint32_t aoff = (uint32_t)((warpM * 32 + (lane & 15)) * ASW + (lane >> 4) * 4) * 4;
        const uint32_t boff = (uint32_t)((BS_OFF + (warpN * 64 + (lane & 7) + ((lane >> 4) << 3)) * ASW)
                                         + ((lane >> 3) & 1) * 4) * 4;

        const int KT = C_ / 32;
        for (int kt = 0; kt < KT; kt++) {
            const int buf = kt & (GST - 1);
            CP_WAIT2();
            __syncthreads();

            const int nxt = kt + GST - 1;
            if (nxt < KT)
                wc_issue_stage_256(smem_base + (nxt & (GST - 1)) * STAGE_WORDS * 4,
                                   Ab, Bb2, nxt, tid);
            CP_COMMIT();

            const uint32_t stage_u = smem_base + buf * STAGE_WORDS * 4;
            #pragma unroll
            for (int ks = 0; ks < 2; ks++) {
                uint32_t af[2][4], bf[8][2];
                #pragma unroll
                for (int mt = 0; mt < 2; mt++)
                    ldsm4(af[mt][0], af[mt][1], af[mt][2], af[mt][3],
                          stage_u + aoff + (uint32_t)(mt * 16 * ASW + ks * 8) * 4);
                #pragma unroll
                for (int np = 0; np < 4; np++)
                    ldsm4(bf[2*np][0], bf[2*np][1], bf[2*np+1][0], bf[2*np+1][1],
                          stage_u + boff + (uint32_t)(np * 16 * ASW + ks * 8) * 4);
                #pragma unroll
                for (int mt = 0; mt < 2; mt++)
                    #pragma unroll
                    for (int nt = 0; nt < 8; nt++)
                        mma_f16(acc[mt][nt][0], acc[mt][nt][1], acc[mt][nt][2], acc[mt][nt][3],
                                af[mt][0], af[mt][1], af[mt][2], af[mt][3],
                                bf[nt][0], bf[nt][1]);
            }
            __syncthreads();
        }

        float* Cb = Out + (size_t)by * BM * C_ + (size_t)bx * BN;
        const int r = lane >> 2, c = lane & 3;
        const int ccol0 = warpN * 64 + c * 2;
        #pragma unroll
        for (int mt = 0; mt < 2; mt++) {
            const int rr = warpM * 32 + mt * 16 + r;
            #pragma unroll
            for (int nt = 0; nt < 8; nt++) {
                const int cc = ccol0 + nt * 8;
                store2(Cb + (size_t)rr * C_ + cc,       acc[mt][nt][0], acc[mt][nt][1]);
                store2(Cb + (size_t)(rr + 8) * C_ + cc, acc[mt][nt][2], acc[mt][nt][3]);
            }
        }
    }
}

// ============================================================================
// Launch
// ============================================================================
extern "C" void kernel_launch(void* const* d_in, const int* in_sizes, int n_in,
                              void* d_out, int out_size)
{
    (void)in_sizes; (void)n_in; (void)out_size;
    const float* x  = (const float*)d_in[0];
    const float* fc = (const float*)d_in[1];
    const float* Wq = (const float*)d_in[2];
    const float* Wk = (const float*)d_in[3];
    const float* Wv = (const float*)d_in[4];
    const float* Wc = (const float*)d_in[5];
    float* out = (float*)d_out;

    __half *xh, *vg, *qh, *kh, *yh;
    uint32_t *vh, *wqt, *wkt, *wvt, *wct;
    cudaGetSymbolAddress((void**)&xh,  g_xh);
    cudaGetSymbolAddress((void**)&vg,  g_vg);
    cudaGetSymbolAddress((void**)&qh,  g_qh);
    cudaGetSymbolAddress((void**)&kh,  g_kh);
    cudaGetSymbolAddress((void**)&vh,  g_vh);
    cudaGetSymbolAddress((void**)&yh,  g_yh);
    cudaGetSymbolAddress((void**)&wqt, g_wqt);
    cudaGetSymbolAddress((void**)&wkt, g_wkt);
    cudaGetSymbolAddress((void**)&wvt, g_wvt);
    cudaGetSymbolAddress((void**)&wct, g_wct);

    // Prep
    cvt_f2h_kernel<<<(M_ * C_ / 4 + 255) / 256, 256>>>(
        (const float4*)x, (uint2*)xh, M_ * C_ / 4);
    conv_wt_kernel<<<dim3((H_ * D_) / 32, K2C / 32), dim3(32, 8)>>>(Wq, wqt, C_, H_ * D_);
    conv_wt_kernel<<<dim3((HKV_ * D_) / 32, K2C / 32), dim3(32, 8)>>>(Wk, wkt, C_, HKV_ * D_);
    conv_wt_kernel<<<dim3((HKV_ * D_) / 32, K2C / 32), dim3(32, 8)>>>(Wv, wvt, C_, HKV_ * D_);
    conv_wt_kernel<<<dim3(C_ / 32, K2C / 32), dim3(32, 8)>>>(Wc, wct, C_, C_);

    cudaFuncSetAttribute(qkv_gemm_kernel, cudaFuncAttributeMaxDynamicSharedMemorySize, GEMM_SMEM);
    cudaFuncSetAttribute(flash_wc_kernel, cudaFuncAttributeMaxDynamicSharedMemorySize, FLASH_SMEM);

    // Fused QKV projection + RMSNorm + RoPE epilogue
    qkv_gemm_kernel<<<dim3(24, M_ / BM), 128, GEMM_SMEM>>>(
        xh, wqt, wkt, wvt, qh, kh, vg, fc);

    // V -> [bk][d][t2] half2 (also zeroes g_cnt for the fused kernel)
    conv_v_kernel<<<(B_ * HKV_ * D_ * (T_/2) + 255) / 256, 256>>>(vg, vh);

    // Fused flash attention + output projection (dataflow-overlapped, LPT order)
    flash_wc_kernel<<<2048, 256, FLASH_SMEM>>>(qh, kh, vh, yh, wct, out);
}